// round 6
// baseline (speedup 1.0000x reference)
#include <cuda_runtime.h>
#include <cuda_bf16.h>
#include <cstdint>
#include <math.h>

// Problem constants
#define Bq 8
#define Nq 1025
#define Cq 3200
#define Hq 25
#define Dq 128
#define Mq (Bq * Nq)        // 8200
#define QKV_N (3 * Cq)      // 9600
#define Kp2 (2 * Cq)        // 6400: paired [hi|lo] layout
#define EPSq 1e-6f

// Scratch (__device__ globals per alloc-free rule)
__device__ float g_qkv[(size_t)Mq * QKV_N];
__device__ __nv_bfloat16 g_as[(size_t)Mq * Kp2];
__device__ __nv_bfloat16 g_wq[(size_t)QKV_N * Kp2];
__device__ __nv_bfloat16 g_wp[(size_t)Cq * Kp2];

// ===========================================================================
// helpers
// ===========================================================================
__device__ __forceinline__ uint32_t smem_u32(const void* p) {
    uint32_t a;
    asm("{ .reg .u64 t; cvta.to.shared.u64 t, %1; cvt.u32.u64 %0, t; }"
        : "=r"(a) : "l"(p));
    return a;
}
__device__ __forceinline__ uint32_t swz128(uint32_t off) {
    return off ^ ((off >> 3) & 0x70);
}
__device__ __forceinline__ void cp16(uint32_t s, const void* g) {
    asm volatile("cp.async.cg.shared.global [%0], [%1], 16;"
                 :: "r"(s), "l"(g) : "memory");
}
#define CP_COMMIT() asm volatile("cp.async.commit_group;" ::: "memory")

#define LDSM_X4(r, addr)                                                       \
    asm volatile("ldmatrix.sync.aligned.m8n8.x4.shared.b16 {%0,%1,%2,%3}, [%4];" \
        : "=r"((r)[0]), "=r"((r)[1]), "=r"((r)[2]), "=r"((r)[3]) : "r"(addr))

#define LDSM_X4_T(r, addr)                                                     \
    asm volatile("ldmatrix.sync.aligned.m8n8.x4.trans.shared.b16 {%0,%1,%2,%3}, [%4];" \
        : "=r"((r)[0]), "=r"((r)[1]), "=r"((r)[2]), "=r"((r)[3]) : "r"(addr))

#define MMA16816(d, a, b)                                                      \
    asm volatile("mma.sync.aligned.m16n8k16.row.col.f32.bf16.bf16.f32 "        \
        "{%0,%1,%2,%3}, {%4,%5,%6,%7}, {%8,%9}, {%0,%1,%2,%3};"                \
        : "+f"((d)[0]), "+f"((d)[1]), "+f"((d)[2]), "+f"((d)[3])               \
        : "r"((a)[0]), "r"((a)[1]), "r"((a)[2]), "r"((a)[3]),                  \
          "r"((b)[0]), "r"((b)[1]))

// ===========================================================================
// Split kernels: fp32 -> bf16 [hi | lo] pairs, row stride Kp2
// ===========================================================================
__global__ __launch_bounds__(256) void split_a_kernel(
    const float* __restrict__ in, __nv_bfloat16* __restrict__ out, int M)
{
    size_t idx = (size_t)blockIdx.x * 256 + threadIdx.x;
    if (idx * 2 >= (size_t)M * Cq) return;
    int m = (int)((idx * 2) / Cq);
    int k = (int)((idx * 2) % Cq);
    float2 v = *(const float2*)(in + (size_t)m * Cq + k);
    __nv_bfloat16 h0 = __float2bfloat16_rn(v.x);
    __nv_bfloat16 h1 = __float2bfloat16_rn(v.y);
    __nv_bfloat16 l0 = __float2bfloat16_rn(v.x - __bfloat162float(h0));
    __nv_bfloat16 l1 = __float2bfloat16_rn(v.y - __bfloat162float(h1));
    __nv_bfloat162 hh; hh.x = h0; hh.y = h1;
    __nv_bfloat162 ll; ll.x = l0; ll.y = l1;
    __nv_bfloat16* row = out + (size_t)m * Kp2;
    *(__nv_bfloat162*)(row + k)      = hh;
    *(__nv_bfloat162*)(row + Cq + k) = ll;
}

__global__ __launch_bounds__(256) void split_wt_kernel(
    const float* __restrict__ W, __nv_bfloat16* __restrict__ out, int Nw)
{
    __shared__ float tile[32][33];
    int n0 = blockIdx.x * 32, k0 = blockIdx.y * 32;
    int tx = threadIdx.x, ty = threadIdx.y;       // 32 x 8
    #pragma unroll
    for (int i = ty; i < 32; i += 8)
        tile[i][tx] = W[(size_t)(k0 + i) * Nw + n0 + tx];
    __syncthreads();
    #pragma unroll
    for (int i = ty; i < 32; i += 8) {
        int n = n0 + i, k = k0 + tx;
        float v = tile[tx][i];
        __nv_bfloat16 h = __float2bfloat16_rn(v);
        __nv_bfloat16 l = __float2bfloat16_rn(v - __bfloat162float(h));
        __nv_bfloat16* row = out + (size_t)n * Kp2;
        row[k]      = h;
        row[Cq + k] = l;
    }
}

// ===========================================================================
// bf16 mma.sync GEMM with paired [hi|lo] fragments + 3-pass correction.
// C[M,Nt] = Ah Bh^T + Ah Bl^T + Al Bh^T + bias.
// CTA 128x128, original-K chunk 32/iter, smem rows = [hi 64B | lo 64B].
// 8 warps (2x4), warp tile 64x32, 3-stage cp.async pipeline, 2 CTA/SM.
// ===========================================================================
#define GBM 128
#define GBN 128
#define GBK 32                     // original-K elements per iter
#define GNIT (Cq / GBK)            // 100
#define ABYTES (GBM * 128)         // 16 KB ([hi|lo] = 128 B/row)
#define BBYTES (GBN * 128)         // 16 KB
#define BUFB (ABYTES + BBYTES)     // 32 KB
#define GSTAGES 3
#define GSMEM_TOTAL (GSTAGES * BUFB)   // 96 KB
#define G_GM 8

__global__ __launch_bounds__(256, 2) void gemm_mma(
    const __nv_bfloat16* __restrict__ A,
    const __nv_bfloat16* __restrict__ Bt,
    const float* __restrict__ bias,
    float* __restrict__ C,
    int M, int Nt, int mt, int nt)
{
    extern __shared__ char smem[];
    const uint32_t sbase = smem_u32(smem);
    const int tid = threadIdx.x;
    const int wid = tid >> 5, lane = tid & 31;
    const int wm = wid >> 2, wn = wid & 3;     // 2 x 4 warp grid

    int bid = blockIdx.x;
    int per_group = G_GM * nt;
    int gid = bid / per_group;
    int first_m = gid * G_GM;
    int gsz = min(G_GM, mt - first_m);
    int rem = bid % per_group;
    const int m0 = (first_m + rem % gsz) * GBM;
    const int n0 = (rem / gsz) * GBN;

    float acc[4][4][4];
    #pragma unroll
    for (int i = 0; i < 4; i++)
        #pragma unroll
        for (int j = 0; j < 4; j++)
            #pragma unroll
            for (int r = 0; r < 4; r++) acc[i][j][r] = 0.f;

    // Each smem row r: bytes [0,64) = hi[k0..k0+32), [64,128) = lo[...]
    auto load_tile = [&](int it, int buf) {
        const int k0 = it * GBK;
        const uint32_t sA = sbase + buf * BUFB;
        const uint32_t sB = sA + ABYTES;
        #pragma unroll
        for (int p = 0; p < 4; p++) {
            int id = p * 256 + tid;
            int row = id >> 3, ch = id & 7;          // 8 chunks of 16B per row
            uint32_t so = swz128((uint32_t)(row * 128 + ch * 16));
            // ch 0-3 -> hi half, ch 4-7 -> lo half (offset Cq in source row)
            int srcoff = (ch < 4) ? (k0 + ch * 8) : (Cq + k0 + (ch - 4) * 8);
            int m = min(m0 + row, M - 1);
            cp16(sA + so, A  + (size_t)m * Kp2 + srcoff);
            cp16(sB + so, Bt + (size_t)(n0 + row) * Kp2 + srcoff);
        }
        CP_COMMIT();
    };

    auto compute = [&](int buf) {
        const uint32_t sA = sbase + buf * BUFB + (uint32_t)(wm * 64 * 128);
        const uint32_t sB = sbase + buf * BUFB + ABYTES + (uint32_t)(wn * 32 * 128);
        #pragma unroll
        for (int kk = 0; kk < 2; kk++) {
            const int hb = kk * 32;        // hi byte offset of this k16
            const int lb = 64 + kk * 32;   // lo byte offset
            uint32_t ah[4][4], al[4][4];
            #pragma unroll
            for (int mi = 0; mi < 4; mi++) {
                int row = mi * 16 + (lane & 15);
                int cc = (lane >> 4) << 4;
                LDSM_X4(ah[mi], sA + swz128((uint32_t)(row * 128 + hb + cc)));
                LDSM_X4(al[mi], sA + swz128((uint32_t)(row * 128 + lb + cc)));
            }
            uint32_t bh[4][2], bl[4][2];
            #pragma unroll
            for (int bj = 0; bj < 2; bj++) {
                int row = bj * 16 + ((lane >> 4) << 3) + (lane & 7);
                int cc = ((lane >> 3) & 1) << 4;
                uint32_t r[4];
                LDSM_X4(r, sB + swz128((uint32_t)(row * 128 + hb + cc)));
                bh[2 * bj][0] = r[0];     bh[2 * bj][1] = r[1];
                bh[2 * bj + 1][0] = r[2]; bh[2 * bj + 1][1] = r[3];
                LDSM_X4(r, sB + swz128((uint32_t)(row * 128 + lb + cc)));
                bl[2 * bj][0] = r[0];     bl[2 * bj][1] = r[1];
                bl[2 * bj + 1][0] = r[2]; bl[2 * bj + 1][1] = r[3];
            }
            #pragma unroll
            for (int mi = 0; mi < 4; mi++)
                #pragma unroll
                for (int nj = 0; nj < 4; nj++)
                    MMA16816(acc[mi][nj], ah[mi], bh[nj]);
            #pragma unroll
            for (int mi = 0; mi < 4; mi++)
                #pragma unroll
                for (int nj = 0; nj < 4; nj++)
                    MMA16816(acc[mi][nj], ah[mi], bl[nj]);
            #pragma unroll
            for (int mi = 0; mi < 4; mi++)
                #pragma unroll
                for (int nj = 0; nj < 4; nj++)
                    MMA16816(acc[mi][nj], al[mi], bh[nj]);
        }
    };

    load_tile(0, 0);
    load_tile(1, 1);
    for (int it = 0; it < GNIT; it++) {
        if (it + 1 < GNIT)
            asm volatile("cp.async.wait_group 1;" ::: "memory");
        else
            asm volatile("cp.async.wait_group 0;" ::: "memory");
        __syncthreads();
        if (it + 2 < GNIT) load_tile(it + 2, (it + 2) % GSTAGES);
        compute(it % GSTAGES);
    }

    const int mbase = m0 + wm * 64;
    const int nbase = n0 + wn * 32;
    #pragma unroll
    for (int mi = 0; mi < 4; mi++) {
        #pragma unroll
        for (int nj = 0; nj < 4; nj++) {
            int r0 = mbase + mi * 16 + (lane >> 2);
            int c = nbase + nj * 8 + 2 * (lane & 3);
            float bx = bias[c], by = bias[c + 1];
            if (r0 < M) {
                float2 o = make_float2(acc[mi][nj][0] + bx, acc[mi][nj][1] + by);
                *(float2*)(C + (size_t)r0 * Nt + c) = o;
            }
            if (r0 + 8 < M) {
                float2 o = make_float2(acc[mi][nj][2] + bx, acc[mi][nj][3] + by);
                *(float2*)(C + (size_t)(r0 + 8) * Nt + c) = o;
            }
        }
    }
}

// ===========================================================================
// RMSNorm in-place over q / k slices of g_qkv.
// ===========================================================================
__global__ __launch_bounds__(256) void rmsnorm_kernel(
    float* __restrict__ qkv, const float* __restrict__ qw,
    const float* __restrict__ kw)
{
    const int row = blockIdx.x;
    const int which = blockIdx.y;
    const float* w = which ? kw : qw;
    float* p = qkv + (size_t)row * QKV_N + which * Cq;

    float ss = 0.f;
    for (int c = threadIdx.x * 4; c < Cq; c += 256 * 4) {
        float4 v = *(const float4*)(p + c);
        ss += v.x * v.x + v.y * v.y + v.z * v.z + v.w * v.w;
    }
    #pragma unroll
    for (int o = 16; o; o >>= 1) ss += __shfl_xor_sync(0xffffffffu, ss, o);
    __shared__ float red[8];
    if ((threadIdx.x & 31) == 0) red[threadIdx.x >> 5] = ss;
    __syncthreads();
    if (threadIdx.x < 8) {
        float v = red[threadIdx.x];
        #pragma unroll
        for (int o = 4; o; o >>= 1) v += __shfl_xor_sync(0xffu, v, o);
        if (threadIdx.x == 0) red[0] = v;
    }
    __syncthreads();
    const float inv = rsqrtf(red[0] * (1.f / Cq) + EPSq);
    for (int c = threadIdx.x * 4; c < Cq; c += 256 * 4) {
        float4 v = *(const float4*)(p + c);
        float4 wv = *(const float4*)(w + c);
        v.x *= inv * wv.x; v.y *= inv * wv.y;
        v.z *= inv * wv.z; v.w *= inv * wv.w;
        *(float4*)(p + c) = v;
    }
}

// ===========================================================================
// Flash attention with bf16 mma.sync + hi/lo splits (proven round-5 kernel).
// Epilogue writes paired [hi|lo] layout directly to g_as.
// ===========================================================================
#define FQK_S 264
#define FQK_B (FQK_S * 2)
#define FV_S 264
#define FV_B (FV_S * 2)
#define FPS_S 68
#define FPB_S 136
#define FPB_B (FPB_S * 2)

#define FA_Q_OFF 0
#define FA_K_OFF (64 * FQK_S * 2)
#define FA_V_OFF (FA_K_OFF + 64 * FQK_S * 2)
#define FA_PS_OFF (FA_V_OFF + 64 * FV_S * 2)
#define FA_PB_OFF (FA_PS_OFF + 64 * FPS_S * 4)
#define FA_ML_OFF (FA_PB_OFF + 64 * FPB_S * 2)
#define FA_SMEM_BYTES (FA_ML_OFF + 3 * 64 * 4)

__global__ __launch_bounds__(256, 1) void flash_attn_mma(
    const float* __restrict__ qkv, __nv_bfloat16* __restrict__ outAs)
{
    extern __shared__ char sm[];
    __nv_bfloat16* Qs = (__nv_bfloat16*)(sm + FA_Q_OFF);
    __nv_bfloat16* Ks = (__nv_bfloat16*)(sm + FA_K_OFF);
    __nv_bfloat16* Vs = (__nv_bfloat16*)(sm + FA_V_OFF);
    float*         Ps = (float*)(sm + FA_PS_OFF);
    __nv_bfloat16* Pb = (__nv_bfloat16*)(sm + FA_PB_OFF);
    float*        m_s = (float*)(sm + FA_ML_OFF);
    float*        l_s = m_s + 64;
    float*       corr = l_s + 64;

    const uint32_t sq  = smem_u32(Qs);
    const uint32_t skm = smem_u32(Ks);
    const uint32_t svm = smem_u32(Vs);
    const uint32_t spb = smem_u32(Pb);

    const int qt = blockIdx.x;
    const int h  = blockIdx.y;
    const int b  = blockIdx.z;
    const int tid = threadIdx.x;
    const int wid = tid >> 5, lane = tid & 31;
    const int wm = wid >> 1, wn = wid & 1;          // 4 x 2 warp grid
    const float scale = 0.08838834764831845f;       // 128^-0.5

    const int q0 = qt * 64;
    const float* qbase = qkv + (size_t)b * Nq * QKV_N + h * Dq;
    const float* kbase = qbase + Cq;
    const float* vbase = qbase + 2 * Cq;

    for (int idx = tid; idx < 64 * 32; idx += 256) {
        int r = idx >> 5, c4 = (idx & 31) * 4;
        int n = q0 + r;
        float4 v = make_float4(0.f, 0.f, 0.f, 0.f);
        if (n < Nq) v = *(const float4*)(qbase + (size_t)n * QKV_N + c4);
        float f[4] = {v.x * scale, v.y * scale, v.z * scale, v.w * scale};
        #pragma unroll
        for (int j = 0; j < 4; j++) {
            __nv_bfloat16 hh = __float2bfloat16_rn(f[j]);
            __nv_bfloat16 ll = __float2bfloat16_rn(f[j] - __bfloat162float(hh));
            Qs[r * FQK_S + c4 + j] = hh;
            Qs[r * FQK_S + 128 + c4 + j] = ll;
        }
    }
    if (tid < 64) { m_s[tid] = -1e30f; l_s[tid] = 0.f; }

    float acc_o[8][4];
    #pragma unroll
    for (int nj = 0; nj < 8; nj++)
        #pragma unroll
        for (int r = 0; r < 4; r++) acc_o[nj][r] = 0.f;
    __syncthreads();

    for (int kt = 0; kt < 17; kt++) {
        const int k0g = kt * 64;

        for (int idx = tid; idx < 64 * 32; idx += 256) {
            int r = idx >> 5, c4 = (idx & 31) * 4;
            int n = k0g + r;
            float4 kv = make_float4(0.f, 0.f, 0.f, 0.f);
            float4 vv = make_float4(0.f, 0.f, 0.f, 0.f);
            if (n < Nq) {
                kv = *(const float4*)(kbase + (size_t)n * QKV_N + c4);
                vv = *(const float4*)(vbase + (size_t)n * QKV_N + c4);
            }
            float kf[4] = {kv.x, kv.y, kv.z, kv.w};
            float vf[4] = {vv.x, vv.y, vv.z, vv.w};
            #pragma unroll
            for (int j = 0; j < 4; j++) {
                __nv_bfloat16 khh = __float2bfloat16_rn(kf[j]);
                __nv_bfloat16 kll = __float2bfloat16_rn(kf[j] - __bfloat162float(khh));
                Ks[r * FQK_S + c4 + j] = khh;
                Ks[r * FQK_S + 128 + c4 + j] = kll;
                __nv_bfloat16 vhh = __float2bfloat16_rn(vf[j]);
                __nv_bfloat16 vll = __float2bfloat16_rn(vf[j] - __bfloat162float(vhh));
                Vs[r * FV_S + c4 + j] = vhh;
                Vs[r * FV_S + 128 + c4 + j] = vll;
            }
        }
        __syncthreads();

        float accs[4][4];
        #pragma unroll
        for (int nj = 0; nj < 4; nj++)
            #pragma unroll
            for (int r = 0; r < 4; r++) accs[nj][r] = 0.f;

        #pragma unroll
        for (int ks = 0; ks < 24; ks++) {
            int aoff, boff;
            if (ks < 8)       { aoff = ks * 32;             boff = ks * 32; }
            else if (ks < 16) { aoff = 256 + (ks - 8) * 32; boff = (ks - 8) * 32; }
            else              { aoff = (ks - 16) * 32;      boff = 256 + (ks - 16) * 32; }

            uint32_t afr[4];
            {
                int row = wm * 16 + (lane & 15);
                LDSM_X4(afr, sq + (uint32_t)(row * FQK_B + aoff + ((lane >> 4) << 4)));
            }
            uint32_t bfr[4][2];
            #pragma unroll
            for (int bj = 0; bj < 2; bj++) {
                int row = wn * 32 + bj * 16 + ((lane >> 4) << 3) + (lane & 7);
                uint32_t r[4];
                LDSM_X4(r, skm + (uint32_t)(row * FQK_B + boff + (((lane >> 3) & 1) << 4)));
                bfr[2 * bj][0] = r[0];     bfr[2 * bj][1] = r[1];
                bfr[2 * bj + 1][0] = r[2]; bfr[2 * bj + 1][1] = r[3];
            }
            #pragma unroll
            for (int nj = 0; nj < 4; nj++)
                MMA16816(accs[nj], afr, bfr[nj]);
        }

        {
            int r0 = wm * 16 + (lane >> 2);
            int cb = wn * 32 + 2 * (lane & 3);
            #pragma unroll
            for (int nj = 0; nj < 4; nj++) {
                int c = cb + nj * 8;
                Ps[r0 * FPS_S + c]           = accs[nj][0];
                Ps[r0 * FPS_S + c + 1]       = accs[nj][1];
                Ps[(r0 + 8) * FPS_S + c]     = accs[nj][2];
                Ps[(r0 + 8) * FPS_S + c + 1] = accs[nj][3];
            }
        }
        __syncthreads();

        {
            const int r = tid >> 2;
            const int q4 = tid & 3;
            float mx = -1e30f;
            #pragma unroll
            for (int c = q4 * 16; c < q4 * 16 + 16; c++) {
                bool valid = (k0g + c < Nq);
                float sv = valid ? Ps[r * FPS_S + c] : -1e30f;
                mx = fmaxf(mx, sv);
            }
            mx = fmaxf(mx, __shfl_xor_sync(0xffffffffu, mx, 1));
            mx = fmaxf(mx, __shfl_xor_sync(0xffffffffu, mx, 2));
            const float mold = m_s[r];
            const float mnew = fmaxf(mold, mx);
            float sum = 0.f;
            #pragma unroll
            for (int c = q4 * 16; c < q4 * 16 + 16; c++) {
                bool valid = (k0g + c < Nq);
                float pv = valid ? __expf(Ps[r * FPS_S + c] - mnew) : 0.f;
                sum += pv;
                __nv_bfloat16 ph = __float2bfloat16_rn(pv);
                __nv_bfloat16 pl = __float2bfloat16_rn(pv - __bfloat162float(ph));
                Pb[r * FPB_S + c]      = ph;
                Pb[r * FPB_S + 64 + c] = pl;
            }
            sum += __shfl_xor_sync(0xffffffffu, sum, 1);
            sum += __shfl_xor_sync(0xffffffffu, sum, 2);
            if (q4 == 0) {
                float cr = __expf(mold - mnew);
                l_s[r] = l_s[r] * cr + sum;
                m_s[r] = mnew;
                corr[r] = cr;
            }
        }
        __syncthreads();

        {
            float c0 = corr[wm * 16 + (lane >> 2)];
            float c1 = corr[wm * 16 + (lane >> 2) + 8];
            #pragma unroll
            for (int nj = 0; nj < 8; nj++) {
                acc_o[nj][0] *= c0; acc_o[nj][1] *= c0;
                acc_o[nj][2] *= c1; acc_o[nj][3] *= c1;
            }
        }

        #pragma unroll
        for (int ks = 0; ks < 12; ks++) {
            int aoff = (ks < 4) ? ks * 32
                     : (ks < 8) ? 128 + (ks - 4) * 32
                                : (ks - 8) * 32;
            int vco  = (ks < 8) ? 0 : 256;
            int krow = (ks & 3) * 16;

            uint32_t afr[4];
            {
                int row = wm * 16 + (lane & 15);
                LDSM_X4(afr, spb + (uint32_t)(row * FPB_B + aoff + ((lane >> 4) << 4)));
            }
            uint32_t bfr[8][2];
            #pragma unroll
            for (int g = 0; g < 4; g++) {
                int vrow = krow + (lane & 7) + (((lane >> 3) & 1) << 3);
                int bcol = vco + (wn * 64 + g * 16) * 2 + ((lane >> 4) << 4);
                uint32_t r[4];
                LDSM_X4_T(r, svm + (uint32_t)(vrow * FV_B + bcol));
                bfr[2 * g][0] = r[0];     bfr[2 * g][1] = r[1];
                bfr[2 * g + 1][0] = r[2]; bfr[2 * g + 1][1] = r[3];
            }
            #pragma unroll
            for (int nj = 0; nj < 8; nj++)
                MMA16816(acc_o[nj], afr, bfr[nj]);
        }
        __syncthreads();
    }

    // ---- epilogue: normalize, split hi/lo, write paired layout to g_as ----
    {
        int r0 = wm * 16 + (lane >> 2);
        float invl0 = 1.f / l_s[r0];
        float invl1 = 1.f / l_s[r0 + 8];
        int n0v = q0 + r0;
        int n1v = q0 + r0 + 8;
        #pragma unroll
        for (int nj = 0; nj < 8; nj++) {
            int c = h * Dq + wn * 64 + nj * 8 + 2 * (lane & 3);
            if (n0v < Nq) {
                float o0 = acc_o[nj][0] * invl0;
                float o1 = acc_o[nj][1] * invl0;
                __nv_bfloat16 h0 = __float2bfloat16_rn(o0);
                __nv_bfloat16 h1 = __float2bfloat16_rn(o1);
                __nv_bfloat16 l0 = __float2bfloat16_rn(o0 - __bfloat162float(h0));
                __nv_bfloat16 l1 = __float2bfloat16_rn(o1 - __bfloat162float(h1));
                __nv_bfloat162 hh; hh.x = h0; hh.y = h1;
                __nv_bfloat162 ll; ll.x = l0; ll.y = l1;
                __nv_bfloat16* row = outAs + (size_t)(b * Nq + n0v) * Kp2;
                *(__nv_bfloat162*)(row + c)      = hh;
                *(__nv_bfloat162*)(row + Cq + c) = ll;
            }
            if (n1v < Nq) {
                float o0 = acc_o[nj][2] * invl1;
                float o1 = acc_o[nj][3] * invl1;
                __nv_bfloat16 h0 = __float2bfloat16_rn(o0);
                __nv_bfloat16 h1 = __float2bfloat16_rn(o1);
                __nv_bfloat16 l0 = __float2bfloat16_rn(o0 - __bfloat162float(h0));
                __nv_bfloat16 l1 = __float2bfloat16_rn(o1 - __bfloat162float(h1));
                __nv_bfloat162 hh; hh.x = h0; hh.y = h1;
                __nv_bfloat162 ll; ll.x = l0; ll.y = l1;
                __nv_bfloat16* row = outAs + (size_t)(b * Nq + n1v) * Kp2;
                *(__nv_bfloat162*)(row + c)      = hh;
                *(__nv_bfloat162*)(row + Cq + c) = ll;
            }
        }
    }
}

// ===========================================================================
extern "C" void kernel_launch(void* const* d_in, const int* in_sizes, int n_in,
                              void* d_out, int out_size)
{
    const float* x        = (const float*)d_in[0];
    const float* qkv_w    = (const float*)d_in[1];
    const float* qkv_b    = (const float*)d_in[2];
    const float* q_norm_w = (const float*)d_in[3];
    const float* k_norm_w = (const float*)d_in[4];
    const float* proj_w   = (const float*)d_in[5];
    const float* proj_b   = (const float*)d_in[6];
    float* out = (float*)d_out;

    float* qkvp = nullptr;
    __nv_bfloat16 *asp = nullptr, *wqp = nullptr, *wpp = nullptr;
    cudaGetSymbolAddress((void**)&qkvp, g_qkv);
    cudaGetSymbolAddress((void**)&asp, g_as);
    cudaGetSymbolAddress((void**)&wqp, g_wq);
    cudaGetSymbolAddress((void**)&wpp, g_wp);

    cudaFuncSetAttribute(gemm_mma,
                         cudaFuncAttributeMaxDynamicSharedMemorySize, GSMEM_TOTAL);
    cudaFuncSetAttribute(flash_attn_mma,
                         cudaFuncAttributeMaxDynamicSharedMemorySize, FA_SMEM_BYTES);

    const int mt = (Mq + GBM - 1) / GBM;        // 65
    const int nt_qkv = QKV_N / GBN;             // 75
    const int nt_prj = Cq / GBN;                // 25

    // 1) split inputs / weights into bf16 [hi|lo] pairs
    {
        size_t e2 = (size_t)Mq * Cq / 2;
        split_a_kernel<<<(unsigned)((e2 + 255) / 256), 256>>>(x, asp, Mq);
    }
    split_wt_kernel<<<dim3(QKV_N / 32, Cq / 32), dim3(32, 8)>>>(qkv_w, wqp, QKV_N);
    split_wt_kernel<<<dim3(Cq / 32, Cq / 32), dim3(32, 8)>>>(proj_w, wpp, Cq);

    // 2) qkv = x @ qkv_w + b
    gemm_mma<<<mt * nt_qkv, 256, GSMEM_TOTAL>>>(
        asp, wqp, qkv_b, qkvp, Mq, QKV_N, mt, nt_qkv);

    // 3) RMSNorm q/k in place
    rmsnorm_kernel<<<dim3(Mq, 2), 256>>>(qkvp, q_norm_w, k_norm_w);

    // 4) attention -> g_as (paired [hi|lo] layout, ready for proj GEMM)
    flash_attn_mma<<<dim3(17, Hq, Bq), 256, FA_SMEM_BYTES>>>(qkvp, asp);

    // 5) out = att @ proj_w + b
    gemm_mma<<<mt * nt_prj, 256, GSMEM_TOTAL>>>(
        asp, wpp, proj_b, out, Mq, Cq, mt, nt_prj);
}

// round 7
// speedup vs baseline: 1.3143x; 1.3143x over previous
#include <cuda_runtime.h>
#include <cuda_bf16.h>
#include <cuda_fp16.h>
#include <cstdint>
#include <math.h>

// Problem constants
#define Bq 8
#define Nq 1025
#define Cq 3200
#define Hq 25
#define Dq 128
#define Mq (Bq * Nq)        // 8200
#define QKV_N (3 * Cq)      // 9600
#define Ka 6400             // A-side K'': [Ah | Al] fp16 pairs
#define EPSq 1e-6f

// Scratch (__device__ globals per alloc-free rule)
__device__ float g_qkv[(size_t)Mq * QKV_N];
__device__ __half g_as[(size_t)Mq * Ka];          // A' = [hi|lo] fp16
__device__ __half g_wq[(size_t)QKV_N * Cq];       // qkv_w^T fp16 (hi only)
__device__ __half g_wp[(size_t)Cq * Cq];          // proj_w^T fp16 (hi only)

// ===========================================================================
// helpers
// ===========================================================================
__device__ __forceinline__ uint32_t smem_u32(const void* p) {
    uint32_t a;
    asm("{ .reg .u64 t; cvta.to.shared.u64 t, %1; cvt.u32.u64 %0, t; }"
        : "=r"(a) : "l"(p));
    return a;
}
__device__ __forceinline__ uint32_t swz128(uint32_t off) {
    return off ^ ((off >> 3) & 0x70);
}
__device__ __forceinline__ void cp16(uint32_t s, const void* g) {
    asm volatile("cp.async.cg.shared.global [%0], [%1], 16;"
                 :: "r"(s), "l"(g) : "memory");
}
#define CP_COMMIT() asm volatile("cp.async.commit_group;" ::: "memory")

#define LDSM_X4(r, addr)                                                       \
    asm volatile("ldmatrix.sync.aligned.m8n8.x4.shared.b16 {%0,%1,%2,%3}, [%4];" \
        : "=r"((r)[0]), "=r"((r)[1]), "=r"((r)[2]), "=r"((r)[3]) : "r"(addr))

#define LDSM_X4_T(r, addr)                                                     \
    asm volatile("ldmatrix.sync.aligned.m8n8.x4.trans.shared.b16 {%0,%1,%2,%3}, [%4];" \
        : "=r"((r)[0]), "=r"((r)[1]), "=r"((r)[2]), "=r"((r)[3]) : "r"(addr))

// fp16 MMA (GEMM path)
#define MMA16816_F16(d, a, b)                                                  \
    asm volatile("mma.sync.aligned.m16n8k16.row.col.f32.f16.f16.f32 "          \
        "{%0,%1,%2,%3}, {%4,%5,%6,%7}, {%8,%9}, {%0,%1,%2,%3};"                \
        : "+f"((d)[0]), "+f"((d)[1]), "+f"((d)[2]), "+f"((d)[3])               \
        : "r"((a)[0]), "r"((a)[1]), "r"((a)[2]), "r"((a)[3]),                  \
          "r"((b)[0]), "r"((b)[1]))

// bf16 MMA (attention path)
#define MMA16816_BF(d, a, b)                                                   \
    asm volatile("mma.sync.aligned.m16n8k16.row.col.f32.bf16.bf16.f32 "        \
        "{%0,%1,%2,%3}, {%4,%5,%6,%7}, {%8,%9}, {%0,%1,%2,%3};"                \
        : "+f"((d)[0]), "+f"((d)[1]), "+f"((d)[2]), "+f"((d)[3])               \
        : "r"((a)[0]), "r"((a)[1]), "r"((a)[2]), "r"((a)[3]),                  \
          "r"((b)[0]), "r"((b)[1]))

// ===========================================================================
// Split kernels
// A: fp32 -> fp16 [hi | lo] pairs, row stride Ka=6400
// W: fp32 [K,N] -> fp16 W^T [N,K] hi only, row stride Cq
// ===========================================================================
__global__ __launch_bounds__(256) void split_a_kernel(
    const float* __restrict__ in, __half* __restrict__ out, int M)
{
    size_t idx = (size_t)blockIdx.x * 256 + threadIdx.x;
    if (idx * 2 >= (size_t)M * Cq) return;
    int m = (int)((idx * 2) / Cq);
    int k = (int)((idx * 2) % Cq);
    float2 v = *(const float2*)(in + (size_t)m * Cq + k);
    __half h0 = __float2half_rn(v.x);
    __half h1 = __float2half_rn(v.y);
    __half l0 = __float2half_rn(v.x - __half2float(h0));
    __half l1 = __float2half_rn(v.y - __half2float(h1));
    __half2 hh; hh.x = h0; hh.y = h1;
    __half2 ll; ll.x = l0; ll.y = l1;
    __half* row = out + (size_t)m * Ka;
    *(__half2*)(row + k)      = hh;
    *(__half2*)(row + Cq + k) = ll;
}

__global__ __launch_bounds__(256) void split_wt_kernel(
    const float* __restrict__ W, __half* __restrict__ out, int Nw)
{
    __shared__ float tile[32][33];
    int n0 = blockIdx.x * 32, k0 = blockIdx.y * 32;
    int tx = threadIdx.x, ty = threadIdx.y;       // 32 x 8
    #pragma unroll
    for (int i = ty; i < 32; i += 8)
        tile[i][tx] = W[(size_t)(k0 + i) * Nw + n0 + tx];
    __syncthreads();
    #pragma unroll
    for (int i = ty; i < 32; i += 8) {
        int n = n0 + i, k = k0 + tx;
        out[(size_t)n * Cq + k] = __float2half_rn(tile[tx][i]);
    }
}

// ===========================================================================
// fp16 mma.sync GEMM: C[M,Nt] = (Ah+Al)[M,Ka] @ Bh[Nt,Cq]^T + bias
// Iterates K''=Ka=6400; B source index wraps mod Cq (Bh streamed twice).
// CTA 128x128x64, 8 warps (2x4), warp tile 64x32, 3-stage cp.async, 2 CTA/SM.
// (structure identical to the round-5 kernel that measured tensor=70%)
// ===========================================================================
#define GBM 128
#define GBN 128
#define GBK 64
#define GNIT (Ka / GBK)            // 100
#define ABYTES (GBM * GBK * 2)     // 16 KB
#define BBYTES (GBN * GBK * 2)     // 16 KB
#define BUFB (ABYTES + BBYTES)     // 32 KB
#define GSTAGES 3
#define GSMEM_TOTAL (GSTAGES * BUFB)   // 96 KB
#define G_GM 8

__global__ __launch_bounds__(256, 2) void gemm_mma(
    const __half* __restrict__ A,
    const __half* __restrict__ Bt,
    const float* __restrict__ bias,
    float* __restrict__ C,
    int M, int Nt, int mt, int nt)
{
    extern __shared__ char smem[];
    const uint32_t sbase = smem_u32(smem);
    const int tid = threadIdx.x;
    const int wid = tid >> 5, lane = tid & 31;
    const int wm = wid >> 2, wn = wid & 3;     // 2 x 4 warp grid

    int bid = blockIdx.x;
    int per_group = G_GM * nt;
    int gid = bid / per_group;
    int first_m = gid * G_GM;
    int gsz = min(G_GM, mt - first_m);
    int rem = bid % per_group;
    const int m0 = (first_m + rem % gsz) * GBM;
    const int n0 = (rem / gsz) * GBN;

    float acc[4][4][4];
    #pragma unroll
    for (int i = 0; i < 4; i++)
        #pragma unroll
        for (int j = 0; j < 4; j++)
            #pragma unroll
            for (int r = 0; r < 4; r++) acc[i][j][r] = 0.f;

    auto load_tile = [&](int it, int buf) {
        const int k0 = it * GBK;
        const int bk0 = (k0 >= Cq) ? (k0 - Cq) : k0;   // B wraps (hi streamed twice)
        const uint32_t sA = sbase + buf * BUFB;
        const uint32_t sB = sA + ABYTES;
        #pragma unroll
        for (int p = 0; p < 4; p++) {
            int id = p * 256 + tid;
            int row = id >> 3, ch = id & 7;
            uint32_t so = swz128((uint32_t)(row * 128 + ch * 16));
            int m = min(m0 + row, M - 1);
            cp16(sA + so, A  + (size_t)m * Ka + k0 + ch * 8);
            cp16(sB + so, Bt + (size_t)(n0 + row) * Cq + bk0 + ch * 8);
        }
        CP_COMMIT();
    };

    auto compute = [&](int buf) {
        const uint32_t sA = sbase + buf * BUFB + (uint32_t)(wm * 64 * 128);
        const uint32_t sB = sbase + buf * BUFB + ABYTES + (uint32_t)(wn * 32 * 128);
        #pragma unroll
        for (int kk = 0; kk < 4; kk++) {
            uint32_t afr[4][4];
            #pragma unroll
            for (int mi = 0; mi < 4; mi++) {
                int row = mi * 16 + (lane & 15);
                int cb = kk * 32 + ((lane >> 4) << 4);
                LDSM_X4(afr[mi], sA + swz128((uint32_t)(row * 128 + cb)));
            }
            uint32_t bfr[4][2];
            #pragma unroll
            for (int bj = 0; bj < 2; bj++) {
                int row = bj * 16 + ((lane >> 4) << 3) + (lane & 7);
                int cb = kk * 32 + (((lane >> 3) & 1) << 4);
                uint32_t r[4];
                LDSM_X4(r, sB + swz128((uint32_t)(row * 128 + cb)));
                bfr[2 * bj][0] = r[0];     bfr[2 * bj][1] = r[1];
                bfr[2 * bj + 1][0] = r[2]; bfr[2 * bj + 1][1] = r[3];
            }
            #pragma unroll
            for (int mi = 0; mi < 4; mi++)
                #pragma unroll
                for (int nj = 0; nj < 4; nj++)
                    MMA16816_F16(acc[mi][nj], afr[mi], bfr[nj]);
        }
    };

    load_tile(0, 0);
    load_tile(1, 1);
    for (int it = 0; it < GNIT; it++) {
        if (it + 1 < GNIT)
            asm volatile("cp.async.wait_group 1;" ::: "memory");
        else
            asm volatile("cp.async.wait_group 0;" ::: "memory");
        __syncthreads();
        if (it + 2 < GNIT) load_tile(it + 2, (it + 2) % GSTAGES);
        compute(it % GSTAGES);
    }

    const int mbase = m0 + wm * 64;
    const int nbase = n0 + wn * 32;
    #pragma unroll
    for (int mi = 0; mi < 4; mi++) {
        #pragma unroll
        for (int nj = 0; nj < 4; nj++) {
            int r0 = mbase + mi * 16 + (lane >> 2);
            int c = nbase + nj * 8 + 2 * (lane & 3);
            float bx = bias[c], by = bias[c + 1];
            if (r0 < M) {
                float2 o = make_float2(acc[mi][nj][0] + bx, acc[mi][nj][1] + by);
                *(float2*)(C + (size_t)r0 * Nt + c) = o;
            }
            if (r0 + 8 < M) {
                float2 o = make_float2(acc[mi][nj][2] + bx, acc[mi][nj][3] + by);
                *(float2*)(C + (size_t)(r0 + 8) * Nt + c) = o;
            }
        }
    }
}

// ===========================================================================
// RMSNorm in-place over q / k slices of g_qkv.
// ===========================================================================
__global__ __launch_bounds__(256) void rmsnorm_kernel(
    float* __restrict__ qkv, const float* __restrict__ qw,
    const float* __restrict__ kw)
{
    const int row = blockIdx.x;
    const int which = blockIdx.y;
    const float* w = which ? kw : qw;
    float* p = qkv + (size_t)row * QKV_N + which * Cq;

    float ss = 0.f;
    for (int c = threadIdx.x * 4; c < Cq; c += 256 * 4) {
        float4 v = *(const float4*)(p + c);
        ss += v.x * v.x + v.y * v.y + v.z * v.z + v.w * v.w;
    }
    #pragma unroll
    for (int o = 16; o; o >>= 1) ss += __shfl_xor_sync(0xffffffffu, ss, o);
    __shared__ float red[8];
    if ((threadIdx.x & 31) == 0) red[threadIdx.x >> 5] = ss;
    __syncthreads();
    if (threadIdx.x < 8) {
        float v = red[threadIdx.x];
        #pragma unroll
        for (int o = 4; o; o >>= 1) v += __shfl_xor_sync(0xffu, v, o);
        if (threadIdx.x == 0) red[0] = v;
    }
    __syncthreads();
    const float inv = rsqrtf(red[0] * (1.f / Cq) + EPSq);
    for (int c = threadIdx.x * 4; c < Cq; c += 256 * 4) {
        float4 v = *(const float4*)(p + c);
        float4 wv = *(const float4*)(w + c);
        v.x *= inv * wv.x; v.y *= inv * wv.y;
        v.z *= inv * wv.z; v.w *= inv * wv.w;
        *(float4*)(p + c) = v;
    }
}

// ===========================================================================
// Flash attention with bf16 mma.sync + hi/lo splits (proven round-5 kernel).
// Epilogue writes fp16 [hi|lo] pairs (stride Ka) directly to g_as.
// ===========================================================================
#define FQK_S 264
#define FQK_B (FQK_S * 2)
#define FV_S 264
#define FV_B (FV_S * 2)
#define FPS_S 68
#define FPB_S 136
#define FPB_B (FPB_S * 2)

#define FA_Q_OFF 0
#define FA_K_OFF (64 * FQK_S * 2)
#define FA_V_OFF (FA_K_OFF + 64 * FQK_S * 2)
#define FA_PS_OFF (FA_V_OFF + 64 * FV_S * 2)
#define FA_PB_OFF (FA_PS_OFF + 64 * FPS_S * 4)
#define FA_ML_OFF (FA_PB_OFF + 64 * FPB_S * 2)
#define FA_SMEM_BYTES (FA_ML_OFF + 3 * 64 * 4)

__global__ __launch_bounds__(256, 1) void flash_attn_mma(
    const float* __restrict__ qkv, __half* __restrict__ outAs)
{
    extern __shared__ char sm[];
    __nv_bfloat16* Qs = (__nv_bfloat16*)(sm + FA_Q_OFF);
    __nv_bfloat16* Ks = (__nv_bfloat16*)(sm + FA_K_OFF);
    __nv_bfloat16* Vs = (__nv_bfloat16*)(sm + FA_V_OFF);
    float*         Ps = (float*)(sm + FA_PS_OFF);
    __nv_bfloat16* Pb = (__nv_bfloat16*)(sm + FA_PB_OFF);
    float*        m_s = (float*)(sm + FA_ML_OFF);
    float*        l_s = m_s + 64;
    float*       corr = l_s + 64;

    const uint32_t sq  = smem_u32(Qs);
    const uint32_t skm = smem_u32(Ks);
    const uint32_t svm = smem_u32(Vs);
    const uint32_t spb = smem_u32(Pb);

    const int qt = blockIdx.x;
    const int h  = blockIdx.y;
    const int b  = blockIdx.z;
    const int tid = threadIdx.x;
    const int wid = tid >> 5, lane = tid & 31;
    const int wm = wid >> 1, wn = wid & 1;          // 4 x 2 warp grid
    const float scale = 0.08838834764831845f;       // 128^-0.5

    const int q0 = qt * 64;
    const float* qbase = qkv + (size_t)b * Nq * QKV_N + h * Dq;
    const float* kbase = qbase + Cq;
    const float* vbase = qbase + 2 * Cq;

    for (int idx = tid; idx < 64 * 32; idx += 256) {
        int r = idx >> 5, c4 = (idx & 31) * 4;
        int n = q0 + r;
        float4 v = make_float4(0.f, 0.f, 0.f, 0.f);
        if (n < Nq) v = *(const float4*)(qbase + (size_t)n * QKV_N + c4);
        float f[4] = {v.x * scale, v.y * scale, v.z * scale, v.w * scale};
        #pragma unroll
        for (int j = 0; j < 4; j++) {
            __nv_bfloat16 hh = __float2bfloat16_rn(f[j]);
            __nv_bfloat16 ll = __float2bfloat16_rn(f[j] - __bfloat162float(hh));
            Qs[r * FQK_S + c4 + j] = hh;
            Qs[r * FQK_S + 128 + c4 + j] = ll;
        }
    }
    if (tid < 64) { m_s[tid] = -1e30f; l_s[tid] = 0.f; }

    float acc_o[8][4];
    #pragma unroll
    for (int nj = 0; nj < 8; nj++)
        #pragma unroll
        for (int r = 0; r < 4; r++) acc_o[nj][r] = 0.f;
    __syncthreads();

    for (int kt = 0; kt < 17; kt++) {
        const int k0g = kt * 64;

        for (int idx = tid; idx < 64 * 32; idx += 256) {
            int r = idx >> 5, c4 = (idx & 31) * 4;
            int n = k0g + r;
            float4 kv = make_float4(0.f, 0.f, 0.f, 0.f);
            float4 vv = make_float4(0.f, 0.f, 0.f, 0.f);
            if (n < Nq) {
                kv = *(const float4*)(kbase + (size_t)n * QKV_N + c4);
                vv = *(const float4*)(vbase + (size_t)n * QKV_N + c4);
            }
            float kf[4] = {kv.x, kv.y, kv.z, kv.w};
            float vf[4] = {vv.x, vv.y, vv.z, vv.w};
            #pragma unroll
            for (int j = 0; j < 4; j++) {
                __nv_bfloat16 khh = __float2bfloat16_rn(kf[j]);
                __nv_bfloat16 kll = __float2bfloat16_rn(kf[j] - __bfloat162float(khh));
                Ks[r * FQK_S + c4 + j] = khh;
                Ks[r * FQK_S + 128 + c4 + j] = kll;
                __nv_bfloat16 vhh = __float2bfloat16_rn(vf[j]);
                __nv_bfloat16 vll = __float2bfloat16_rn(vf[j] - __bfloat162float(vhh));
                Vs[r * FV_S + c4 + j] = vhh;
                Vs[r * FV_S + 128 + c4 + j] = vll;
            }
        }
        __syncthreads();

        float accs[4][4];
        #pragma unroll
        for (int nj = 0; nj < 4; nj++)
            #pragma unroll
            for (int r = 0; r < 4; r++) accs[nj][r] = 0.f;

        #pragma unroll
        for (int ks = 0; ks < 24; ks++) {
            int aoff, boff;
            if (ks < 8)       { aoff = ks * 32;             boff = ks * 32; }
            else if (ks < 16) { aoff = 256 + (ks - 8) * 32; boff = (ks - 8) * 32; }
            else              { aoff = (ks - 16) * 32;      boff = 256 + (ks - 16) * 32; }

            uint32_t afr[4];
            {
                int row = wm * 16 + (lane & 15);
                LDSM_X4(afr, sq + (uint32_t)(row * FQK_B + aoff + ((lane >> 4) << 4)));
            }
            uint32_t bfr[4][2];
            #pragma unroll
            for (int bj = 0; bj < 2; bj++) {
                int row = wn * 32 + bj * 16 + ((lane >> 4) << 3) + (lane & 7);
                uint32_t r[4];
                LDSM_X4(r, skm + (uint32_t)(row * FQK_B + boff + (((lane >> 3) & 1) << 4)));
                bfr[2 * bj][0] = r[0];     bfr[2 * bj][1] = r[1];
                bfr[2 * bj + 1][0] = r[2]; bfr[2 * bj + 1][1] = r[3];
            }
            #pragma unroll
            for (int nj = 0; nj < 4; nj++)
                MMA16816_BF(accs[nj], afr, bfr[nj]);
        }

        {
            int r0 = wm * 16 + (lane >> 2);
            int cb = wn * 32 + 2 * (lane & 3);
            #pragma unroll
            for (int nj = 0; nj < 4; nj++) {
                int c = cb + nj * 8;
                Ps[r0 * FPS_S + c]           = accs[nj][0];
                Ps[r0 * FPS_S + c + 1]       = accs[nj][1];
                Ps[(r0 + 8) * FPS_S + c]     = accs[nj][2];
                Ps[(r0 + 8) * FPS_S + c + 1] = accs[nj][3];
            }
        }
        __syncthreads();

        {
            const int r = tid >> 2;
            const int q4 = tid & 3;
            float mx = -1e30f;
            #pragma unroll
            for (int c = q4 * 16; c < q4 * 16 + 16; c++) {
                bool valid = (k0g + c < Nq);
                float sv = valid ? Ps[r * FPS_S + c] : -1e30f;
                mx = fmaxf(mx, sv);
            }
            mx = fmaxf(mx, __shfl_xor_sync(0xffffffffu, mx, 1));
            mx = fmaxf(mx, __shfl_xor_sync(0xffffffffu, mx, 2));
            const float mold = m_s[r];
            const float mnew = fmaxf(mold, mx);
            float sum = 0.f;
            #pragma unroll
            for (int c = q4 * 16; c < q4 * 16 + 16; c++) {
                bool valid = (k0g + c < Nq);
                float pv = valid ? __expf(Ps[r * FPS_S + c] - mnew) : 0.f;
                sum += pv;
                __nv_bfloat16 ph = __float2bfloat16_rn(pv);
                __nv_bfloat16 pl = __float2bfloat16_rn(pv - __bfloat162float(ph));
                Pb[r * FPB_S + c]      = ph;
                Pb[r * FPB_S + 64 + c] = pl;
            }
            sum += __shfl_xor_sync(0xffffffffu, sum, 1);
            sum += __shfl_xor_sync(0xffffffffu, sum, 2);
            if (q4 == 0) {
                float cr = __expf(mold - mnew);
                l_s[r] = l_s[r] * cr + sum;
                m_s[r] = mnew;
                corr[r] = cr;
            }
        }
        __syncthreads();

        {
            float c0 = corr[wm * 16 + (lane >> 2)];
            float c1 = corr[wm * 16 + (lane >> 2) + 8];
            #pragma unroll
            for (int nj = 0; nj < 8; nj++) {
                acc_o[nj][0] *= c0; acc_o[nj][1] *= c0;
                acc_o[nj][2] *= c1; acc_o[nj][3] *= c1;
            }
        }

        #pragma unroll
        for (int ks = 0; ks < 12; ks++) {
            int aoff = (ks < 4) ? ks * 32
                     : (ks < 8) ? 128 + (ks - 4) * 32
                                : (ks - 8) * 32;
            int vco  = (ks < 8) ? 0 : 256;
            int krow = (ks & 3) * 16;

            uint32_t afr[4];
            {
                int row = wm * 16 + (lane & 15);
                LDSM_X4(afr, spb + (uint32_t)(row * FPB_B + aoff + ((lane >> 4) << 4)));
            }
            uint32_t bfr[8][2];
            #pragma unroll
            for (int g = 0; g < 4; g++) {
                int vrow = krow + (lane & 7) + (((lane >> 3) & 1) << 3);
                int bcol = vco + (wn * 64 + g * 16) * 2 + ((lane >> 4) << 4);
                uint32_t r[4];
                LDSM_X4_T(r, svm + (uint32_t)(vrow * FV_B + bcol));
                bfr[2 * g][0] = r[0];     bfr[2 * g][1] = r[1];
                bfr[2 * g + 1][0] = r[2]; bfr[2 * g + 1][1] = r[3];
            }
            #pragma unroll
            for (int nj = 0; nj < 8; nj++)
                MMA16816_BF(acc_o[nj], afr, bfr[nj]);
        }
        __syncthreads();
    }

    // ---- epilogue: normalize, split to fp16 [hi|lo], write to g_as ----
    {
        int r0 = wm * 16 + (lane >> 2);
        float invl0 = 1.f / l_s[r0];
        float invl1 = 1.f / l_s[r0 + 8];
        int n0v = q0 + r0;
        int n1v = q0 + r0 + 8;
        #pragma unroll
        for (int nj = 0; nj < 8; nj++) {
            int c = h * Dq + wn * 64 + nj * 8 + 2 * (lane & 3);
            if (n0v < Nq) {
                float o0 = acc_o[nj][0] * invl0;
                float o1 = acc_o[nj][1] * invl0;
                __half h0 = __float2half_rn(o0);
                __half h1 = __float2half_rn(o1);
                __half l0 = __float2half_rn(o0 - __half2float(h0));
                __half l1 = __float2half_rn(o1 - __half2float(h1));
                __half2 hh; hh.x = h0; hh.y = h1;
                __half2 ll; ll.x = l0; ll.y = l1;
                __half* row = outAs + (size_t)(b * Nq + n0v) * Ka;
                *(__half2*)(row + c)      = hh;
                *(__half2*)(row + Cq + c) = ll;
            }
            if (n1v < Nq) {
                float o0 = acc_o[nj][2] * invl1;
                float o1 = acc_o[nj][3] * invl1;
                __half h0 = __float2half_rn(o0);
                __half h1 = __float2half_rn(o1);
                __half l0 = __float2half_rn(o0 - __half2float(h0));
                __half l1 = __float2half_rn(o1 - __half2float(h1));
                __half2 hh; hh.x = h0; hh.y = h1;
                __half2 ll; ll.x = l0; ll.y = l1;
                __half* row = outAs + (size_t)(b * Nq + n1v) * Ka;
                *(__half2*)(row + c)      = hh;
                *(__half2*)(row + Cq + c) = ll;
            }
        }
    }
}

// ===========================================================================
extern "C" void kernel_launch(void* const* d_in, const int* in_sizes, int n_in,
                              void* d_out, int out_size)
{
    const float* x        = (const float*)d_in[0];
    const float* qkv_w    = (const float*)d_in[1];
    const float* qkv_b    = (const float*)d_in[2];
    const float* q_norm_w = (const float*)d_in[3];
    const float* k_norm_w = (const float*)d_in[4];
    const float* proj_w   = (const float*)d_in[5];
    const float* proj_b   = (const float*)d_in[6];
    float* out = (float*)d_out;

    float* qkvp = nullptr;
    __half *asp = nullptr, *wqp = nullptr, *wpp = nullptr;
    cudaGetSymbolAddress((void**)&qkvp, g_qkv);
    cudaGetSymbolAddress((void**)&asp, g_as);
    cudaGetSymbolAddress((void**)&wqp, g_wq);
    cudaGetSymbolAddress((void**)&wpp, g_wp);

    cudaFuncSetAttribute(gemm_mma,
                         cudaFuncAttributeMaxDynamicSharedMemorySize, GSMEM_TOTAL);
    cudaFuncSetAttribute(flash_attn_mma,
                         cudaFuncAttributeMaxDynamicSharedMemorySize, FA_SMEM_BYTES);

    const int mt = (Mq + GBM - 1) / GBM;        // 65
    const int nt_qkv = QKV_N / GBN;             // 75
    const int nt_prj = Cq / GBN;                // 25

    // 1) split A to fp16 [hi|lo]; round weights to fp16 (transposed)
    {
        size_t e2 = (size_t)Mq * Cq / 2;
        split_a_kernel<<<(unsigned)((e2 + 255) / 256), 256>>>(x, asp, Mq);
    }
    split_wt_kernel<<<dim3(QKV_N / 32, Cq / 32), dim3(32, 8)>>>(qkv_w, wqp, QKV_N);
    split_wt_kernel<<<dim3(Cq / 32, Cq / 32), dim3(32, 8)>>>(proj_w, wpp, Cq);

    // 2) qkv = x @ qkv_w + b   (fp16 2-pass)
    gemm_mma<<<mt * nt_qkv, 256, GSMEM_TOTAL>>>(
        asp, wqp, qkv_b, qkvp, Mq, QKV_N, mt, nt_qkv);

    // 3) RMSNorm q/k in place
    rmsnorm_kernel<<<dim3(Mq, 2), 256>>>(qkvp, q_norm_w, k_norm_w);

    // 4) attention -> g_as (fp16 [hi|lo] layout, ready for proj GEMM)
    flash_attn_mma<<<dim3(17, Hq, Bq), 256, FA_SMEM_BYTES>>>(qkvp, asp);

    // 5) out = att @ proj_w + b   (fp16 2-pass)
    gemm_mma<<<mt * nt_prj, 256, GSMEM_TOTAL>>>(
        asp, wpp, proj_b, out, Mq, Cq, mt, nt_prj);
}

// round 10
// speedup vs baseline: 1.6668x; 1.2682x over previous
#include <cuda_runtime.h>
#include <cuda_bf16.h>
#include <cuda_fp16.h>
#include <cstdint>
#include <math.h>

// Problem constants
#define Bq 8
#define Nq 1025
#define Cq 3200
#define Hq 25
#define Dq 128
#define Mq (Bq * Nq)        // 8200
#define QKV_N (3 * Cq)      // 9600
#define Ka 6400             // A-side K'': [Ah | Al] fp16 pairs
#define EPSq 1e-6f

// Scratch (__device__ globals per alloc-free rule)
__device__ float g_qkv[(size_t)Mq * QKV_N];
__device__ __half g_as[(size_t)Mq * Ka];          // A' = [hi|lo] fp16
__device__ __half g_wq[(size_t)QKV_N * Cq];       // qkv_w^T fp16 (hi only)
__device__ __half g_wp[(size_t)Cq * Cq];          // proj_w^T fp16 (hi only)

// ===========================================================================
// helpers
// ===========================================================================
__device__ __forceinline__ uint32_t smem_u32(const void* p) {
    uint32_t a;
    asm("{ .reg .u64 t; cvta.to.shared.u64 t, %1; cvt.u32.u64 %0, t; }"
        : "=r"(a) : "l"(p));
    return a;
}
__device__ __forceinline__ uint32_t swz128(uint32_t off) {
    return off ^ ((off >> 3) & 0x70);
}
__device__ __forceinline__ void cp16(uint32_t s, const void* g) {
    asm volatile("cp.async.cg.shared.global [%0], [%1], 16;"
                 :: "r"(s), "l"(g) : "memory");
}
#define CP_COMMIT() asm volatile("cp.async.commit_group;" ::: "memory")

#define LDSM_X4(r, addr)                                                       \
    asm volatile("ldmatrix.sync.aligned.m8n8.x4.shared.b16 {%0,%1,%2,%3}, [%4];" \
        : "=r"((r)[0]), "=r"((r)[1]), "=r"((r)[2]), "=r"((r)[3]) : "r"(addr))

#define LDSM_X4_T(r, addr)                                                     \
    asm volatile("ldmatrix.sync.aligned.m8n8.x4.trans.shared.b16 {%0,%1,%2,%3}, [%4];" \
        : "=r"((r)[0]), "=r"((r)[1]), "=r"((r)[2]), "=r"((r)[3]) : "r"(addr))

// fp16 MMA
#define MMA16816_F16(d, a, b)                                                  \
    asm volatile("mma.sync.aligned.m16n8k16.row.col.f32.f16.f16.f32 "          \
        "{%0,%1,%2,%3}, {%4,%5,%6,%7}, {%8,%9}, {%0,%1,%2,%3};"                \
        : "+f"((d)[0]), "+f"((d)[1]), "+f"((d)[2]), "+f"((d)[3])               \
        : "r"((a)[0]), "r"((a)[1]), "r"((a)[2]), "r"((a)[3]),                  \
          "r"((b)[0]), "r"((b)[1]))

// ===========================================================================
// Split kernels
// A: fp32 -> fp16 [hi | lo] pairs, row stride Ka=6400
// W: fp32 [K,N] -> fp16 W^T [N,K] hi only, row stride Cq
// ===========================================================================
__global__ __launch_bounds__(256) void split_a_kernel(
    const float* __restrict__ in, __half* __restrict__ out, int M)
{
    size_t idx = (size_t)blockIdx.x * 256 + threadIdx.x;
    if (idx * 2 >= (size_t)M * Cq) return;
    int m = (int)((idx * 2) / Cq);
    int k = (int)((idx * 2) % Cq);
    float2 v = *(const float2*)(in + (size_t)m * Cq + k);
    __half h0 = __float2half_rn(v.x);
    __half h1 = __float2half_rn(v.y);
    __half l0 = __float2half_rn(v.x - __half2float(h0));
    __half l1 = __float2half_rn(v.y - __half2float(h1));
    __half2 hh; hh.x = h0; hh.y = h1;
    __half2 ll; ll.x = l0; ll.y = l1;
    __half* row = out + (size_t)m * Ka;
    *(__half2*)(row + k)      = hh;
    *(__half2*)(row + Cq + k) = ll;
}

__global__ __launch_bounds__(256) void split_wt_kernel(
    const float* __restrict__ W, __half* __restrict__ out, int Nw)
{
    __shared__ float tile[32][33];
    int n0 = blockIdx.x * 32, k0 = blockIdx.y * 32;
    int tx = threadIdx.x, ty = threadIdx.y;       // 32 x 8
    #pragma unroll
    for (int i = ty; i < 32; i += 8)
        tile[i][tx] = W[(size_t)(k0 + i) * Nw + n0 + tx];
    __syncthreads();
    #pragma unroll
    for (int i = ty; i < 32; i += 8) {
        int n = n0 + i, k = k0 + tx;
        out[(size_t)n * Cq + k] = __float2half_rn(tile[tx][i]);
    }
}

// ===========================================================================
// fp16 mma.sync GEMM: C[M,Nt] = (Ah+Al)[M,Ka] @ Bh[Nt,Cq]^T + bias
// (unchanged proven structure: tensor=71.6%)
// ===========================================================================
#define GBM 128
#define GBN 128
#define GBK 64
#define GNIT (Ka / GBK)            // 100
#define ABYTES (GBM * GBK * 2)
#define BBYTES (GBN * GBK * 2)
#define BUFB (ABYTES + BBYTES)
#define GSTAGES 3
#define GSMEM_TOTAL (GSTAGES * BUFB)   // 96 KB
#define G_GM 8

__global__ __launch_bounds__(256, 2) void gemm_mma(
    const __half* __restrict__ A,
    const __half* __restrict__ Bt,
    const float* __restrict__ bias,
    float* __restrict__ C,
    int M, int Nt, int mt, int nt)
{
    extern __shared__ char smem[];
    const uint32_t sbase = smem_u32(smem);
    const int tid = threadIdx.x;
    const int wid = tid >> 5, lane = tid & 31;
    const int wm = wid >> 2, wn = wid & 3;

    int bid = blockIdx.x;
    int per_group = G_GM * nt;
    int gid = bid / per_group;
    int first_m = gid * G_GM;
    int gsz = min(G_GM, mt - first_m);
    int rem = bid % per_group;
    const int m0 = (first_m + rem % gsz) * GBM;
    const int n0 = (rem / gsz) * GBN;

    float acc[4][4][4];
    #pragma unroll
    for (int i = 0; i < 4; i++)
        #pragma unroll
        for (int j = 0; j < 4; j++)
            #pragma unroll
            for (int r = 0; r < 4; r++) acc[i][j][r] = 0.f;

    auto load_tile = [&](int it, int buf) {
        const int k0 = it * GBK;
        const int bk0 = (k0 >= Cq) ? (k0 - Cq) : k0;
        const uint32_t sA = sbase + buf * BUFB;
        const uint32_t sB = sA + ABYTES;
        #pragma unroll
        for (int p = 0; p < 4; p++) {
            int id = p * 256 + tid;
            int row = id >> 3, ch = id & 7;
            uint32_t so = swz128((uint32_t)(row * 128 + ch * 16));
            int m = min(m0 + row, M - 1);
            cp16(sA + so, A  + (size_t)m * Ka + k0 + ch * 8);
            cp16(sB + so, Bt + (size_t)(n0 + row) * Cq + bk0 + ch * 8);
        }
        CP_COMMIT();
    };

    auto compute = [&](int buf) {
        const uint32_t sA = sbase + buf * BUFB + (uint32_t)(wm * 64 * 128);
        const uint32_t sB = sbase + buf * BUFB + ABYTES + (uint32_t)(wn * 32 * 128);
        #pragma unroll
        for (int kk = 0; kk < 4; kk++) {
            uint32_t afr[4][4];
            #pragma unroll
            for (int mi = 0; mi < 4; mi++) {
                int row = mi * 16 + (lane & 15);
                int cb = kk * 32 + ((lane >> 4) << 4);
                LDSM_X4(afr[mi], sA + swz128((uint32_t)(row * 128 + cb)));
            }
            uint32_t bfr[4][2];
            #pragma unroll
            for (int bj = 0; bj < 2; bj++) {
                int row = bj * 16 + ((lane >> 4) << 3) + (lane & 7);
                int cb = kk * 32 + (((lane >> 3) & 1) << 4);
                uint32_t r[4];
                LDSM_X4(r, sB + swz128((uint32_t)(row * 128 + cb)));
                bfr[2 * bj][0] = r[0];     bfr[2 * bj][1] = r[1];
                bfr[2 * bj + 1][0] = r[2]; bfr[2 * bj + 1][1] = r[3];
            }
            #pragma unroll
            for (int mi = 0; mi < 4; mi++)
                #pragma unroll
                for (int nj = 0; nj < 4; nj++)
                    MMA16816_F16(acc[mi][nj], afr[mi], bfr[nj]);
        }
    };

    load_tile(0, 0);
    load_tile(1, 1);
    for (int it = 0; it < GNIT; it++) {
        if (it + 1 < GNIT)
            asm volatile("cp.async.wait_group 1;" ::: "memory");
        else
            asm volatile("cp.async.wait_group 0;" ::: "memory");
        __syncthreads();
        if (it + 2 < GNIT) load_tile(it + 2, (it + 2) % GSTAGES);
        compute(it % GSTAGES);
    }

    const int mbase = m0 + wm * 64;
    const int nbase = n0 + wn * 32;
    #pragma unroll
    for (int mi = 0; mi < 4; mi++) {
        #pragma unroll
        for (int nj = 0; nj < 4; nj++) {
            int r0 = mbase + mi * 16 + (lane >> 2);
            int c = nbase + nj * 8 + 2 * (lane & 3);
            float bx = bias[c], by = bias[c + 1];
            if (r0 < M) {
                float2 o = make_float2(acc[mi][nj][0] + bx, acc[mi][nj][1] + by);
                *(float2*)(C + (size_t)r0 * Nt + c) = o;
            }
            if (r0 + 8 < M) {
                float2 o = make_float2(acc[mi][nj][2] + bx, acc[mi][nj][3] + by);
                *(float2*)(C + (size_t)(r0 + 8) * Nt + c) = o;
            }
        }
    }
}

// ===========================================================================
// RMSNorm in-place over q / k slices of g_qkv.
// ===========================================================================
__global__ __launch_bounds__(256) void rmsnorm_kernel(
    float* __restrict__ qkv, const float* __restrict__ qw,
    const float* __restrict__ kw)
{
    const int row = blockIdx.x;
    const int which = blockIdx.y;
    const float* w = which ? kw : qw;
    float* p = qkv + (size_t)row * QKV_N + which * Cq;

    float ss = 0.f;
    for (int c = threadIdx.x * 4; c < Cq; c += 256 * 4) {
        float4 v = *(const float4*)(p + c);
        ss += v.x * v.x + v.y * v.y + v.z * v.z + v.w * v.w;
    }
    #pragma unroll
    for (int o = 16; o; o >>= 1) ss += __shfl_xor_sync(0xffffffffu, ss, o);
    __shared__ float red[8];
    if ((threadIdx.x & 31) == 0) red[threadIdx.x >> 5] = ss;
    __syncthreads();
    if (threadIdx.x < 8) {
        float v = red[threadIdx.x];
        #pragma unroll
        for (int o = 4; o; o >>= 1) v += __shfl_xor_sync(0xffu, v, o);
        if (threadIdx.x == 0) red[0] = v;
    }
    __syncthreads();
    const float inv = rsqrtf(red[0] * (1.f / Cq) + EPSq);
    for (int c = threadIdx.x * 4; c < Cq; c += 256 * 4) {
        float4 v = *(const float4*)(p + c);
        float4 wv = *(const float4*)(w + c);
        v.x *= inv * wv.x; v.y *= inv * wv.y;
        v.z *= inv * wv.z; v.w *= inv * wv.w;
        *(float4*)(p + c) = v;
    }
}

// ===========================================================================
// Flash attention, fp16 2-term everywhere:
//   S = (Qh+Ql) Kh^T   (16 k16-steps)
//   O = (Ph+Pl) Vh     (8 k16-steps)
// Q rows [hi 128 | lo 128] fp16; K/V rows 128 fp16; P rows [ph 64 | pl 64].
// Row strides *2 bytes ≡ 16 mod 128 -> conflict-free ldmatrix.
// ===========================================================================
#define FQ_S 264
#define FQ_B (FQ_S * 2)      // 528
#define FK_S 136
#define FK_B (FK_S * 2)      // 272
#define FV_S 136
#define FV_B (FV_S * 2)      // 272
#define FPS_S 68
#define FPB_S 136
#define FPB_B (FPB_S * 2)    // 272

#define FA_Q_OFF 0
#define FA_K_OFF (64 * FQ_S * 2)                  // 33792
#define FA_V_OFF (FA_K_OFF + 64 * FK_S * 2)       // 51200
#define FA_PS_OFF (FA_V_OFF + 64 * FV_S * 2)      // 68608
#define FA_PB_OFF (FA_PS_OFF + 64 * FPS_S * 4)    // 86016
#define FA_ML_OFF (FA_PB_OFF + 64 * FPB_S * 2)    // 103424
#define FA_SMEM_BYTES (FA_ML_OFF + 3 * 64 * 4)    // 104192

__global__ __launch_bounds__(256, 2) void flash_attn_mma(
    const float* __restrict__ qkv, __half* __restrict__ outAs)
{
    extern __shared__ char sm[];
    __half* Qs = (__half*)(sm + FA_Q_OFF);
    __half* Ks = (__half*)(sm + FA_K_OFF);
    __half* Vs = (__half*)(sm + FA_V_OFF);
    float*  Ps = (float*)(sm + FA_PS_OFF);
    __half* Pb = (__half*)(sm + FA_PB_OFF);
    float* m_s = (float*)(sm + FA_ML_OFF);
    float* l_s = m_s + 64;
    float* corr = l_s + 64;

    const uint32_t sq  = smem_u32(Qs);
    const uint32_t skm = smem_u32(Ks);
    const uint32_t svm = smem_u32(Vs);
    const uint32_t spb = smem_u32(Pb);

    const int qt = blockIdx.x;
    const int h  = blockIdx.y;
    const int b  = blockIdx.z;
    const int tid = threadIdx.x;
    const int wid = tid >> 5, lane = tid & 31;
    const int wm = wid >> 1, wn = wid & 1;          // 4 x 2 warp grid
    const float scale = 0.08838834764831845f;       // 128^-0.5

    const int q0 = qt * 64;
    const float* qbase = qkv + (size_t)b * Nq * QKV_N + h * Dq;
    const float* kbase = qbase + Cq;
    const float* vbase = qbase + 2 * Cq;

    // ---- load Q tile, prescale, split fp16 hi/lo ----
    for (int idx = tid; idx < 64 * 32; idx += 256) {
        int r = idx >> 5, c4 = (idx & 31) * 4;
        int n = q0 + r;
        float4 v = make_float4(0.f, 0.f, 0.f, 0.f);
        if (n < Nq) v = *(const float4*)(qbase + (size_t)n * QKV_N + c4);
        float f[4] = {v.x * scale, v.y * scale, v.z * scale, v.w * scale};
        #pragma unroll
        for (int j = 0; j < 4; j++) {
            __half hh = __float2half_rn(f[j]);
            __half ll = __float2half_rn(f[j] - __half2float(hh));
            Qs[r * FQ_S + c4 + j] = hh;
            Qs[r * FQ_S + 128 + c4 + j] = ll;
        }
    }
    if (tid < 64) { m_s[tid] = -1e30f; l_s[tid] = 0.f; }

    float acc_o[8][4];
    #pragma unroll
    for (int nj = 0; nj < 8; nj++)
        #pragma unroll
        for (int r = 0; r < 4; r++) acc_o[nj][r] = 0.f;
    __syncthreads();

    for (int kt = 0; kt < 17; kt++) {
        const int k0g = kt * 64;

        // ---- load K, V tiles (fp16, hi only) ----
        for (int idx = tid; idx < 64 * 32; idx += 256) {
            int r = idx >> 5, c4 = (idx & 31) * 4;
            int n = k0g + r;
            float4 kv = make_float4(0.f, 0.f, 0.f, 0.f);
            float4 vv = make_float4(0.f, 0.f, 0.f, 0.f);
            if (n < Nq) {
                kv = *(const float4*)(kbase + (size_t)n * QKV_N + c4);
                vv = *(const float4*)(vbase + (size_t)n * QKV_N + c4);
            }
            __half2 k0h; k0h.x = __float2half_rn(kv.x); k0h.y = __float2half_rn(kv.y);
            __half2 k1h; k1h.x = __float2half_rn(kv.z); k1h.y = __float2half_rn(kv.w);
            *(__half2*)&Ks[r * FK_S + c4]     = k0h;
            *(__half2*)&Ks[r * FK_S + c4 + 2] = k1h;
            __half2 v0h; v0h.x = __float2half_rn(vv.x); v0h.y = __float2half_rn(vv.y);
            __half2 v1h; v1h.x = __float2half_rn(vv.z); v1h.y = __float2half_rn(vv.w);
            *(__half2*)&Vs[r * FV_S + c4]     = v0h;
            *(__half2*)&Vs[r * FV_S + c4 + 2] = v1h;
        }
        __syncthreads();

        // ---- S = (Qh+Ql) Kh^T : 16 k16-steps ----
        float accs[4][4];
        #pragma unroll
        for (int nj = 0; nj < 4; nj++)
            #pragma unroll
            for (int r = 0; r < 4; r++) accs[nj][r] = 0.f;

        #pragma unroll
        for (int ks = 0; ks < 16; ks++) {
            int aoff = (ks < 8) ? ks * 32 : 256 + (ks - 8) * 32;  // Qh then Ql
            int boff = (ks & 7) * 32;

            uint32_t afr[4];
            {
                int row = wm * 16 + (lane & 15);
                LDSM_X4(afr, sq + (uint32_t)(row * FQ_B + aoff + ((lane >> 4) << 4)));
            }
            uint32_t bfr[4][2];
            #pragma unroll
            for (int bj = 0; bj < 2; bj++) {
                int row = wn * 32 + bj * 16 + ((lane >> 4) << 3) + (lane & 7);
                uint32_t r[4];
                LDSM_X4(r, skm + (uint32_t)(row * FK_B + boff + (((lane >> 3) & 1) << 4)));
                bfr[2 * bj][0] = r[0];     bfr[2 * bj][1] = r[1];
                bfr[2 * bj + 1][0] = r[2]; bfr[2 * bj + 1][1] = r[3];
            }
            #pragma unroll
            for (int nj = 0; nj < 4; nj++)
                MMA16816_F16(accs[nj], afr, bfr[nj]);
        }

        // ---- write S fragments to Ps ----
        {
            int r0 = wm * 16 + (lane >> 2);
            int cb = wn * 32 + 2 * (lane & 3);
            #pragma unroll
            for (int nj = 0; nj < 4; nj++) {
                int c = cb + nj * 8;
                Ps[r0 * FPS_S + c]           = accs[nj][0];
                Ps[r0 * FPS_S + c + 1]       = accs[nj][1];
                Ps[(r0 + 8) * FPS_S + c]     = accs[nj][2];
                Ps[(r0 + 8) * FPS_S + c + 1] = accs[nj][3];
            }
        }
        __syncthreads();

        // ---- online softmax, write ph/pl (fp16) ----
        {
            const int r = tid >> 2;
            const int q4 = tid & 3;
            float mx = -1e30f;
            #pragma unroll
            for (int c = q4 * 16; c < q4 * 16 + 16; c++) {
                bool valid = (k0g + c < Nq);
                float sv = valid ? Ps[r * FPS_S + c] : -1e30f;
                mx = fmaxf(mx, sv);
            }
            mx = fmaxf(mx, __shfl_xor_sync(0xffffffffu, mx, 1));
            mx = fmaxf(mx, __shfl_xor_sync(0xffffffffu, mx, 2));
            const float mold = m_s[r];
            const float mnew = fmaxf(mold, mx);
            float sum = 0.f;
            #pragma unroll
            for (int c = q4 * 16; c < q4 * 16 + 16; c++) {
                bool valid = (k0g + c < Nq);
                float pv = valid ? __expf(Ps[r * FPS_S + c] - mnew) : 0.f;
                sum += pv;
                __half ph = __float2half_rn(pv);
                __half pl = __float2half_rn(pv - __half2float(ph));
                Pb[r * FPB_S + c]      = ph;
                Pb[r * FPB_S + 64 + c] = pl;
            }
            sum += __shfl_xor_sync(0xffffffffu, sum, 1);
            sum += __shfl_xor_sync(0xffffffffu, sum, 2);
            if (q4 == 0) {
                float cr = __expf(mold - mnew);
                l_s[r] = l_s[r] * cr + sum;
                m_s[r] = mnew;
                corr[r] = cr;
            }
        }
        __syncthreads();

        // ---- rescale O accumulators ----
        {
            float c0 = corr[wm * 16 + (lane >> 2)];
            float c1 = corr[wm * 16 + (lane >> 2) + 8];
            #pragma unroll
            for (int nj = 0; nj < 8; nj++) {
                acc_o[nj][0] *= c0; acc_o[nj][1] *= c0;
                acc_o[nj][2] *= c1; acc_o[nj][3] *= c1;
            }
        }

        // ---- O += (Ph+Pl) Vh : 8 k16-steps ----
        #pragma unroll
        for (int ks = 0; ks < 8; ks++) {
            int aoff = (ks < 4) ? ks * 32 : 128 + (ks - 4) * 32;  // Ph then Pl
            int krow = (ks & 3) * 16;

            uint32_t afr[4];
            {
                int row = wm * 16 + (lane & 15);
                LDSM_X4(afr, spb + (uint32_t)(row * FPB_B + aoff + ((lane >> 4) << 4)));
            }
            uint32_t bfr[8][2];
            #pragma unroll
            for (int g = 0; g < 4; g++) {
                int vrow = krow + (lane & 7) + (((lane >> 3) & 1) << 3);
                int bcol = (wn * 64 + g * 16) * 2 + ((lane >> 4) << 4);
                uint32_t r[4];
                LDSM_X4_T(r, svm + (uint32_t)(vrow * FV_B + bcol));
                bfr[2 * g][0] = r[0];     bfr[2 * g][1] = r[1];
                bfr[2 * g + 1][0] = r[2]; bfr[2 * g + 1][1] = r[3];
            }
            #pragma unroll
            for (int nj = 0; nj < 8; nj++)
                MMA16816_F16(acc_o[nj], afr, bfr[nj]);
        }
        __syncthreads();
    }

    // ---- epilogue: normalize, split to fp16 [hi|lo], write to g_as ----
    {
        int r0 = wm * 16 + (lane >> 2);
        float invl0 = 1.f / l_s[r0];
        float invl1 = 1.f / l_s[r0 + 8];
        int n0v = q0 + r0;
        int n1v = q0 + r0 + 8;
        #pragma unroll
        for (int nj = 0; nj < 8; nj++) {
            int c = h * Dq + wn * 64 + nj * 8 + 2 * (lane & 3);
            if (n0v < Nq) {
                float o0 = acc_o[nj][0] * invl0;
                float o1 = acc_o[nj][1] * invl0;
                __half h0 = __float2half_rn(o0);
                __half h1 = __float2half_rn(o1);
                __half l0 = __float2half_rn(o0 - __half2float(h0));
                __half l1 = __float2half_rn(o1 - __half2float(h1));
                __half2 hh; hh.x = h0; hh.y = h1;
                __half2 ll; ll.x = l0; ll.y = l1;
                __half* row = outAs + (size_t)(b * Nq + n0v) * Ka;
                *(__half2*)(row + c)      = hh;
                *(__half2*)(row + Cq + c) = ll;
            }
            if (n1v < Nq) {
                float o0 = acc_o[nj][2] * invl1;
                float o1 = acc_o[nj][3] * invl1;
                __half h0 = __float2half_rn(o0);
                __half h1 = __float2half_rn(o1);
                __half l0 = __float2half_rn(o0 - __half2float(h0));
                __half l1 = __float2half_rn(o1 - __half2float(h1));
                __half2 hh; hh.x = h0; hh.y = h1;
                __half2 ll; ll.x = l0; ll.y = l1;
                __half* row = outAs + (size_t)(b * Nq + n1v) * Ka;
                *(__half2*)(row + c)      = hh;
                *(__half2*)(row + Cq + c) = ll;
            }
        }
    }
}

// ===========================================================================
extern "C" void kernel_launch(void* const* d_in, const int* in_sizes, int n_in,
                              void* d_out, int out_size)
{
    const float* x        = (const float*)d_in[0];
    const float* qkv_w    = (const float*)d_in[1];
    const float* qkv_b    = (const float*)d_in[2];
    const float* q_norm_w = (const float*)d_in[3];
    const float* k_norm_w = (const float*)d_in[4];
    const float* proj_w   = (const float*)d_in[5];
    const float* proj_b   = (const float*)d_in[6];
    float* out = (float*)d_out;

    float* qkvp = nullptr;
    __half *asp = nullptr, *wqp = nullptr, *wpp = nullptr;
    cudaGetSymbolAddress((void**)&qkvp, g_qkv);
    cudaGetSymbolAddress((void**)&asp, g_as);
    cudaGetSymbolAddress((void**)&wqp, g_wq);
    cudaGetSymbolAddress((void**)&wpp, g_wp);

    cudaFuncSetAttribute(gemm_mma,
                         cudaFuncAttributeMaxDynamicSharedMemorySize, GSMEM_TOTAL);
    cudaFuncSetAttribute(flash_attn_mma,
                         cudaFuncAttributeMaxDynamicSharedMemorySize, FA_SMEM_BYTES);

    const int mt = (Mq + GBM - 1) / GBM;        // 65
    const int nt_qkv = QKV_N / GBN;             // 75
    const int nt_prj = Cq / GBN;                // 25

    // 1) split A to fp16 [hi|lo]; round weights to fp16 (transposed)
    {
        size_t e2 = (size_t)Mq * Cq / 2;
        split_a_kernel<<<(unsigned)((e2 + 255) / 256), 256>>>(x, asp, Mq);
    }
    split_wt_kernel<<<dim3(QKV_N / 32, Cq / 32), dim3(32, 8)>>>(qkv_w, wqp, QKV_N);
    split_wt_kernel<<<dim3(Cq / 32, Cq / 32), dim3(32, 8)>>>(proj_w, wpp, Cq);

    // 2) qkv = x @ qkv_w + b   (fp16 2-pass)
    gemm_mma<<<mt * nt_qkv, 256, GSMEM_TOTAL>>>(
        asp, wqp, qkv_b, qkvp, Mq, QKV_N, mt, nt_qkv);

    // 3) RMSNorm q/k in place
    rmsnorm_kernel<<<dim3(Mq, 2), 256>>>(qkvp, q_norm_w, k_norm_w);

    // 4) attention -> g_as (fp16 [hi|lo] layout, ready for proj GEMM)
    flash_attn_mma<<<dim3(17, Hq, Bq), 256, FA_SMEM_BYTES>>>(qkvp, asp);

    // 5) out = att @ proj_w + b   (fp16 2-pass)
    gemm_mma<<<mt * nt_prj, 256, GSMEM_TOTAL>>>(
        asp, wpp, proj_b, out, Mq, Cq, mt, nt_prj);
}

// round 11
// speedup vs baseline: 1.8992x; 1.1394x over previous
#include <cuda_runtime.h>
#include <cuda_bf16.h>
#include <cuda_fp16.h>
#include <cstdint>
#include <math.h>

// Problem constants
#define Bq 8
#define Nq 1025
#define Cq 3200
#define Hq 25
#define Dq 128
#define Mq (Bq * Nq)        // 8200
#define QKV_N (3 * Cq)      // 9600
#define Ka 6400             // A-side K'': [Ah | Al] fp16 pairs
#define EPSq 1e-6f

// Scratch (__device__ globals per alloc-free rule)
__device__ float g_qkv[(size_t)Mq * QKV_N];
__device__ __half g_as[(size_t)Mq * Ka];            // A' = [hi|lo] fp16 (GEMM input)
__device__ __half g_wq[(size_t)QKV_N * Cq];         // qkv_w^T fp16
__device__ __half g_wp[(size_t)Cq * Cq];            // proj_w^T fp16
__device__ __half g_q[(size_t)Bq * Hq * Nq * 256];  // q: [b][h][n][hi128|lo128], prescaled+normed
__device__ __half g_k[(size_t)Bq * Hq * Nq * 128];  // k: fp16, normed
__device__ __half g_v[(size_t)Bq * Hq * Nq * 128];  // v: fp16

// ===========================================================================
// helpers
// ===========================================================================
__device__ __forceinline__ uint32_t smem_u32(const void* p) {
    uint32_t a;
    asm("{ .reg .u64 t; cvta.to.shared.u64 t, %1; cvt.u32.u64 %0, t; }"
        : "=r"(a) : "l"(p));
    return a;
}
__device__ __forceinline__ uint32_t swz128(uint32_t off) {
    return off ^ ((off >> 3) & 0x70);
}
__device__ __forceinline__ void cp16(uint32_t s, const void* g) {
    asm volatile("cp.async.cg.shared.global [%0], [%1], 16;"
                 :: "r"(s), "l"(g) : "memory");
}
__device__ __forceinline__ void cp16z(uint32_t s, const void* g, int sz) {
    asm volatile("cp.async.cg.shared.global [%0], [%1], 16, %2;"
                 :: "r"(s), "l"(g), "r"(sz) : "memory");
}
#define CP_COMMIT() asm volatile("cp.async.commit_group;" ::: "memory")

#define LDSM_X4(r, addr)                                                       \
    asm volatile("ldmatrix.sync.aligned.m8n8.x4.shared.b16 {%0,%1,%2,%3}, [%4];" \
        : "=r"((r)[0]), "=r"((r)[1]), "=r"((r)[2]), "=r"((r)[3]) : "r"(addr))

#define LDSM_X4_T(r, addr)                                                     \
    asm volatile("ldmatrix.sync.aligned.m8n8.x4.trans.shared.b16 {%0,%1,%2,%3}, [%4];" \
        : "=r"((r)[0]), "=r"((r)[1]), "=r"((r)[2]), "=r"((r)[3]) : "r"(addr))

#define MMA16816_F16(d, a, b)                                                  \
    asm volatile("mma.sync.aligned.m16n8k16.row.col.f32.f16.f16.f32 "          \
        "{%0,%1,%2,%3}, {%4,%5,%6,%7}, {%8,%9}, {%0,%1,%2,%3};"                \
        : "+f"((d)[0]), "+f"((d)[1]), "+f"((d)[2]), "+f"((d)[3])               \
        : "r"((a)[0]), "r"((a)[1]), "r"((a)[2]), "r"((a)[3]),                  \
          "r"((b)[0]), "r"((b)[1]))

__device__ __forceinline__ void pack_hl(float x, float y, uint32_t& hp, uint32_t& lp) {
    __half hx = __float2half_rn(x), hy = __float2half_rn(y);
    __half lx = __float2half_rn(x - __half2float(hx));
    __half ly = __float2half_rn(y - __half2float(hy));
    __half2 h2; h2.x = hx; h2.y = hy;
    __half2 l2; l2.x = lx; l2.y = ly;
    hp = *(uint32_t*)&h2;
    lp = *(uint32_t*)&l2;
}

// ===========================================================================
// Split kernels (unchanged, proven)
// ===========================================================================
__global__ __launch_bounds__(256) void split_a_kernel(
    const float* __restrict__ in, __half* __restrict__ out, int M)
{
    size_t idx = (size_t)blockIdx.x * 256 + threadIdx.x;
    if (idx * 2 >= (size_t)M * Cq) return;
    int m = (int)((idx * 2) / Cq);
    int k = (int)((idx * 2) % Cq);
    float2 v = *(const float2*)(in + (size_t)m * Cq + k);
    __half h0 = __float2half_rn(v.x);
    __half h1 = __float2half_rn(v.y);
    __half l0 = __float2half_rn(v.x - __half2float(h0));
    __half l1 = __float2half_rn(v.y - __half2float(h1));
    __half2 hh; hh.x = h0; hh.y = h1;
    __half2 ll; ll.x = l0; ll.y = l1;
    __half* row = out + (size_t)m * Ka;
    *(__half2*)(row + k)      = hh;
    *(__half2*)(row + Cq + k) = ll;
}

__global__ __launch_bounds__(256) void split_wt_kernel(
    const float* __restrict__ W, __half* __restrict__ out, int Nw)
{
    __shared__ float tile[32][33];
    int n0 = blockIdx.x * 32, k0 = blockIdx.y * 32;
    int tx = threadIdx.x, ty = threadIdx.y;
    #pragma unroll
    for (int i = ty; i < 32; i += 8)
        tile[i][tx] = W[(size_t)(k0 + i) * Nw + n0 + tx];
    __syncthreads();
    #pragma unroll
    for (int i = ty; i < 32; i += 8) {
        int n = n0 + i, k = k0 + tx;
        out[(size_t)n * Cq + k] = __float2half_rn(tile[tx][i]);
    }
}

// ===========================================================================
// fp16 mma.sync GEMM (unchanged, proven: tensor=71.8%)
// ===========================================================================
#define GBM 128
#define GBN 128
#define GBK 64
#define GNIT (Ka / GBK)
#define ABYTES (GBM * GBK * 2)
#define BBYTES (GBN * GBK * 2)
#define BUFB (ABYTES + BBYTES)
#define GSTAGES 3
#define GSMEM_TOTAL (GSTAGES * BUFB)
#define G_GM 8

__global__ __launch_bounds__(256, 2) void gemm_mma(
    const __half* __restrict__ A,
    const __half* __restrict__ Bt,
    const float* __restrict__ bias,
    float* __restrict__ C,
    int M, int Nt, int mt, int nt)
{
    extern __shared__ char smem[];
    const uint32_t sbase = smem_u32(smem);
    const int tid = threadIdx.x;
    const int wid = tid >> 5, lane = tid & 31;
    const int wm = wid >> 2, wn = wid & 3;

    int bid = blockIdx.x;
    int per_group = G_GM * nt;
    int gid = bid / per_group;
    int first_m = gid * G_GM;
    int gsz = min(G_GM, mt - first_m);
    int rem = bid % per_group;
    const int m0 = (first_m + rem % gsz) * GBM;
    const int n0 = (rem / gsz) * GBN;

    float acc[4][4][4];
    #pragma unroll
    for (int i = 0; i < 4; i++)
        #pragma unroll
        for (int j = 0; j < 4; j++)
            #pragma unroll
            for (int r = 0; r < 4; r++) acc[i][j][r] = 0.f;

    auto load_tile = [&](int it, int buf) {
        const int k0 = it * GBK;
        const int bk0 = (k0 >= Cq) ? (k0 - Cq) : k0;
        const uint32_t sA = sbase + buf * BUFB;
        const uint32_t sB = sA + ABYTES;
        #pragma unroll
        for (int p = 0; p < 4; p++) {
            int id = p * 256 + tid;
            int row = id >> 3, ch = id & 7;
            uint32_t so = swz128((uint32_t)(row * 128 + ch * 16));
            int m = min(m0 + row, M - 1);
            cp16(sA + so, A  + (size_t)m * Ka + k0 + ch * 8);
            cp16(sB + so, Bt + (size_t)(n0 + row) * Cq + bk0 + ch * 8);
        }
        CP_COMMIT();
    };

    auto compute = [&](int buf) {
        const uint32_t sA = sbase + buf * BUFB + (uint32_t)(wm * 64 * 128);
        const uint32_t sB = sbase + buf * BUFB + ABYTES + (uint32_t)(wn * 32 * 128);
        #pragma unroll
        for (int kk = 0; kk < 4; kk++) {
            uint32_t afr[4][4];
            #pragma unroll
            for (int mi = 0; mi < 4; mi++) {
                int row = mi * 16 + (lane & 15);
                int cb = kk * 32 + ((lane >> 4) << 4);
                LDSM_X4(afr[mi], sA + swz128((uint32_t)(row * 128 + cb)));
            }
            uint32_t bfr[4][2];
            #pragma unroll
            for (int bj = 0; bj < 2; bj++) {
                int row = bj * 16 + ((lane >> 4) << 3) + (lane & 7);
                int cb = kk * 32 + (((lane >> 3) & 1) << 4);
                uint32_t r[4];
                LDSM_X4(r, sB + swz128((uint32_t)(row * 128 + cb)));
                bfr[2 * bj][0] = r[0];     bfr[2 * bj][1] = r[1];
                bfr[2 * bj + 1][0] = r[2]; bfr[2 * bj + 1][1] = r[3];
            }
            #pragma unroll
            for (int mi = 0; mi < 4; mi++)
                #pragma unroll
                for (int nj = 0; nj < 4; nj++)
                    MMA16816_F16(acc[mi][nj], afr[mi], bfr[nj]);
        }
    };

    load_tile(0, 0);
    load_tile(1, 1);
    for (int it = 0; it < GNIT; it++) {
        if (it + 1 < GNIT)
            asm volatile("cp.async.wait_group 1;" ::: "memory");
        else
            asm volatile("cp.async.wait_group 0;" ::: "memory");
        __syncthreads();
        if (it + 2 < GNIT) load_tile(it + 2, (it + 2) % GSTAGES);
        compute(it % GSTAGES);
    }

    const int mbase = m0 + wm * 64;
    const int nbase = n0 + wn * 32;
    #pragma unroll
    for (int mi = 0; mi < 4; mi++) {
        #pragma unroll
        for (int nj = 0; nj < 4; nj++) {
            int r0 = mbase + mi * 16 + (lane >> 2);
            int c = nbase + nj * 8 + 2 * (lane & 3);
            float bx = bias[c], by = bias[c + 1];
            if (r0 < M) {
                float2 o = make_float2(acc[mi][nj][0] + bx, acc[mi][nj][1] + by);
                *(float2*)(C + (size_t)r0 * Nt + c) = o;
            }
            if (r0 + 8 < M) {
                float2 o = make_float2(acc[mi][nj][2] + bx, acc[mi][nj][3] + by);
                *(float2*)(C + (size_t)(r0 + 8) * Nt + c) = o;
            }
        }
    }
}

// ===========================================================================
// Fused rmsnorm + fp16 convert + head-contiguous layout.
// which=0: q -> norm, *scale, split hi/lo -> g_q [b][h][n][hi128|lo128]
// which=1: k -> norm, fp16           -> g_k [b][h][n][128]
// which=2: v -> fp16                 -> g_v [b][h][n][128]
// ===========================================================================
__global__ __launch_bounds__(256) void fuse_nc(
    const float* __restrict__ qkv,
    const float* __restrict__ qw, const float* __restrict__ kw,
    __half* __restrict__ gq, __half* __restrict__ gk, __half* __restrict__ gv)
{
    const int row = blockIdx.x;         // 0..Mq-1
    const int which = blockIdx.y;       // 0 q, 1 k, 2 v
    const int b = row / Nq, n = row % Nq;
    const float* p = qkv + (size_t)row * QKV_N + which * Cq;
    const int tid = threadIdx.x;

    float inv = 1.f;
    if (which < 2) {
        float ss = 0.f;
        for (int c = tid * 4; c < Cq; c += 1024) {
            float4 v = *(const float4*)(p + c);
            ss += v.x * v.x + v.y * v.y + v.z * v.z + v.w * v.w;
        }
        #pragma unroll
        for (int o = 16; o; o >>= 1) ss += __shfl_xor_sync(0xffffffffu, ss, o);
        __shared__ float red[8];
        if ((tid & 31) == 0) red[tid >> 5] = ss;
        __syncthreads();
        if (tid < 8) {
            float v = red[tid];
            #pragma unroll
            for (int o = 4; o; o >>= 1) v += __shfl_xor_sync(0xffu, v, o);
            if (tid == 0) red[0] = v;
        }
        __syncthreads();
        inv = rsqrtf(red[0] * (1.f / Cq) + EPSq);
    }

    if (which == 0) {
        const float sc = 0.08838834764831845f;
        for (int c = tid * 4; c < Cq; c += 1024) {
            float4 v = *(const float4*)(p + c);
            float4 wv = *(const float4*)(qw + c);
            int h = c >> 7, d = c & 127;
            __half* orow = gq + ((size_t)(b * Hq + h) * Nq + n) * 256;
            float f0 = v.x * inv * wv.x * sc;
            float f1 = v.y * inv * wv.y * sc;
            float f2 = v.z * inv * wv.z * sc;
            float f3 = v.w * inv * wv.w * sc;
            uint32_t h01, l01, h23, l23;
            pack_hl(f0, f1, h01, l01);
            pack_hl(f2, f3, h23, l23);
            *(uint32_t*)(orow + d)           = h01;
            *(uint32_t*)(orow + d + 2)       = h23;
            *(uint32_t*)(orow + 128 + d)     = l01;
            *(uint32_t*)(orow + 128 + d + 2) = l23;
        }
    } else if (which == 1) {
        for (int c = tid * 4; c < Cq; c += 1024) {
            float4 v = *(const float4*)(p + c);
            float4 wv = *(const float4*)(kw + c);
            int h = c >> 7, d = c & 127;
            __half* orow = gk + ((size_t)(b * Hq + h) * Nq + n) * 128;
            __half2 a; a.x = __float2half_rn(v.x * inv * wv.x);
                       a.y = __float2half_rn(v.y * inv * wv.y);
            __half2 bb; bb.x = __float2half_rn(v.z * inv * wv.z);
                        bb.y = __float2half_rn(v.w * inv * wv.w);
            *(__half2*)(orow + d)     = a;
            *(__half2*)(orow + d + 2) = bb;
        }
    } else {
        for (int c = tid * 4; c < Cq; c += 1024) {
            float4 v = *(const float4*)(p + c);
            int h = c >> 7, d = c & 127;
            __half* orow = gv + ((size_t)(b * Hq + h) * Nq + n) * 128;
            __half2 a; a.x = __float2half_rn(v.x); a.y = __float2half_rn(v.y);
            __half2 bb; bb.x = __float2half_rn(v.z); bb.y = __float2half_rn(v.w);
            *(__half2*)(orow + d)     = a;
            *(__half2*)(orow + d + 2) = bb;
        }
    }
}

// ===========================================================================
// FA2-style flash attention: q-tile 128, 8 warps row-split (16 rows each),
// register-resident softmax, in-register P fragment packing (hi/lo),
// fp16 inputs via cp.async, K/V double-buffered.
//   S = (Qh+Ql) Kh^T  (2x8 k16-steps), O = (Ph+Pl) Vh  (2x4 k16-steps)
// ===========================================================================
#define ZQ_S 264
#define ZQ_B (ZQ_S * 2)        // 528 B (== 16 mod 128: conflict-free)
#define ZK_B 272               // 64x128 fp16 rows, stride 272 B
#define ZKBUF (64 * ZK_B)      // 17408
#define ZA_Q 0
#define ZA_K (128 * ZQ_B)                  // 67584
#define ZA_V (ZA_K + 2 * ZKBUF)            // 102400
#define ZSMEM (ZA_V + 2 * ZKBUF)           // 137216

__global__ __launch_bounds__(256) void fa2(
    const __half* __restrict__ gq, const __half* __restrict__ gk,
    const __half* __restrict__ gv, __half* __restrict__ outAs)
{
    extern __shared__ char sm[];
    const uint32_t sq = smem_u32(sm + ZA_Q);
    const uint32_t sk = smem_u32(sm + ZA_K);
    const uint32_t sv = smem_u32(sm + ZA_V);

    const int qt = blockIdx.x, h = blockIdx.y, b = blockIdx.z;
    const int tid = threadIdx.x, w = tid >> 5, lane = tid & 31;
    const int q0 = qt * 128;

    const __half* qb = gq + (size_t)(b * Hq + h) * Nq * 256;
    const __half* kb = gk + (size_t)(b * Hq + h) * Nq * 128;
    const __half* vb = gv + (size_t)(b * Hq + h) * Nq * 128;

    // ---- Q fill (group 0) ----
    for (int i = tid; i < 128 * 32; i += 256) {
        int r = i >> 5, ch = i & 31;
        int n = q0 + r;
        int nc = min(n, Nq - 1);
        cp16z(sq + (uint32_t)(r * ZQ_B + ch * 16),
              qb + (size_t)nc * 256 + ch * 8, (n < Nq) ? 16 : 0);
    }
    CP_COMMIT();

    auto fillKV = [&](int kt, int buf) {
        const int k0 = kt * 64;
        const uint32_t dk = sk + buf * ZKBUF;
        const uint32_t dv = sv + buf * ZKBUF;
        for (int i = tid; i < 64 * 16; i += 256) {
            int r = i >> 4, ch = i & 15;
            int n = k0 + r;
            int nc = min(n, Nq - 1);
            int sz = (n < Nq) ? 16 : 0;
            cp16z(dk + (uint32_t)(r * ZK_B + ch * 16), kb + (size_t)nc * 128 + ch * 8, sz);
            cp16z(dv + (uint32_t)(r * ZK_B + ch * 16), vb + (size_t)nc * 128 + ch * 8, sz);
        }
        CP_COMMIT();
    };
    fillKV(0, 0);

    float m0 = -1e30f, m1 = -1e30f, l0 = 0.f, l1 = 0.f;
    float acc_o[16][4];
    #pragma unroll
    for (int g = 0; g < 16; g++)
        #pragma unroll
        for (int r = 0; r < 4; r++) acc_o[g][r] = 0.f;

    const int arow = w * 16 + (lane & 15);
    const uint32_t a_cb = (uint32_t)((lane >> 4) << 4);
    const int krow_b = ((lane >> 4) << 3) + (lane & 7);
    const uint32_t b_cb = (uint32_t)(((lane >> 3) & 1) << 4);

    for (int kt = 0; kt < 17; kt++) {
        const int buf = kt & 1;
        asm volatile("cp.async.wait_group 0;" ::: "memory");
        __syncthreads();
        if (kt < 16) fillKV(kt + 1, buf ^ 1);

        const uint32_t skb = sk + buf * ZKBUF;
        const uint32_t svb = sv + buf * ZKBUF;

        // ---- S = (Qh+Ql) Kh^T ----
        float accs[8][4];
        #pragma unroll
        for (int nj = 0; nj < 8; nj++)
            #pragma unroll
            for (int r = 0; r < 4; r++) accs[nj][r] = 0.f;

        #pragma unroll
        for (int pass = 0; pass < 2; pass++) {
            #pragma unroll
            for (int ks = 0; ks < 8; ks++) {
                uint32_t afr[4];
                LDSM_X4(afr, sq + (uint32_t)(arow * ZQ_B + pass * 256 + ks * 32) + a_cb);
                #pragma unroll
                for (int bj = 0; bj < 4; bj++) {
                    uint32_t r[4];
                    LDSM_X4(r, skb + (uint32_t)((bj * 16 + krow_b) * ZK_B + ks * 32) + b_cb);
                    uint32_t b0[2] = {r[0], r[1]};
                    uint32_t b1[2] = {r[2], r[3]};
                    MMA16816_F16(accs[2 * bj],     afr, b0);
                    MMA16816_F16(accs[2 * bj + 1], afr, b1);
                }
            }
        }

        // ---- mask invalid key columns (only last tile) ----
        if (kt == 16) {
            #pragma unroll
            for (int nj = 0; nj < 8; nj++)
                #pragma unroll
                for (int j = 0; j < 4; j++) {
                    int col = 1024 + nj * 8 + 2 * (lane & 3) + (j & 1);
                    if (col >= Nq) accs[nj][j] = -1e30f;
                }
        }

        // ---- register softmax ----
        float mx0 = -1e30f, mx1 = -1e30f;
        #pragma unroll
        for (int nj = 0; nj < 8; nj++) {
            mx0 = fmaxf(mx0, fmaxf(accs[nj][0], accs[nj][1]));
            mx1 = fmaxf(mx1, fmaxf(accs[nj][2], accs[nj][3]));
        }
        mx0 = fmaxf(mx0, __shfl_xor_sync(0xffffffffu, mx0, 1));
        mx0 = fmaxf(mx0, __shfl_xor_sync(0xffffffffu, mx0, 2));
        mx1 = fmaxf(mx1, __shfl_xor_sync(0xffffffffu, mx1, 1));
        mx1 = fmaxf(mx1, __shfl_xor_sync(0xffffffffu, mx1, 2));

        const float mn0 = fmaxf(m0, mx0), mn1 = fmaxf(m1, mx1);
        const float cr0 = __expf(m0 - mn0), cr1 = __expf(m1 - mn1);

        float s0 = 0.f, s1 = 0.f;
        uint32_t ph[8][2], pl[8][2];
        #pragma unroll
        for (int nj = 0; nj < 8; nj++) {
            float p0 = __expf(accs[nj][0] - mn0);
            float p1 = __expf(accs[nj][1] - mn0);
            float p2 = __expf(accs[nj][2] - mn1);
            float p3 = __expf(accs[nj][3] - mn1);
            s0 += p0 + p1; s1 += p2 + p3;
            pack_hl(p0, p1, ph[nj][0], pl[nj][0]);
            pack_hl(p2, p3, ph[nj][1], pl[nj][1]);
        }
        s0 += __shfl_xor_sync(0xffffffffu, s0, 1);
        s0 += __shfl_xor_sync(0xffffffffu, s0, 2);
        s1 += __shfl_xor_sync(0xffffffffu, s1, 1);
        s1 += __shfl_xor_sync(0xffffffffu, s1, 2);
        l0 = l0 * cr0 + s0; l1 = l1 * cr1 + s1;
        m0 = mn0; m1 = mn1;

        #pragma unroll
        for (int g = 0; g < 16; g++) {
            acc_o[g][0] *= cr0; acc_o[g][1] *= cr0;
            acc_o[g][2] *= cr1; acc_o[g][3] *= cr1;
        }

        // ---- O += (Ph+Pl) Vh ----
        const int vrow_b = (lane & 7) + (((lane >> 3) & 1) << 3);
        const uint32_t v_cb = (uint32_t)((lane >> 4) << 4);
        #pragma unroll
        for (int kc = 0; kc < 4; kc++) {
            uint32_t aPh[4] = {ph[2 * kc][0], ph[2 * kc][1], ph[2 * kc + 1][0], ph[2 * kc + 1][1]};
            uint32_t aPl[4] = {pl[2 * kc][0], pl[2 * kc][1], pl[2 * kc + 1][0], pl[2 * kc + 1][1]};
            #pragma unroll
            for (int g2 = 0; g2 < 8; g2++) {
                uint32_t r[4];
                LDSM_X4_T(r, svb + (uint32_t)((kc * 16 + vrow_b) * ZK_B + g2 * 32) + v_cb);
                uint32_t b0[2] = {r[0], r[1]};
                uint32_t b1[2] = {r[2], r[3]};
                MMA16816_F16(acc_o[2 * g2],     aPh, b0);
                MMA16816_F16(acc_o[2 * g2 + 1], aPh, b1);
                MMA16816_F16(acc_o[2 * g2],     aPl, b0);
                MMA16816_F16(acc_o[2 * g2 + 1], aPl, b1);
            }
        }
    }

    // ---- epilogue: normalize, split fp16 hi/lo, write to g_as ----
    {
        const float invl0 = 1.f / l0, invl1 = 1.f / l1;
        const int n0v = q0 + w * 16 + (lane >> 2);
        const int n1v = n0v + 8;
        #pragma unroll
        for (int g = 0; g < 16; g++) {
            int c = h * Dq + g * 8 + 2 * (lane & 3);
            if (n0v < Nq) {
                uint32_t hp, lp;
                pack_hl(acc_o[g][0] * invl0, acc_o[g][1] * invl0, hp, lp);
                __half* row = outAs + (size_t)(b * Nq + n0v) * Ka;
                *(uint32_t*)(row + c)      = hp;
                *(uint32_t*)(row + Cq + c) = lp;
            }
            if (n1v < Nq) {
                uint32_t hp, lp;
                pack_hl(acc_o[g][2] * invl1, acc_o[g][3] * invl1, hp, lp);
                __half* row = outAs + (size_t)(b * Nq + n1v) * Ka;
                *(uint32_t*)(row + c)      = hp;
                *(uint32_t*)(row + Cq + c) = lp;
            }
        }
    }
}

// ===========================================================================
extern "C" void kernel_launch(void* const* d_in, const int* in_sizes, int n_in,
                              void* d_out, int out_size)
{
    const float* x        = (const float*)d_in[0];
    const float* qkv_w    = (const float*)d_in[1];
    const float* qkv_b    = (const float*)d_in[2];
    const float* q_norm_w = (const float*)d_in[3];
    const float* k_norm_w = (const float*)d_in[4];
    const float* proj_w   = (const float*)d_in[5];
    const float* proj_b   = (const float*)d_in[6];
    float* out = (float*)d_out;

    float* qkvp = nullptr;
    __half *asp = nullptr, *wqp = nullptr, *wpp = nullptr;
    __half *qp = nullptr, *kp = nullptr, *vp = nullptr;
    cudaGetSymbolAddress((void**)&qkvp, g_qkv);
    cudaGetSymbolAddress((void**)&asp, g_as);
    cudaGetSymbolAddress((void**)&wqp, g_wq);
    cudaGetSymbolAddress((void**)&wpp, g_wp);
    cudaGetSymbolAddress((void**)&qp, g_q);
    cudaGetSymbolAddress((void**)&kp, g_k);
    cudaGetSymbolAddress((void**)&vp, g_v);

    cudaFuncSetAttribute(gemm_mma,
                         cudaFuncAttributeMaxDynamicSharedMemorySize, GSMEM_TOTAL);
    cudaFuncSetAttribute(fa2,
                         cudaFuncAttributeMaxDynamicSharedMemorySize, ZSMEM);

    const int mt = (Mq + GBM - 1) / GBM;        // 65
    const int nt_qkv = QKV_N / GBN;             // 75
    const int nt_prj = Cq / GBN;                // 25

    // 1) split A to fp16 [hi|lo]; round weights to fp16 (transposed)
    {
        size_t e2 = (size_t)Mq * Cq / 2;
        split_a_kernel<<<(unsigned)((e2 + 255) / 256), 256>>>(x, asp, Mq);
    }
    split_wt_kernel<<<dim3(QKV_N / 32, Cq / 32), dim3(32, 8)>>>(qkv_w, wqp, QKV_N);
    split_wt_kernel<<<dim3(Cq / 32, Cq / 32), dim3(32, 8)>>>(proj_w, wpp, Cq);

    // 2) qkv = x @ qkv_w + b   (fp16 2-pass)
    gemm_mma<<<mt * nt_qkv, 256, GSMEM_TOTAL>>>(
        asp, wqp, qkv_b, qkvp, Mq, QKV_N, mt, nt_qkv);

    // 3) fused rmsnorm + fp16 convert -> g_q / g_k / g_v (head-contiguous)
    fuse_nc<<<dim3(Mq, 3), 256>>>(qkvp, q_norm_w, k_norm_w, qp, kp, vp);

    // 4) FA2 attention -> g_as (fp16 [hi|lo], ready for proj GEMM)
    fa2<<<dim3(9, Hq, Bq), 256, ZSMEM>>>(qp, kp, vp, asp);

    // 5) out = att @ proj_w + b   (fp16 2-pass)
    gemm_mma<<<mt * nt_prj, 256, GSMEM_TOTAL>>>(
        asp, wpp, proj_b, out, Mq, Cq, mt, nt_prj);
}

// round 12
// speedup vs baseline: 2.6227x; 1.3810x over previous
#include <cuda_runtime.h>
#include <cuda_bf16.h>
#include <cuda_fp16.h>
#include <cstdint>
#include <math.h>

// Problem constants
#define Bq 8
#define Nq 1025
#define Cq 3200
#define Hq 25
#define Dq 128
#define Mq (Bq * Nq)        // 8200
#define QKV_N (3 * Cq)      // 9600
#define Ka 6400             // A-side K'': [Ah | Al] fp16 pairs
#define EPSq 1e-6f

// Scratch (__device__ globals per alloc-free rule)
__device__ float g_qkv[(size_t)Mq * QKV_N];
__device__ __half g_as[(size_t)Mq * Ka];            // A' = [hi|lo] fp16 (GEMM input)
__device__ __half g_wq[(size_t)QKV_N * Cq];         // qkv_w^T fp16
__device__ __half g_wp[(size_t)Cq * Cq];            // proj_w^T fp16
__device__ __half g_q[(size_t)Bq * Hq * Nq * 256];  // q: [b][h][n][hi128|lo128]
__device__ __half g_k[(size_t)Bq * Hq * Nq * 128];  // k: fp16, normed
__device__ __half g_v[(size_t)Bq * Hq * Nq * 128];  // v: fp16

// ===========================================================================
// helpers
// ===========================================================================
__device__ __forceinline__ uint32_t smem_u32(const void* p) {
    uint32_t a;
    asm("{ .reg .u64 t; cvta.to.shared.u64 t, %1; cvt.u32.u64 %0, t; }"
        : "=r"(a) : "l"(p));
    return a;
}
__device__ __forceinline__ uint32_t swz128(uint32_t off) {
    return off ^ ((off >> 3) & 0x70);
}
__device__ __forceinline__ void cp16(uint32_t s, const void* g) {
    asm volatile("cp.async.cg.shared.global [%0], [%1], 16;"
                 :: "r"(s), "l"(g) : "memory");
}
__device__ __forceinline__ void cp16z(uint32_t s, const void* g, int sz) {
    asm volatile("cp.async.cg.shared.global [%0], [%1], 16, %2;"
                 :: "r"(s), "l"(g), "r"(sz) : "memory");
}
#define CP_COMMIT() asm volatile("cp.async.commit_group;" ::: "memory")

#define LDSM_X4(r, addr)                                                       \
    asm volatile("ldmatrix.sync.aligned.m8n8.x4.shared.b16 {%0,%1,%2,%3}, [%4];" \
        : "=r"((r)[0]), "=r"((r)[1]), "=r"((r)[2]), "=r"((r)[3]) : "r"(addr))

#define LDSM_X4_T(r, addr)                                                     \
    asm volatile("ldmatrix.sync.aligned.m8n8.x4.trans.shared.b16 {%0,%1,%2,%3}, [%4];" \
        : "=r"((r)[0]), "=r"((r)[1]), "=r"((r)[2]), "=r"((r)[3]) : "r"(addr))

#define MMA16816_F16(d, a, b)                                                  \
    asm volatile("mma.sync.aligned.m16n8k16.row.col.f32.f16.f16.f32 "          \
        "{%0,%1,%2,%3}, {%4,%5,%6,%7}, {%8,%9}, {%0,%1,%2,%3};"                \
        : "+f"((d)[0]), "+f"((d)[1]), "+f"((d)[2]), "+f"((d)[3])               \
        : "r"((a)[0]), "r"((a)[1]), "r"((a)[2]), "r"((a)[3]),                  \
          "r"((b)[0]), "r"((b)[1]))

__device__ __forceinline__ void pack_hl(float x, float y, uint32_t& hp, uint32_t& lp) {
    __half hx = __float2half_rn(x), hy = __float2half_rn(y);
    __half lx = __float2half_rn(x - __half2float(hx));
    __half ly = __float2half_rn(y - __half2float(hy));
    __half2 h2; h2.x = hx; h2.y = hy;
    __half2 l2; l2.x = lx; l2.y = ly;
    hp = *(uint32_t*)&h2;
    lp = *(uint32_t*)&l2;
}
__device__ __forceinline__ uint32_t pack_h(float x, float y) {
    __half2 h2; h2.x = __float2half_rn(x); h2.y = __float2half_rn(y);
    return *(uint32_t*)&h2;
}

// ===========================================================================
// Split kernels (unchanged, proven)
// ===========================================================================
__global__ __launch_bounds__(256) void split_a_kernel(
    const float* __restrict__ in, __half* __restrict__ out, int M)
{
    size_t idx = (size_t)blockIdx.x * 256 + threadIdx.x;
    if (idx * 2 >= (size_t)M * Cq) return;
    int m = (int)((idx * 2) / Cq);
    int k = (int)((idx * 2) % Cq);
    float2 v = *(const float2*)(in + (size_t)m * Cq + k);
    __half h0 = __float2half_rn(v.x);
    __half h1 = __float2half_rn(v.y);
    __half l0 = __float2half_rn(v.x - __half2float(h0));
    __half l1 = __float2half_rn(v.y - __half2float(h1));
    __half2 hh; hh.x = h0; hh.y = h1;
    __half2 ll; ll.x = l0; ll.y = l1;
    __half* row = out + (size_t)m * Ka;
    *(__half2*)(row + k)      = hh;
    *(__half2*)(row + Cq + k) = ll;
}

__global__ __launch_bounds__(256) void split_wt_kernel(
    const float* __restrict__ W, __half* __restrict__ out, int Nw)
{
    __shared__ float tile[32][33];
    int n0 = blockIdx.x * 32, k0 = blockIdx.y * 32;
    int tx = threadIdx.x, ty = threadIdx.y;
    #pragma unroll
    for (int i = ty; i < 32; i += 8)
        tile[i][tx] = W[(size_t)(k0 + i) * Nw + n0 + tx];
    __syncthreads();
    #pragma unroll
    for (int i = ty; i < 32; i += 8) {
        int n = n0 + i, k = k0 + tx;
        out[(size_t)n * Cq + k] = __float2half_rn(tile[tx][i]);
    }
}

// ===========================================================================
// fp16 mma.sync GEMM: C[M,Nt] = (Ah[+Al]) @ Bh^T + bias
// Tiles with n0 >= half_n0 run only the hi pass (NIT=50): used for k/v
// columns of the qkv GEMM (outputs re-rounded to fp16 downstream) and for
// the whole proj GEMM (A-lo below existing error floor).
// ===========================================================================
#define GBM 128
#define GBN 128
#define GBK 64
#define GNIT (Ka / GBK)            // 100
#define ABYTES (GBM * GBK * 2)
#define BBYTES (GBN * GBK * 2)
#define BUFB (ABYTES + BBYTES)
#define GSTAGES 3
#define GSMEM_TOTAL (GSTAGES * BUFB)
#define G_GM 8

__global__ __launch_bounds__(256, 2) void gemm_mma(
    const __half* __restrict__ A,
    const __half* __restrict__ Bt,
    const float* __restrict__ bias,
    float* __restrict__ C,
    int M, int Nt, int mt, int nt, int half_n0)
{
    extern __shared__ char smem[];
    const uint32_t sbase = smem_u32(smem);
    const int tid = threadIdx.x;
    const int wid = tid >> 5, lane = tid & 31;
    const int wm = wid >> 2, wn = wid & 3;

    int bid = blockIdx.x;
    int per_group = G_GM * nt;
    int gid = bid / per_group;
    int first_m = gid * G_GM;
    int gsz = min(G_GM, mt - first_m);
    int rem = bid % per_group;
    const int m0 = (first_m + rem % gsz) * GBM;
    const int n0 = (rem / gsz) * GBN;

    const int NIT = (n0 >= half_n0) ? (GNIT / 2) : GNIT;

    float acc[4][4][4];
    #pragma unroll
    for (int i = 0; i < 4; i++)
        #pragma unroll
        for (int j = 0; j < 4; j++)
            #pragma unroll
            for (int r = 0; r < 4; r++) acc[i][j][r] = 0.f;

    auto load_tile = [&](int it, int buf) {
        const int k0 = it * GBK;
        const int bk0 = (k0 >= Cq) ? (k0 - Cq) : k0;
        const uint32_t sA = sbase + buf * BUFB;
        const uint32_t sB = sA + ABYTES;
        #pragma unroll
        for (int p = 0; p < 4; p++) {
            int id = p * 256 + tid;
            int row = id >> 3, ch = id & 7;
            uint32_t so = swz128((uint32_t)(row * 128 + ch * 16));
            int m = min(m0 + row, M - 1);
            cp16(sA + so, A  + (size_t)m * Ka + k0 + ch * 8);
            cp16(sB + so, Bt + (size_t)(n0 + row) * Cq + bk0 + ch * 8);
        }
        CP_COMMIT();
    };

    auto compute = [&](int buf) {
        const uint32_t sA = sbase + buf * BUFB + (uint32_t)(wm * 64 * 128);
        const uint32_t sB = sbase + buf * BUFB + ABYTES + (uint32_t)(wn * 32 * 128);
        #pragma unroll
        for (int kk = 0; kk < 4; kk++) {
            uint32_t afr[4][4];
            #pragma unroll
            for (int mi = 0; mi < 4; mi++) {
                int row = mi * 16 + (lane & 15);
                int cb = kk * 32 + ((lane >> 4) << 4);
                LDSM_X4(afr[mi], sA + swz128((uint32_t)(row * 128 + cb)));
            }
            uint32_t bfr[4][2];
            #pragma unroll
            for (int bj = 0; bj < 2; bj++) {
                int row = bj * 16 + ((lane >> 4) << 3) + (lane & 7);
                int cb = kk * 32 + (((lane >> 3) & 1) << 4);
                uint32_t r[4];
                LDSM_X4(r, sB + swz128((uint32_t)(row * 128 + cb)));
                bfr[2 * bj][0] = r[0];     bfr[2 * bj][1] = r[1];
                bfr[2 * bj + 1][0] = r[2]; bfr[2 * bj + 1][1] = r[3];
            }
            #pragma unroll
            for (int mi = 0; mi < 4; mi++)
                #pragma unroll
                for (int nj = 0; nj < 4; nj++)
                    MMA16816_F16(acc[mi][nj], afr[mi], bfr[nj]);
        }
    };

    load_tile(0, 0);
    load_tile(1, 1);
    for (int it = 0; it < NIT; it++) {
        if (it + 1 < NIT)
            asm volatile("cp.async.wait_group 1;" ::: "memory");
        else
            asm volatile("cp.async.wait_group 0;" ::: "memory");
        __syncthreads();
        if (it + 2 < NIT) load_tile(it + 2, (it + 2) % GSTAGES);
        compute(it % GSTAGES);
    }

    const int mbase = m0 + wm * 64;
    const int nbase = n0 + wn * 32;
    #pragma unroll
    for (int mi = 0; mi < 4; mi++) {
        #pragma unroll
        for (int nj = 0; nj < 4; nj++) {
            int r0 = mbase + mi * 16 + (lane >> 2);
            int c = nbase + nj * 8 + 2 * (lane & 3);
            float bx = bias[c], by = bias[c + 1];
            if (r0 < M) {
                float2 o = make_float2(acc[mi][nj][0] + bx, acc[mi][nj][1] + by);
                *(float2*)(C + (size_t)r0 * Nt + c) = o;
            }
            if (r0 + 8 < M) {
                float2 o = make_float2(acc[mi][nj][2] + bx, acc[mi][nj][3] + by);
                *(float2*)(C + (size_t)(r0 + 8) * Nt + c) = o;
            }
        }
    }
}

// ===========================================================================
// Fused rmsnorm + fp16 convert + head-contiguous layout (proven).
// ===========================================================================
__global__ __launch_bounds__(256) void fuse_nc(
    const float* __restrict__ qkv,
    const float* __restrict__ qw, const float* __restrict__ kw,
    __half* __restrict__ gq, __half* __restrict__ gk, __half* __restrict__ gv)
{
    const int row = blockIdx.x;
    const int which = blockIdx.y;
    const int b = row / Nq, n = row % Nq;
    const float* p = qkv + (size_t)row * QKV_N + which * Cq;
    const int tid = threadIdx.x;

    float inv = 1.f;
    if (which < 2) {
        float ss = 0.f;
        for (int c = tid * 4; c < Cq; c += 1024) {
            float4 v = *(const float4*)(p + c);
            ss += v.x * v.x + v.y * v.y + v.z * v.z + v.w * v.w;
        }
        #pragma unroll
        for (int o = 16; o; o >>= 1) ss += __shfl_xor_sync(0xffffffffu, ss, o);
        __shared__ float red[8];
        if ((tid & 31) == 0) red[tid >> 5] = ss;
        __syncthreads();
        if (tid < 8) {
            float v = red[tid];
            #pragma unroll
            for (int o = 4; o; o >>= 1) v += __shfl_xor_sync(0xffu, v, o);
            if (tid == 0) red[0] = v;
        }
        __syncthreads();
        inv = rsqrtf(red[0] * (1.f / Cq) + EPSq);
    }

    if (which == 0) {
        const float sc = 0.08838834764831845f;
        for (int c = tid * 4; c < Cq; c += 1024) {
            float4 v = *(const float4*)(p + c);
            float4 wv = *(const float4*)(qw + c);
            int h = c >> 7, d = c & 127;
            __half* orow = gq + ((size_t)(b * Hq + h) * Nq + n) * 256;
            float f0 = v.x * inv * wv.x * sc;
            float f1 = v.y * inv * wv.y * sc;
            float f2 = v.z * inv * wv.z * sc;
            float f3 = v.w * inv * wv.w * sc;
            uint32_t h01, l01, h23, l23;
            pack_hl(f0, f1, h01, l01);
            pack_hl(f2, f3, h23, l23);
            *(uint32_t*)(orow + d)           = h01;
            *(uint32_t*)(orow + d + 2)       = h23;
            *(uint32_t*)(orow + 128 + d)     = l01;
            *(uint32_t*)(orow + 128 + d + 2) = l23;
        }
    } else if (which == 1) {
        for (int c = tid * 4; c < Cq; c += 1024) {
            float4 v = *(const float4*)(p + c);
            float4 wv = *(const float4*)(kw + c);
            int h = c >> 7, d = c & 127;
            __half* orow = gk + ((size_t)(b * Hq + h) * Nq + n) * 128;
            *(uint32_t*)(orow + d)     = pack_h(v.x * inv * wv.x, v.y * inv * wv.y);
            *(uint32_t*)(orow + d + 2) = pack_h(v.z * inv * wv.z, v.w * inv * wv.w);
        }
    } else {
        for (int c = tid * 4; c < Cq; c += 1024) {
            float4 v = *(const float4*)(p + c);
            int h = c >> 7, d = c & 127;
            __half* orow = gv + ((size_t)(b * Hq + h) * Nq + n) * 128;
            *(uint32_t*)(orow + d)     = pack_h(v.x, v.y);
            *(uint32_t*)(orow + d + 2) = pack_h(v.z, v.w);
        }
    }
}

// ===========================================================================
// FA2-style flash attention (proven round-11 kernel).
// Epilogue now writes only hi (proj GEMM runs 1-pass).
// ===========================================================================
#define ZQ_S 264
#define ZQ_B (ZQ_S * 2)
#define ZK_B 272
#define ZKBUF (64 * ZK_B)
#define ZA_Q 0
#define ZA_K (128 * ZQ_B)
#define ZA_V (ZA_K + 2 * ZKBUF)
#define ZSMEM (ZA_V + 2 * ZKBUF)

__global__ __launch_bounds__(256) void fa2(
    const __half* __restrict__ gq, const __half* __restrict__ gk,
    const __half* __restrict__ gv, __half* __restrict__ outAs)
{
    extern __shared__ char sm[];
    const uint32_t sq = smem_u32(sm + ZA_Q);
    const uint32_t sk = smem_u32(sm + ZA_K);
    const uint32_t sv = smem_u32(sm + ZA_V);

    const int qt = blockIdx.x, h = blockIdx.y, b = blockIdx.z;
    const int tid = threadIdx.x, w = tid >> 5, lane = tid & 31;
    const int q0 = qt * 128;

    const __half* qb = gq + (size_t)(b * Hq + h) * Nq * 256;
    const __half* kb = gk + (size_t)(b * Hq + h) * Nq * 128;
    const __half* vb = gv + (size_t)(b * Hq + h) * Nq * 128;

    for (int i = tid; i < 128 * 32; i += 256) {
        int r = i >> 5, ch = i & 31;
        int n = q0 + r;
        int nc = min(n, Nq - 1);
        cp16z(sq + (uint32_t)(r * ZQ_B + ch * 16),
              qb + (size_t)nc * 256 + ch * 8, (n < Nq) ? 16 : 0);
    }
    CP_COMMIT();

    auto fillKV = [&](int kt, int buf) {
        const int k0 = kt * 64;
        const uint32_t dk = sk + buf * ZKBUF;
        const uint32_t dv = sv + buf * ZKBUF;
        for (int i = tid; i < 64 * 16; i += 256) {
            int r = i >> 4, ch = i & 15;
            int n = k0 + r;
            int nc = min(n, Nq - 1);
            int sz = (n < Nq) ? 16 : 0;
            cp16z(dk + (uint32_t)(r * ZK_B + ch * 16), kb + (size_t)nc * 128 + ch * 8, sz);
            cp16z(dv + (uint32_t)(r * ZK_B + ch * 16), vb + (size_t)nc * 128 + ch * 8, sz);
        }
        CP_COMMIT();
    };
    fillKV(0, 0);

    float m0 = -1e30f, m1 = -1e30f, l0 = 0.f, l1 = 0.f;
    float acc_o[16][4];
    #pragma unroll
    for (int g = 0; g < 16; g++)
        #pragma unroll
        for (int r = 0; r < 4; r++) acc_o[g][r] = 0.f;

    const int arow = w * 16 + (lane & 15);
    const uint32_t a_cb = (uint32_t)((lane >> 4) << 4);
    const int krow_b = ((lane >> 4) << 3) + (lane & 7);
    const uint32_t b_cb = (uint32_t)(((lane >> 3) & 1) << 4);

    for (int kt = 0; kt < 17; kt++) {
        const int buf = kt & 1;
        asm volatile("cp.async.wait_group 0;" ::: "memory");
        __syncthreads();
        if (kt < 16) fillKV(kt + 1, buf ^ 1);

        const uint32_t skb = sk + buf * ZKBUF;
        const uint32_t svb = sv + buf * ZKBUF;

        float accs[8][4];
        #pragma unroll
        for (int nj = 0; nj < 8; nj++)
            #pragma unroll
            for (int r = 0; r < 4; r++) accs[nj][r] = 0.f;

        #pragma unroll
        for (int pass = 0; pass < 2; pass++) {
            #pragma unroll
            for (int ks = 0; ks < 8; ks++) {
                uint32_t afr[4];
                LDSM_X4(afr, sq + (uint32_t)(arow * ZQ_B + pass * 256 + ks * 32) + a_cb);
                #pragma unroll
                for (int bj = 0; bj < 4; bj++) {
                    uint32_t r[4];
                    LDSM_X4(r, skb + (uint32_t)((bj * 16 + krow_b) * ZK_B + ks * 32) + b_cb);
                    uint32_t b0[2] = {r[0], r[1]};
                    uint32_t b1[2] = {r[2], r[3]};
                    MMA16816_F16(accs[2 * bj],     afr, b0);
                    MMA16816_F16(accs[2 * bj + 1], afr, b1);
                }
            }
        }

        if (kt == 16) {
            #pragma unroll
            for (int nj = 0; nj < 8; nj++)
                #pragma unroll
                for (int j = 0; j < 4; j++) {
                    int col = 1024 + nj * 8 + 2 * (lane & 3) + (j & 1);
                    if (col >= Nq) accs[nj][j] = -1e30f;
                }
        }

        float mx0 = -1e30f, mx1 = -1e30f;
        #pragma unroll
        for (int nj = 0; nj < 8; nj++) {
            mx0 = fmaxf(mx0, fmaxf(accs[nj][0], accs[nj][1]));
            mx1 = fmaxf(mx1, fmaxf(accs[nj][2], accs[nj][3]));
        }
        mx0 = fmaxf(mx0, __shfl_xor_sync(0xffffffffu, mx0, 1));
        mx0 = fmaxf(mx0, __shfl_xor_sync(0xffffffffu, mx0, 2));
        mx1 = fmaxf(mx1, __shfl_xor_sync(0xffffffffu, mx1, 1));
        mx1 = fmaxf(mx1, __shfl_xor_sync(0xffffffffu, mx1, 2));

        const float mn0 = fmaxf(m0, mx0), mn1 = fmaxf(m1, mx1);
        const float cr0 = __expf(m0 - mn0), cr1 = __expf(m1 - mn1);

        float s0 = 0.f, s1 = 0.f;
        uint32_t ph[8][2], pl[8][2];
        #pragma unroll
        for (int nj = 0; nj < 8; nj++) {
            float p0 = __expf(accs[nj][0] - mn0);
            float p1 = __expf(accs[nj][1] - mn0);
            float p2 = __expf(accs[nj][2] - mn1);
            float p3 = __expf(accs[nj][3] - mn1);
            s0 += p0 + p1; s1 += p2 + p3;
            pack_hl(p0, p1, ph[nj][0], pl[nj][0]);
            pack_hl(p2, p3, ph[nj][1], pl[nj][1]);
        }
        s0 += __shfl_xor_sync(0xffffffffu, s0, 1);
        s0 += __shfl_xor_sync(0xffffffffu, s0, 2);
        s1 += __shfl_xor_sync(0xffffffffu, s1, 1);
        s1 += __shfl_xor_sync(0xffffffffu, s1, 2);
        l0 = l0 * cr0 + s0; l1 = l1 * cr1 + s1;
        m0 = mn0; m1 = mn1;

        #pragma unroll
        for (int g = 0; g < 16; g++) {
            acc_o[g][0] *= cr0; acc_o[g][1] *= cr0;
            acc_o[g][2] *= cr1; acc_o[g][3] *= cr1;
        }

        const int vrow_b = (lane & 7) + (((lane >> 3) & 1) << 3);
        const uint32_t v_cb = (uint32_t)((lane >> 4) << 4);
        #pragma unroll
        for (int kc = 0; kc < 4; kc++) {
            uint32_t aPh[4] = {ph[2 * kc][0], ph[2 * kc][1], ph[2 * kc + 1][0], ph[2 * kc + 1][1]};
            uint32_t aPl[4] = {pl[2 * kc][0], pl[2 * kc][1], pl[2 * kc + 1][0], pl[2 * kc + 1][1]};
            #pragma unroll
            for (int g2 = 0; g2 < 8; g2++) {
                uint32_t r[4];
                LDSM_X4_T(r, svb + (uint32_t)((kc * 16 + vrow_b) * ZK_B + g2 * 32) + v_cb);
                uint32_t b0[2] = {r[0], r[1]};
                uint32_t b1[2] = {r[2], r[3]};
                MMA16816_F16(acc_o[2 * g2],     aPh, b0);
                MMA16816_F16(acc_o[2 * g2 + 1], aPh, b1);
                MMA16816_F16(acc_o[2 * g2],     aPl, b0);
                MMA16816_F16(acc_o[2 * g2 + 1], aPl, b1);
            }
        }
    }

    // ---- epilogue: normalize, write fp16 hi only (proj GEMM is 1-pass) ----
    {
        const float invl0 = 1.f / l0, invl1 = 1.f / l1;
        const int n0v = q0 + w * 16 + (lane >> 2);
        const int n1v = n0v + 8;
        #pragma unroll
        for (int g = 0; g < 16; g++) {
            int c = h * Dq + g * 8 + 2 * (lane & 3);
            if (n0v < Nq) {
                __half* row = outAs + (size_t)(b * Nq + n0v) * Ka;
                *(uint32_t*)(row + c) = pack_h(acc_o[g][0] * invl0, acc_o[g][1] * invl0);
            }
            if (n1v < Nq) {
                __half* row = outAs + (size_t)(b * Nq + n1v) * Ka;
                *(uint32_t*)(row + c) = pack_h(acc_o[g][2] * invl1, acc_o[g][3] * invl1);
            }
        }
    }
}

// ===========================================================================
extern "C" void kernel_launch(void* const* d_in, const int* in_sizes, int n_in,
                              void* d_out, int out_size)
{
    const float* x        = (const float*)d_in[0];
    const float* qkv_w    = (const float*)d_in[1];
    const float* qkv_b    = (const float*)d_in[2];
    const float* q_norm_w = (const float*)d_in[3];
    const float* k_norm_w = (const float*)d_in[4];
    const float* proj_w   = (const float*)d_in[5];
    const float* proj_b   = (const float*)d_in[6];
    float* out = (float*)d_out;

    float* qkvp = nullptr;
    __half *asp = nullptr, *wqp = nullptr, *wpp = nullptr;
    __half *qp = nullptr, *kp = nullptr, *vp = nullptr;
    cudaGetSymbolAddress((void**)&qkvp, g_qkv);
    cudaGetSymbolAddress((void**)&asp, g_as);
    cudaGetSymbolAddress((void**)&wqp, g_wq);
    cudaGetSymbolAddress((void**)&wpp, g_wp);
    cudaGetSymbolAddress((void**)&qp, g_q);
    cudaGetSymbolAddress((void**)&kp, g_k);
    cudaGetSymbolAddress((void**)&vp, g_v);

    cudaFuncSetAttribute(gemm_mma,
                         cudaFuncAttributeMaxDynamicSharedMemorySize, GSMEM_TOTAL);
    cudaFuncSetAttribute(fa2,
                         cudaFuncAttributeMaxDynamicSharedMemorySize, ZSMEM);

    const int mt = (Mq + GBM - 1) / GBM;        // 65
    const int nt_qkv = QKV_N / GBN;             // 75
    const int nt_prj = Cq / GBN;                // 25

    // 1) split x to fp16 [hi|lo]; round weights to fp16 (transposed)
    {
        size_t e2 = (size_t)Mq * Cq / 2;
        split_a_kernel<<<(unsigned)((e2 + 255) / 256), 256>>>(x, asp, Mq);
    }
    split_wt_kernel<<<dim3(QKV_N / 32, Cq / 32), dim3(32, 8)>>>(qkv_w, wqp, QKV_N);
    split_wt_kernel<<<dim3(Cq / 32, Cq / 32), dim3(32, 8)>>>(proj_w, wpp, Cq);

    // 2) qkv = x @ qkv_w + b   (q: 2-pass; k,v columns (n0>=Cq): 1-pass)
    gemm_mma<<<mt * nt_qkv, 256, GSMEM_TOTAL>>>(
        asp, wqp, qkv_b, qkvp, Mq, QKV_N, mt, nt_qkv, Cq);

    // 3) fused rmsnorm + fp16 convert -> g_q / g_k / g_v
    fuse_nc<<<dim3(Mq, 3), 256>>>(qkvp, q_norm_w, k_norm_w, qp, kp, vp);

    // 4) FA2 attention -> g_as (hi only)
    fa2<<<dim3(9, Hq, Bq), 256, ZSMEM>>>(qp, kp, vp, asp);

    // 5) out = att @ proj_w + b   (1-pass: half_n0 = 0)
    gemm_mma<<<mt * nt_prj, 256, GSMEM_TOTAL>>>(
        asp, wpp, proj_b, out, Mq, Cq, mt, nt_prj, 0);
}

// round 13
// speedup vs baseline: 3.0272x; 1.1542x over previous
#include <cuda_runtime.h>
#include <cuda_bf16.h>
#include <cuda_fp16.h>
#include <cstdint>
#include <math.h>

// Problem constants
#define Bq 8
#define Nq 1025
#define Cq 3200
#define Hq 25
#define Dq 128
#define Mq (Bq * Nq)        // 8200
#define QKV_N (3 * Cq)      // 9600
#define EPSq 1e-6f

// Scratch (__device__ globals per alloc-free rule)
__device__ float g_qkv[(size_t)Mq * QKV_N];
__device__ __half g_as[(size_t)Mq * Cq];            // fp16 A (x, then attn out)
__device__ __half g_wq[(size_t)QKV_N * Cq];         // qkv_w^T fp16
__device__ __half g_wp[(size_t)Cq * Cq];            // proj_w^T fp16
__device__ __half g_q[(size_t)Bq * Hq * Nq * 256];  // q: [b][h][n][hi128|lo128]
__device__ __half g_k[(size_t)Bq * Hq * Nq * 128];  // k: fp16, normed
__device__ __half g_v[(size_t)Bq * Hq * Nq * 128];  // v: fp16

// ===========================================================================
// helpers
// ===========================================================================
__device__ __forceinline__ uint32_t smem_u32(const void* p) {
    uint32_t a;
    asm("{ .reg .u64 t; cvta.to.shared.u64 t, %1; cvt.u32.u64 %0, t; }"
        : "=r"(a) : "l"(p));
    return a;
}
__device__ __forceinline__ uint32_t swz128(uint32_t off) {
    return off ^ ((off >> 3) & 0x70);
}
__device__ __forceinline__ void cp16(uint32_t s, const void* g) {
    asm volatile("cp.async.cg.shared.global [%0], [%1], 16;"
                 :: "r"(s), "l"(g) : "memory");
}
__device__ __forceinline__ void cp16z(uint32_t s, const void* g, int sz) {
    asm volatile("cp.async.cg.shared.global [%0], [%1], 16, %2;"
                 :: "r"(s), "l"(g), "r"(sz) : "memory");
}
#define CP_COMMIT() asm volatile("cp.async.commit_group;" ::: "memory")

#define LDSM_X4(r, addr)                                                       \
    asm volatile("ldmatrix.sync.aligned.m8n8.x4.shared.b16 {%0,%1,%2,%3}, [%4];" \
        : "=r"((r)[0]), "=r"((r)[1]), "=r"((r)[2]), "=r"((r)[3]) : "r"(addr))

#define LDSM_X4_T(r, addr)                                                     \
    asm volatile("ldmatrix.sync.aligned.m8n8.x4.trans.shared.b16 {%0,%1,%2,%3}, [%4];" \
        : "=r"((r)[0]), "=r"((r)[1]), "=r"((r)[2]), "=r"((r)[3]) : "r"(addr))

#define MMA16816_F16(d, a, b)                                                  \
    asm volatile("mma.sync.aligned.m16n8k16.row.col.f32.f16.f16.f32 "          \
        "{%0,%1,%2,%3}, {%4,%5,%6,%7}, {%8,%9}, {%0,%1,%2,%3};"                \
        : "+f"((d)[0]), "+f"((d)[1]), "+f"((d)[2]), "+f"((d)[3])               \
        : "r"((a)[0]), "r"((a)[1]), "r"((a)[2]), "r"((a)[3]),                  \
          "r"((b)[0]), "r"((b)[1]))

__device__ __forceinline__ void pack_hl(float x, float y, uint32_t& hp, uint32_t& lp) {
    __half hx = __float2half_rn(x), hy = __float2half_rn(y);
    __half lx = __float2half_rn(x - __half2float(hx));
    __half ly = __float2half_rn(y - __half2float(hy));
    __half2 h2; h2.x = hx; h2.y = hy;
    __half2 l2; l2.x = lx; l2.y = ly;
    hp = *(uint32_t*)&h2;
    lp = *(uint32_t*)&l2;
}
__device__ __forceinline__ uint32_t pack_h(float x, float y) {
    __half2 h2; h2.x = __float2half_rn(x); h2.y = __float2half_rn(y);
    return *(uint32_t*)&h2;
}

// ===========================================================================
// Convert kernels
// x: fp32 -> fp16, row stride Cq
// W: fp32 [K,N] -> fp16 W^T [N,K], row stride Cq
// ===========================================================================
__global__ __launch_bounds__(256) void conv_a_kernel(
    const float* __restrict__ in, __half* __restrict__ out, int M)
{
    size_t idx = ((size_t)blockIdx.x * 256 + threadIdx.x) * 4;
    if (idx >= (size_t)M * Cq) return;
    float4 v = *(const float4*)(in + idx);
    *(uint32_t*)(out + idx)     = pack_h(v.x, v.y);
    *(uint32_t*)(out + idx + 2) = pack_h(v.z, v.w);
}

__global__ __launch_bounds__(256) void split_wt_kernel(
    const float* __restrict__ W, __half* __restrict__ out, int Nw)
{
    __shared__ float tile[32][33];
    int n0 = blockIdx.x * 32, k0 = blockIdx.y * 32;
    int tx = threadIdx.x, ty = threadIdx.y;
    #pragma unroll
    for (int i = ty; i < 32; i += 8)
        tile[i][tx] = W[(size_t)(k0 + i) * Nw + n0 + tx];
    __syncthreads();
    #pragma unroll
    for (int i = ty; i < 32; i += 8) {
        int n = n0 + i, k = k0 + tx;
        out[(size_t)n * Cq + k] = __float2half_rn(tile[tx][i]);
    }
}

// ===========================================================================
// Plain fp16 mma.sync GEMM: C[M,Nt] = A[M,Cq] @ B[Nt,Cq]^T + bias
// CTA 128x128x64, 50 k-iters, 3-stage cp.async, 2 CTA/SM. (proven structure)
// ===========================================================================
#define GBM 128
#define GBN 128
#define GBK 64
#define GNIT (Cq / GBK)            // 50
#define ABYTES (GBM * GBK * 2)
#define BBYTES (GBN * GBK * 2)
#define BUFB (ABYTES + BBYTES)
#define GSTAGES 3
#define GSMEM_TOTAL (GSTAGES * BUFB)
#define G_GM 8

__global__ __launch_bounds__(256, 2) void gemm_mma(
    const __half* __restrict__ A,
    const __half* __restrict__ Bt,
    const float* __restrict__ bias,
    float* __restrict__ C,
    int M, int Nt, int mt, int nt)
{
    extern __shared__ char smem[];
    const uint32_t sbase = smem_u32(smem);
    const int tid = threadIdx.x;
    const int wid = tid >> 5, lane = tid & 31;
    const int wm = wid >> 2, wn = wid & 3;

    int bid = blockIdx.x;
    int per_group = G_GM * nt;
    int gid = bid / per_group;
    int first_m = gid * G_GM;
    int gsz = min(G_GM, mt - first_m);
    int rem = bid % per_group;
    const int m0 = (first_m + rem % gsz) * GBM;
    const int n0 = (rem / gsz) * GBN;

    float acc[4][4][4];
    #pragma unroll
    for (int i = 0; i < 4; i++)
        #pragma unroll
        for (int j = 0; j < 4; j++)
            #pragma unroll
            for (int r = 0; r < 4; r++) acc[i][j][r] = 0.f;

    auto load_tile = [&](int it, int buf) {
        const int k0 = it * GBK;
        const uint32_t sA = sbase + buf * BUFB;
        const uint32_t sB = sA + ABYTES;
        #pragma unroll
        for (int p = 0; p < 4; p++) {
            int id = p * 256 + tid;
            int row = id >> 3, ch = id & 7;
            uint32_t so = swz128((uint32_t)(row * 128 + ch * 16));
            int m = min(m0 + row, M - 1);
            cp16(sA + so, A  + (size_t)m * Cq + k0 + ch * 8);
            cp16(sB + so, Bt + (size_t)(n0 + row) * Cq + k0 + ch * 8);
        }
        CP_COMMIT();
    };

    auto compute = [&](int buf) {
        const uint32_t sA = sbase + buf * BUFB + (uint32_t)(wm * 64 * 128);
        const uint32_t sB = sbase + buf * BUFB + ABYTES + (uint32_t)(wn * 32 * 128);
        #pragma unroll
        for (int kk = 0; kk < 4; kk++) {
            uint32_t afr[4][4];
            #pragma unroll
            for (int mi = 0; mi < 4; mi++) {
                int row = mi * 16 + (lane & 15);
                int cb = kk * 32 + ((lane >> 4) << 4);
                LDSM_X4(afr[mi], sA + swz128((uint32_t)(row * 128 + cb)));
            }
            uint32_t bfr[4][2];
            #pragma unroll
            for (int bj = 0; bj < 2; bj++) {
                int row = bj * 16 + ((lane >> 4) << 3) + (lane & 7);
                int cb = kk * 32 + (((lane >> 3) & 1) << 4);
                uint32_t r[4];
                LDSM_X4(r, sB + swz128((uint32_t)(row * 128 + cb)));
                bfr[2 * bj][0] = r[0];     bfr[2 * bj][1] = r[1];
                bfr[2 * bj + 1][0] = r[2]; bfr[2 * bj + 1][1] = r[3];
            }
            #pragma unroll
            for (int mi = 0; mi < 4; mi++)
                #pragma unroll
                for (int nj = 0; nj < 4; nj++)
                    MMA16816_F16(acc[mi][nj], afr[mi], bfr[nj]);
        }
    };

    load_tile(0, 0);
    load_tile(1, 1);
    for (int it = 0; it < GNIT; it++) {
        if (it + 1 < GNIT)
            asm volatile("cp.async.wait_group 1;" ::: "memory");
        else
            asm volatile("cp.async.wait_group 0;" ::: "memory");
        __syncthreads();
        if (it + 2 < GNIT) load_tile(it + 2, (it + 2) % GSTAGES);
        compute(it % GSTAGES);
    }

    const int mbase = m0 + wm * 64;
    const int nbase = n0 + wn * 32;
    #pragma unroll
    for (int mi = 0; mi < 4; mi++) {
        #pragma unroll
        for (int nj = 0; nj < 4; nj++) {
            int r0 = mbase + mi * 16 + (lane >> 2);
            int c = nbase + nj * 8 + 2 * (lane & 3);
            float bx = bias[c], by = bias[c + 1];
            if (r0 < M) {
                float2 o = make_float2(acc[mi][nj][0] + bx, acc[mi][nj][1] + by);
                *(float2*)(C + (size_t)r0 * Nt + c) = o;
            }
            if (r0 + 8 < M) {
                float2 o = make_float2(acc[mi][nj][2] + bx, acc[mi][nj][3] + by);
                *(float2*)(C + (size_t)(r0 + 8) * Nt + c) = o;
            }
        }
    }
}

// ===========================================================================
// Fused rmsnorm + fp16 convert + head-contiguous layout (proven).
// q keeps hi/lo split (preserves near-fp32 q through the S MMA).
// ===========================================================================
__global__ __launch_bounds__(256) void fuse_nc(
    const float* __restrict__ qkv,
    const float* __restrict__ qw, const float* __restrict__ kw,
    __half* __restrict__ gq, __half* __restrict__ gk, __half* __restrict__ gv)
{
    const int row = blockIdx.x;
    const int which = blockIdx.y;
    const int b = row / Nq, n = row % Nq;
    const float* p = qkv + (size_t)row * QKV_N + which * Cq;
    const int tid = threadIdx.x;

    float inv = 1.f;
    if (which < 2) {
        float ss = 0.f;
        for (int c = tid * 4; c < Cq; c += 1024) {
            float4 v = *(const float4*)(p + c);
            ss += v.x * v.x + v.y * v.y + v.z * v.z + v.w * v.w;
        }
        #pragma unroll
        for (int o = 16; o; o >>= 1) ss += __shfl_xor_sync(0xffffffffu, ss, o);
        __shared__ float red[8];
        if ((tid & 31) == 0) red[tid >> 5] = ss;
        __syncthreads();
        if (tid < 8) {
            float v = red[tid];
            #pragma unroll
            for (int o = 4; o; o >>= 1) v += __shfl_xor_sync(0xffu, v, o);
            if (tid == 0) red[0] = v;
        }
        __syncthreads();
        inv = rsqrtf(red[0] * (1.f / Cq) + EPSq);
    }

    if (which == 0) {
        const float sc = 0.08838834764831845f;
        for (int c = tid * 4; c < Cq; c += 1024) {
            float4 v = *(const float4*)(p + c);
            float4 wv = *(const float4*)(qw + c);
            int h = c >> 7, d = c & 127;
            __half* orow = gq + ((size_t)(b * Hq + h) * Nq + n) * 256;
            float f0 = v.x * inv * wv.x * sc;
            float f1 = v.y * inv * wv.y * sc;
            float f2 = v.z * inv * wv.z * sc;
            float f3 = v.w * inv * wv.w * sc;
            uint32_t h01, l01, h23, l23;
            pack_hl(f0, f1, h01, l01);
            pack_hl(f2, f3, h23, l23);
            *(uint32_t*)(orow + d)           = h01;
            *(uint32_t*)(orow + d + 2)       = h23;
            *(uint32_t*)(orow + 128 + d)     = l01;
            *(uint32_t*)(orow + 128 + d + 2) = l23;
        }
    } else if (which == 1) {
        for (int c = tid * 4; c < Cq; c += 1024) {
            float4 v = *(const float4*)(p + c);
            float4 wv = *(const float4*)(kw + c);
            int h = c >> 7, d = c & 127;
            __half* orow = gk + ((size_t)(b * Hq + h) * Nq + n) * 128;
            *(uint32_t*)(orow + d)     = pack_h(v.x * inv * wv.x, v.y * inv * wv.y);
            *(uint32_t*)(orow + d + 2) = pack_h(v.z * inv * wv.z, v.w * inv * wv.w);
        }
    } else {
        for (int c = tid * 4; c < Cq; c += 1024) {
            float4 v = *(const float4*)(p + c);
            int h = c >> 7, d = c & 127;
            __half* orow = gv + ((size_t)(b * Hq + h) * Nq + n) * 128;
            *(uint32_t*)(orow + d)     = pack_h(v.x, v.y);
            *(uint32_t*)(orow + d + 2) = pack_h(v.z, v.w);
        }
    }
}

// ===========================================================================
// FA2-style flash attention (proven). Epilogue writes fp16, stride Cq.
// ===========================================================================
#define ZQ_S 264
#define ZQ_B (ZQ_S * 2)
#define ZK_B 272
#define ZKBUF (64 * ZK_B)
#define ZA_Q 0
#define ZA_K (128 * ZQ_B)
#define ZA_V (ZA_K + 2 * ZKBUF)
#define ZSMEM (ZA_V + 2 * ZKBUF)

__global__ __launch_bounds__(256) void fa2(
    const __half* __restrict__ gq, const __half* __restrict__ gk,
    const __half* __restrict__ gv, __half* __restrict__ outAs)
{
    extern __shared__ char sm[];
    const uint32_t sq = smem_u32(sm + ZA_Q);
    const uint32_t sk = smem_u32(sm + ZA_K);
    const uint32_t sv = smem_u32(sm + ZA_V);

    const int qt = blockIdx.x, h = blockIdx.y, b = blockIdx.z;
    const int tid = threadIdx.x, w = tid >> 5, lane = tid & 31;
    const int q0 = qt * 128;

    const __half* qb = gq + (size_t)(b * Hq + h) * Nq * 256;
    const __half* kb = gk + (size_t)(b * Hq + h) * Nq * 128;
    const __half* vb = gv + (size_t)(b * Hq + h) * Nq * 128;

    for (int i = tid; i < 128 * 32; i += 256) {
        int r = i >> 5, ch = i & 31;
        int n = q0 + r;
        int nc = min(n, Nq - 1);
        cp16z(sq + (uint32_t)(r * ZQ_B + ch * 16),
              qb + (size_t)nc * 256 + ch * 8, (n < Nq) ? 16 : 0);
    }
    CP_COMMIT();

    auto fillKV = [&](int kt, int buf) {
        const int k0 = kt * 64;
        const uint32_t dk = sk + buf * ZKBUF;
        const uint32_t dv = sv + buf * ZKBUF;
        for (int i = tid; i < 64 * 16; i += 256) {
            int r = i >> 4, ch = i & 15;
            int n = k0 + r;
            int nc = min(n, Nq - 1);
            int sz = (n < Nq) ? 16 : 0;
            cp16z(dk + (uint32_t)(r * ZK_B + ch * 16), kb + (size_t)nc * 128 + ch * 8, sz);
            cp16z(dv + (uint32_t)(r * ZK_B + ch * 16), vb + (size_t)nc * 128 + ch * 8, sz);
        }
        CP_COMMIT();
    };
    fillKV(0, 0);

    float m0 = -1e30f, m1 = -1e30f, l0 = 0.f, l1 = 0.f;
    float acc_o[16][4];
    #pragma unroll
    for (int g = 0; g < 16; g++)
        #pragma unroll
        for (int r = 0; r < 4; r++) acc_o[g][r] = 0.f;

    const int arow = w * 16 + (lane & 15);
    const uint32_t a_cb = (uint32_t)((lane >> 4) << 4);
    const int krow_b = ((lane >> 4) << 3) + (lane & 7);
    const uint32_t b_cb = (uint32_t)(((lane >> 3) & 1) << 4);

    for (int kt = 0; kt < 17; kt++) {
        const int buf = kt & 1;
        asm volatile("cp.async.wait_group 0;" ::: "memory");
        __syncthreads();
        if (kt < 16) fillKV(kt + 1, buf ^ 1);

        const uint32_t skb = sk + buf * ZKBUF;
        const uint32_t svb = sv + buf * ZKBUF;

        float accs[8][4];
        #pragma unroll
        for (int nj = 0; nj < 8; nj++)
            #pragma unroll
            for (int r = 0; r < 4; r++) accs[nj][r] = 0.f;

        #pragma unroll
        for (int pass = 0; pass < 2; pass++) {
            #pragma unroll
            for (int ks = 0; ks < 8; ks++) {
                uint32_t afr[4];
                LDSM_X4(afr, sq + (uint32_t)(arow * ZQ_B + pass * 256 + ks * 32) + a_cb);
                #pragma unroll
                for (int bj = 0; bj < 4; bj++) {
                    uint32_t r[4];
                    LDSM_X4(r, skb + (uint32_t)((bj * 16 + krow_b) * ZK_B + ks * 32) + b_cb);
                    uint32_t b0[2] = {r[0], r[1]};
                    uint32_t b1[2] = {r[2], r[3]};
                    MMA16816_F16(accs[2 * bj],     afr, b0);
                    MMA16816_F16(accs[2 * bj + 1], afr, b1);
                }
            }
        }

        if (kt == 16) {
            #pragma unroll
            for (int nj = 0; nj < 8; nj++)
                #pragma unroll
                for (int j = 0; j < 4; j++) {
                    int col = 1024 + nj * 8 + 2 * (lane & 3) + (j & 1);
                    if (col >= Nq) accs[nj][j] = -1e30f;
                }
        }

        float mx0 = -1e30f, mx1 = -1e30f;
        #pragma unroll
        for (int nj = 0; nj < 8; nj++) {
            mx0 = fmaxf(mx0, fmaxf(accs[nj][0], accs[nj][1]));
            mx1 = fmaxf(mx1, fmaxf(accs[nj][2], accs[nj][3]));
        }
        mx0 = fmaxf(mx0, __shfl_xor_sync(0xffffffffu, mx0, 1));
        mx0 = fmaxf(mx0, __shfl_xor_sync(0xffffffffu, mx0, 2));
        mx1 = fmaxf(mx1, __shfl_xor_sync(0xffffffffu, mx1, 1));
        mx1 = fmaxf(mx1, __shfl_xor_sync(0xffffffffu, mx1, 2));

        const float mn0 = fmaxf(m0, mx0), mn1 = fmaxf(m1, mx1);
        const float cr0 = __expf(m0 - mn0), cr1 = __expf(m1 - mn1);

        float s0 = 0.f, s1 = 0.f;
        uint32_t ph[8][2], pl[8][2];
        #pragma unroll
        for (int nj = 0; nj < 8; nj++) {
            float p0 = __expf(accs[nj][0] - mn0);
            float p1 = __expf(accs[nj][1] - mn0);
            float p2 = __expf(accs[nj][2] - mn1);
            float p3 = __expf(accs[nj][3] - mn1);
            s0 += p0 + p1; s1 += p2 + p3;
            pack_hl(p0, p1, ph[nj][0], pl[nj][0]);
            pack_hl(p2, p3, ph[nj][1], pl[nj][1]);
        }
        s0 += __shfl_xor_sync(0xffffffffu, s0, 1);
        s0 += __shfl_xor_sync(0xffffffffu, s0, 2);
        s1 += __shfl_xor_sync(0xffffffffu, s1, 1);
        s1 += __shfl_xor_sync(0xffffffffu, s1, 2);
        l0 = l0 * cr0 + s0; l1 = l1 * cr1 + s1;
        m0 = mn0; m1 = mn1;

        #pragma unroll
        for (int g = 0; g < 16; g++) {
            acc_o[g][0] *= cr0; acc_o[g][1] *= cr0;
            acc_o[g][2] *= cr1; acc_o[g][3] *= cr1;
        }

        const int vrow_b = (lane & 7) + (((lane >> 3) & 1) << 3);
        const uint32_t v_cb = (uint32_t)((lane >> 4) << 4);
        #pragma unroll
        for (int kc = 0; kc < 4; kc++) {
            uint32_t aPh[4] = {ph[2 * kc][0], ph[2 * kc][1], ph[2 * kc + 1][0], ph[2 * kc + 1][1]};
            uint32_t aPl[4] = {pl[2 * kc][0], pl[2 * kc][1], pl[2 * kc + 1][0], pl[2 * kc + 1][1]};
            #pragma unroll
            for (int g2 = 0; g2 < 8; g2++) {
                uint32_t r[4];
                LDSM_X4_T(r, svb + (uint32_t)((kc * 16 + vrow_b) * ZK_B + g2 * 32) + v_cb);
                uint32_t b0[2] = {r[0], r[1]};
                uint32_t b1[2] = {r[2], r[3]};
                MMA16816_F16(acc_o[2 * g2],     aPh, b0);
                MMA16816_F16(acc_o[2 * g2 + 1], aPh, b1);
                MMA16816_F16(acc_o[2 * g2],     aPl, b0);
                MMA16816_F16(acc_o[2 * g2 + 1], aPl, b1);
            }
        }
    }

    // ---- epilogue: normalize, write fp16 (stride Cq) ----
    {
        const float invl0 = 1.f / l0, invl1 = 1.f / l1;
        const int n0v = q0 + w * 16 + (lane >> 2);
        const int n1v = n0v + 8;
        #pragma unroll
        for (int g = 0; g < 16; g++) {
            int c = h * Dq + g * 8 + 2 * (lane & 3);
            if (n0v < Nq) {
                __half* row = outAs + (size_t)(b * Nq + n0v) * Cq;
                *(uint32_t*)(row + c) = pack_h(acc_o[g][0] * invl0, acc_o[g][1] * invl0);
            }
            if (n1v < Nq) {
                __half* row = outAs + (size_t)(b * Nq + n1v) * Cq;
                *(uint32_t*)(row + c) = pack_h(acc_o[g][2] * invl1, acc_o[g][3] * invl1);
            }
        }
    }
}

// ===========================================================================
extern "C" void kernel_launch(void* const* d_in, const int* in_sizes, int n_in,
                              void* d_out, int out_size)
{
    const float* x        = (const float*)d_in[0];
    const float* qkv_w    = (const float*)d_in[1];
    const float* qkv_b    = (const float*)d_in[2];
    const float* q_norm_w = (const float*)d_in[3];
    const float* k_norm_w = (const float*)d_in[4];
    const float* proj_w   = (const float*)d_in[5];
    const float* proj_b   = (const float*)d_in[6];
    float* out = (float*)d_out;

    float* qkvp = nullptr;
    __half *asp = nullptr, *wqp = nullptr, *wpp = nullptr;
    __half *qp = nullptr, *kp = nullptr, *vp = nullptr;
    cudaGetSymbolAddress((void**)&qkvp, g_qkv);
    cudaGetSymbolAddress((void**)&asp, g_as);
    cudaGetSymbolAddress((void**)&wqp, g_wq);
    cudaGetSymbolAddress((void**)&wpp, g_wp);
    cudaGetSymbolAddress((void**)&qp, g_q);
    cudaGetSymbolAddress((void**)&kp, g_k);
    cudaGetSymbolAddress((void**)&vp, g_v);

    cudaFuncSetAttribute(gemm_mma,
                         cudaFuncAttributeMaxDynamicSharedMemorySize, GSMEM_TOTAL);
    cudaFuncSetAttribute(fa2,
                         cudaFuncAttributeMaxDynamicSharedMemorySize, ZSMEM);

    const int mt = (Mq + GBM - 1) / GBM;        // 65
    const int nt_qkv = QKV_N / GBN;             // 75
    const int nt_prj = Cq / GBN;                // 25

    // 1) convert x to fp16; round weights to fp16 (transposed)
    {
        size_t e4 = (size_t)Mq * Cq / 4;
        conv_a_kernel<<<(unsigned)((e4 + 255) / 256), 256>>>(x, asp, Mq);
    }
    split_wt_kernel<<<dim3(QKV_N / 32, Cq / 32), dim3(32, 8)>>>(qkv_w, wqp, QKV_N);
    split_wt_kernel<<<dim3(Cq / 32, Cq / 32), dim3(32, 8)>>>(proj_w, wpp, Cq);

    // 2) qkv = x @ qkv_w + b   (1-pass fp16)
    gemm_mma<<<mt * nt_qkv, 256, GSMEM_TOTAL>>>(
        asp, wqp, qkv_b, qkvp, Mq, QKV_N, mt, nt_qkv);

    // 3) fused rmsnorm + fp16 convert -> g_q / g_k / g_v
    fuse_nc<<<dim3(Mq, 3), 256>>>(qkvp, q_norm_w, k_norm_w, qp, kp, vp);

    // 4) FA2 attention -> g_as (fp16)
    fa2<<<dim3(9, Hq, Bq), 256, ZSMEM>>>(qp, kp, vp, asp);

    // 5) out = att @ proj_w + b   (1-pass fp16)
    gemm_mma<<<mt * nt_prj, 256, GSMEM_TOTAL>>>(
        asp, wpp, proj_b, out, Mq, Cq, mt, nt_prj);
}

// round 14
// speedup vs baseline: 3.4517x; 1.1403x over previous
#include <cuda_runtime.h>
#include <cuda_bf16.h>
#include <cuda_fp16.h>
#include <cstdint>
#include <math.h>

// Problem constants
#define Bq 8
#define Nq 1025
#define Cq 3200
#define Hq 25
#define Dq 128
#define Mq (Bq * Nq)        // 8200
#define QKV_N (3 * Cq)      // 9600
#define EPSq 1e-6f

// Scratch (__device__ globals per alloc-free rule)
__device__ float g_qkv[(size_t)Mq * QKV_N];
__device__ __half g_as[(size_t)Mq * Cq];            // fp16 A (x, then attn out)
__device__ __half g_wq[(size_t)QKV_N * Cq];         // qkv_w^T fp16
__device__ __half g_wp[(size_t)Cq * Cq];            // proj_w^T fp16
__device__ __half g_q[(size_t)Bq * Hq * Nq * 128];  // q: fp16, normed+scaled
__device__ __half g_k[(size_t)Bq * Hq * Nq * 128];  // k: fp16, normed
__device__ __half g_v[(size_t)Bq * Hq * Nq * 128];  // v: fp16

// ===========================================================================
// helpers
// ===========================================================================
__device__ __forceinline__ uint32_t smem_u32(const void* p) {
    uint32_t a;
    asm("{ .reg .u64 t; cvta.to.shared.u64 t, %1; cvt.u32.u64 %0, t; }"
        : "=r"(a) : "l"(p));
    return a;
}
__device__ __forceinline__ uint32_t swz128(uint32_t off) {
    return off ^ ((off >> 3) & 0x70);
}
__device__ __forceinline__ void cp16(uint32_t s, const void* g) {
    asm volatile("cp.async.cg.shared.global [%0], [%1], 16;"
                 :: "r"(s), "l"(g) : "memory");
}
__device__ __forceinline__ void cp16z(uint32_t s, const void* g, int sz) {
    asm volatile("cp.async.cg.shared.global [%0], [%1], 16, %2;"
                 :: "r"(s), "l"(g), "r"(sz) : "memory");
}
#define CP_COMMIT() asm volatile("cp.async.commit_group;" ::: "memory")

#define LDSM_X4(r, addr)                                                       \
    asm volatile("ldmatrix.sync.aligned.m8n8.x4.shared.b16 {%0,%1,%2,%3}, [%4];" \
        : "=r"((r)[0]), "=r"((r)[1]), "=r"((r)[2]), "=r"((r)[3]) : "r"(addr))

#define LDSM_X4_T(r, addr)                                                     \
    asm volatile("ldmatrix.sync.aligned.m8n8.x4.trans.shared.b16 {%0,%1,%2,%3}, [%4];" \
        : "=r"((r)[0]), "=r"((r)[1]), "=r"((r)[2]), "=r"((r)[3]) : "r"(addr))

#define MMA16816_F16(d, a, b)                                                  \
    asm volatile("mma.sync.aligned.m16n8k16.row.col.f32.f16.f16.f32 "          \
        "{%0,%1,%2,%3}, {%4,%5,%6,%7}, {%8,%9}, {%0,%1,%2,%3};"                \
        : "+f"((d)[0]), "+f"((d)[1]), "+f"((d)[2]), "+f"((d)[3])               \
        : "r"((a)[0]), "r"((a)[1]), "r"((a)[2]), "r"((a)[3]),                  \
          "r"((b)[0]), "r"((b)[1]))

__device__ __forceinline__ uint32_t pack_h(float x, float y) {
    __half2 h2; h2.x = __float2half_rn(x); h2.y = __float2half_rn(y);
    return *(uint32_t*)&h2;
}

// ===========================================================================
// Convert kernels
// ===========================================================================
__global__ __launch_bounds__(256) void conv_a_kernel(
    const float* __restrict__ in, __half* __restrict__ out, int M)
{
    size_t idx = ((size_t)blockIdx.x * 256 + threadIdx.x) * 4;
    if (idx >= (size_t)M * Cq) return;
    float4 v = *(const float4*)(in + idx);
    *(uint32_t*)(out + idx)     = pack_h(v.x, v.y);
    *(uint32_t*)(out + idx + 2) = pack_h(v.z, v.w);
}

__global__ __launch_bounds__(256) void split_wt_kernel(
    const float* __restrict__ W, __half* __restrict__ out, int Nw)
{
    __shared__ float tile[32][33];
    int n0 = blockIdx.x * 32, k0 = blockIdx.y * 32;
    int tx = threadIdx.x, ty = threadIdx.y;
    #pragma unroll
    for (int i = ty; i < 32; i += 8)
        tile[i][tx] = W[(size_t)(k0 + i) * Nw + n0 + tx];
    __syncthreads();
    #pragma unroll
    for (int i = ty; i < 32; i += 8) {
        int n = n0 + i, k = k0 + tx;
        out[(size_t)n * Cq + k] = __float2half_rn(tile[tx][i]);
    }
}

// ===========================================================================
// Plain fp16 mma.sync GEMM (proven structure, unchanged)
// ===========================================================================
#define GBM 128
#define GBN 128
#define GBK 64
#define GNIT (Cq / GBK)            // 50
#define ABYTES (GBM * GBK * 2)
#define BBYTES (GBN * GBK * 2)
#define BUFB (ABYTES + BBYTES)
#define GSTAGES 3
#define GSMEM_TOTAL (GSTAGES * BUFB)
#define G_GM 8

__global__ __launch_bounds__(256, 2) void gemm_mma(
    const __half* __restrict__ A,
    const __half* __restrict__ Bt,
    const float* __restrict__ bias,
    float* __restrict__ C,
    int M, int Nt, int mt, int nt)
{
    extern __shared__ char smem[];
    const uint32_t sbase = smem_u32(smem);
    const int tid = threadIdx.x;
    const int wid = tid >> 5, lane = tid & 31;
    const int wm = wid >> 2, wn = wid & 3;

    int bid = blockIdx.x;
    int per_group = G_GM * nt;
    int gid = bid / per_group;
    int first_m = gid * G_GM;
    int gsz = min(G_GM, mt - first_m);
    int rem = bid % per_group;
    const int m0 = (first_m + rem % gsz) * GBM;
    const int n0 = (rem / gsz) * GBN;

    float acc[4][4][4];
    #pragma unroll
    for (int i = 0; i < 4; i++)
        #pragma unroll
        for (int j = 0; j < 4; j++)
            #pragma unroll
            for (int r = 0; r < 4; r++) acc[i][j][r] = 0.f;

    auto load_tile = [&](int it, int buf) {
        const int k0 = it * GBK;
        const uint32_t sA = sbase + buf * BUFB;
        const uint32_t sB = sA + ABYTES;
        #pragma unroll
        for (int p = 0; p < 4; p++) {
            int id = p * 256 + tid;
            int row = id >> 3, ch = id & 7;
            uint32_t so = swz128((uint32_t)(row * 128 + ch * 16));
            int m = min(m0 + row, M - 1);
            cp16(sA + so, A  + (size_t)m * Cq + k0 + ch * 8);
            cp16(sB + so, Bt + (size_t)(n0 + row) * Cq + k0 + ch * 8);
        }
        CP_COMMIT();
    };

    auto compute = [&](int buf) {
        const uint32_t sA = sbase + buf * BUFB + (uint32_t)(wm * 64 * 128);
        const uint32_t sB = sbase + buf * BUFB + ABYTES + (uint32_t)(wn * 32 * 128);
        #pragma unroll
        for (int kk = 0; kk < 4; kk++) {
            uint32_t afr[4][4];
            #pragma unroll
            for (int mi = 0; mi < 4; mi++) {
                int row = mi * 16 + (lane & 15);
                int cb = kk * 32 + ((lane >> 4) << 4);
                LDSM_X4(afr[mi], sA + swz128((uint32_t)(row * 128 + cb)));
            }
            uint32_t bfr[4][2];
            #pragma unroll
            for (int bj = 0; bj < 2; bj++) {
                int row = bj * 16 + ((lane >> 4) << 3) + (lane & 7);
                int cb = kk * 32 + (((lane >> 3) & 1) << 4);
                uint32_t r[4];
                LDSM_X4(r, sB + swz128((uint32_t)(row * 128 + cb)));
                bfr[2 * bj][0] = r[0];     bfr[2 * bj][1] = r[1];
                bfr[2 * bj + 1][0] = r[2]; bfr[2 * bj + 1][1] = r[3];
            }
            #pragma unroll
            for (int mi = 0; mi < 4; mi++)
                #pragma unroll
                for (int nj = 0; nj < 4; nj++)
                    MMA16816_F16(acc[mi][nj], afr[mi], bfr[nj]);
        }
    };

    load_tile(0, 0);
    load_tile(1, 1);
    for (int it = 0; it < GNIT; it++) {
        if (it + 1 < GNIT)
            asm volatile("cp.async.wait_group 1;" ::: "memory");
        else
            asm volatile("cp.async.wait_group 0;" ::: "memory");
        __syncthreads();
        if (it + 2 < GNIT) load_tile(it + 2, (it + 2) % GSTAGES);
        compute(it % GSTAGES);
    }

    const int mbase = m0 + wm * 64;
    const int nbase = n0 + wn * 32;
    #pragma unroll
    for (int mi = 0; mi < 4; mi++) {
        #pragma unroll
        for (int nj = 0; nj < 4; nj++) {
            int r0 = mbase + mi * 16 + (lane >> 2);
            int c = nbase + nj * 8 + 2 * (lane & 3);
            float bx = bias[c], by = bias[c + 1];
            if (r0 < M) {
                float2 o = make_float2(acc[mi][nj][0] + bx, acc[mi][nj][1] + by);
                *(float2*)(C + (size_t)r0 * Nt + c) = o;
            }
            if (r0 + 8 < M) {
                float2 o = make_float2(acc[mi][nj][2] + bx, acc[mi][nj][3] + by);
                *(float2*)(C + (size_t)(r0 + 8) * Nt + c) = o;
            }
        }
    }
}

// ===========================================================================
// Fused rmsnorm + fp16 convert + head-contiguous layout.
// q now plain fp16 (128-wide), like k.
// ===========================================================================
__global__ __launch_bounds__(256) void fuse_nc(
    const float* __restrict__ qkv,
    const float* __restrict__ qw, const float* __restrict__ kw,
    __half* __restrict__ gq, __half* __restrict__ gk, __half* __restrict__ gv)
{
    const int row = blockIdx.x;
    const int which = blockIdx.y;
    const int b = row / Nq, n = row % Nq;
    const float* p = qkv + (size_t)row * QKV_N + which * Cq;
    const int tid = threadIdx.x;

    float inv = 1.f;
    if (which < 2) {
        float ss = 0.f;
        for (int c = tid * 4; c < Cq; c += 1024) {
            float4 v = *(const float4*)(p + c);
            ss += v.x * v.x + v.y * v.y + v.z * v.z + v.w * v.w;
        }
        #pragma unroll
        for (int o = 16; o; o >>= 1) ss += __shfl_xor_sync(0xffffffffu, ss, o);
        __shared__ float red[8];
        if ((tid & 31) == 0) red[tid >> 5] = ss;
        __syncthreads();
        if (tid < 8) {
            float v = red[tid];
            #pragma unroll
            for (int o = 4; o; o >>= 1) v += __shfl_xor_sync(0xffu, v, o);
            if (tid == 0) red[0] = v;
        }
        __syncthreads();
        inv = rsqrtf(red[0] * (1.f / Cq) + EPSq);
    }

    if (which == 0) {
        const float sc = 0.08838834764831845f;
        for (int c = tid * 4; c < Cq; c += 1024) {
            float4 v = *(const float4*)(p + c);
            float4 wv = *(const float4*)(qw + c);
            int h = c >> 7, d = c & 127;
            __half* orow = gq + ((size_t)(b * Hq + h) * Nq + n) * 128;
            *(uint32_t*)(orow + d)     = pack_h(v.x * inv * wv.x * sc, v.y * inv * wv.y * sc);
            *(uint32_t*)(orow + d + 2) = pack_h(v.z * inv * wv.z * sc, v.w * inv * wv.w * sc);
        }
    } else if (which == 1) {
        for (int c = tid * 4; c < Cq; c += 1024) {
            float4 v = *(const float4*)(p + c);
            float4 wv = *(const float4*)(kw + c);
            int h = c >> 7, d = c & 127;
            __half* orow = gk + ((size_t)(b * Hq + h) * Nq + n) * 128;
            *(uint32_t*)(orow + d)     = pack_h(v.x * inv * wv.x, v.y * inv * wv.y);
            *(uint32_t*)(orow + d + 2) = pack_h(v.z * inv * wv.z, v.w * inv * wv.w);
        }
    } else {
        for (int c = tid * 4; c < Cq; c += 1024) {
            float4 v = *(const float4*)(p + c);
            int h = c >> 7, d = c & 127;
            __half* orow = gv + ((size_t)(b * Hq + h) * Nq + n) * 128;
            *(uint32_t*)(orow + d)     = pack_h(v.x, v.y);
            *(uint32_t*)(orow + d + 2) = pack_h(v.z, v.w);
        }
    }
}

// ===========================================================================
// FA2-style flash attention, single-pass fp16:
//   S = Qh Kh^T (8 k16-steps), O = Ph Vh (4 k16-steps)
// Q 128x128 fp16, K/V double-buffered. 104 KB smem -> 2 CTAs/SM.
// ===========================================================================
#define ZK_B 272
#define ZKBUF (64 * ZK_B)
#define ZA_Q 0
#define ZA_K (128 * ZK_B)                  // 34816
#define ZA_V (ZA_K + 2 * ZKBUF)            // 69632
#define ZSMEM (ZA_V + 2 * ZKBUF)           // 104448

__global__ __launch_bounds__(256, 2) void fa2(
    const __half* __restrict__ gq, const __half* __restrict__ gk,
    const __half* __restrict__ gv, __half* __restrict__ outAs)
{
    extern __shared__ char sm[];
    const uint32_t sq = smem_u32(sm + ZA_Q);
    const uint32_t sk = smem_u32(sm + ZA_K);
    const uint32_t sv = smem_u32(sm + ZA_V);

    const int qt = blockIdx.x, h = blockIdx.y, b = blockIdx.z;
    const int tid = threadIdx.x, w = tid >> 5, lane = tid & 31;
    const int q0 = qt * 128;

    const __half* qb = gq + (size_t)(b * Hq + h) * Nq * 128;
    const __half* kb = gk + (size_t)(b * Hq + h) * Nq * 128;
    const __half* vb = gv + (size_t)(b * Hq + h) * Nq * 128;

    // ---- Q fill ----
    for (int i = tid; i < 128 * 16; i += 256) {
        int r = i >> 4, ch = i & 15;
        int n = q0 + r;
        int nc = min(n, Nq - 1);
        cp16z(sq + (uint32_t)(r * ZK_B + ch * 16),
              qb + (size_t)nc * 128 + ch * 8, (n < Nq) ? 16 : 0);
    }
    CP_COMMIT();

    auto fillKV = [&](int kt, int buf) {
        const int k0 = kt * 64;
        const uint32_t dk = sk + buf * ZKBUF;
        const uint32_t dv = sv + buf * ZKBUF;
        for (int i = tid; i < 64 * 16; i += 256) {
            int r = i >> 4, ch = i & 15;
            int n = k0 + r;
            int nc = min(n, Nq - 1);
            int sz = (n < Nq) ? 16 : 0;
            cp16z(dk + (uint32_t)(r * ZK_B + ch * 16), kb + (size_t)nc * 128 + ch * 8, sz);
            cp16z(dv + (uint32_t)(r * ZK_B + ch * 16), vb + (size_t)nc * 128 + ch * 8, sz);
        }
        CP_COMMIT();
    };
    fillKV(0, 0);

    float m0 = -1e30f, m1 = -1e30f, l0 = 0.f, l1 = 0.f;
    float acc_o[16][4];
    #pragma unroll
    for (int g = 0; g < 16; g++)
        #pragma unroll
        for (int r = 0; r < 4; r++) acc_o[g][r] = 0.f;

    const int arow = w * 16 + (lane & 15);
    const uint32_t a_cb = (uint32_t)((lane >> 4) << 4);
    const int krow_b = ((lane >> 4) << 3) + (lane & 7);
    const uint32_t b_cb = (uint32_t)(((lane >> 3) & 1) << 4);

    for (int kt = 0; kt < 17; kt++) {
        const int buf = kt & 1;
        asm volatile("cp.async.wait_group 0;" ::: "memory");
        __syncthreads();
        if (kt < 16) fillKV(kt + 1, buf ^ 1);

        const uint32_t skb = sk + buf * ZKBUF;
        const uint32_t svb = sv + buf * ZKBUF;

        // ---- S = Qh Kh^T : 8 k16-steps ----
        float accs[8][4];
        #pragma unroll
        for (int nj = 0; nj < 8; nj++)
            #pragma unroll
            for (int r = 0; r < 4; r++) accs[nj][r] = 0.f;

        #pragma unroll
        for (int ks = 0; ks < 8; ks++) {
            uint32_t afr[4];
            LDSM_X4(afr, sq + (uint32_t)(arow * ZK_B + ks * 32) + a_cb);
            #pragma unroll
            for (int bj = 0; bj < 4; bj++) {
                uint32_t r[4];
                LDSM_X4(r, skb + (uint32_t)((bj * 16 + krow_b) * ZK_B + ks * 32) + b_cb);
                uint32_t b0[2] = {r[0], r[1]};
                uint32_t b1[2] = {r[2], r[3]};
                MMA16816_F16(accs[2 * bj],     afr, b0);
                MMA16816_F16(accs[2 * bj + 1], afr, b1);
            }
        }

        if (kt == 16) {
            #pragma unroll
            for (int nj = 0; nj < 8; nj++)
                #pragma unroll
                for (int j = 0; j < 4; j++) {
                    int col = 1024 + nj * 8 + 2 * (lane & 3) + (j & 1);
                    if (col >= Nq) accs[nj][j] = -1e30f;
                }
        }

        // ---- register softmax ----
        float mx0 = -1e30f, mx1 = -1e30f;
        #pragma unroll
        for (int nj = 0; nj < 8; nj++) {
            mx0 = fmaxf(mx0, fmaxf(accs[nj][0], accs[nj][1]));
            mx1 = fmaxf(mx1, fmaxf(accs[nj][2], accs[nj][3]));
        }
        mx0 = fmaxf(mx0, __shfl_xor_sync(0xffffffffu, mx0, 1));
        mx0 = fmaxf(mx0, __shfl_xor_sync(0xffffffffu, mx0, 2));
        mx1 = fmaxf(mx1, __shfl_xor_sync(0xffffffffu, mx1, 1));
        mx1 = fmaxf(mx1, __shfl_xor_sync(0xffffffffu, mx1, 2));

        const float mn0 = fmaxf(m0, mx0), mn1 = fmaxf(m1, mx1);
        const float cr0 = __expf(m0 - mn0), cr1 = __expf(m1 - mn1);

        float s0 = 0.f, s1 = 0.f;
        uint32_t ph[8][2];
        #pragma unroll
        for (int nj = 0; nj < 8; nj++) {
            float p0 = __expf(accs[nj][0] - mn0);
            float p1 = __expf(accs[nj][1] - mn0);
            float p2 = __expf(accs[nj][2] - mn1);
            float p3 = __expf(accs[nj][3] - mn1);
            s0 += p0 + p1; s1 += p2 + p3;
            ph[nj][0] = pack_h(p0, p1);
            ph[nj][1] = pack_h(p2, p3);
        }
        s0 += __shfl_xor_sync(0xffffffffu, s0, 1);
        s0 += __shfl_xor_sync(0xffffffffu, s0, 2);
        s1 += __shfl_xor_sync(0xffffffffu, s1, 1);
        s1 += __shfl_xor_sync(0xffffffffu, s1, 2);
        l0 = l0 * cr0 + s0; l1 = l1 * cr1 + s1;
        m0 = mn0; m1 = mn1;

        #pragma unroll
        for (int g = 0; g < 16; g++) {
            acc_o[g][0] *= cr0; acc_o[g][1] *= cr0;
            acc_o[g][2] *= cr1; acc_o[g][3] *= cr1;
        }

        // ---- O += Ph Vh : 4 k16-steps ----
        const int vrow_b = (lane & 7) + (((lane >> 3) & 1) << 3);
        const uint32_t v_cb = (uint32_t)((lane >> 4) << 4);
        #pragma unroll
        for (int kc = 0; kc < 4; kc++) {
            uint32_t aPh[4] = {ph[2 * kc][0], ph[2 * kc][1], ph[2 * kc + 1][0], ph[2 * kc + 1][1]};
            #pragma unroll
            for (int g2 = 0; g2 < 8; g2++) {
                uint32_t r[4];
                LDSM_X4_T(r, svb + (uint32_t)((kc * 16 + vrow_b) * ZK_B + g2 * 32) + v_cb);
                uint32_t b0[2] = {r[0], r[1]};
                uint32_t b1[2] = {r[2], r[3]};
                MMA16816_F16(acc_o[2 * g2],     aPh, b0);
                MMA16816_F16(acc_o[2 * g2 + 1], aPh, b1);
            }
        }
    }

    // ---- epilogue: normalize, write fp16 (stride Cq) ----
    {
        const float invl0 = 1.f / l0, invl1 = 1.f / l1;
        const int n0v = q0 + w * 16 + (lane >> 2);
        const int n1v = n0v + 8;
        #pragma unroll
        for (int g = 0; g < 16; g++) {
            int c = h * Dq + g * 8 + 2 * (lane & 3);
            if (n0v < Nq) {
                __half* row = outAs + (size_t)(b * Nq + n0v) * Cq;
                *(uint32_t*)(row + c) = pack_h(acc_o[g][0] * invl0, acc_o[g][1] * invl0);
            }
            if (n1v < Nq) {
                __half* row = outAs + (size_t)(b * Nq + n1v) * Cq;
                *(uint32_t*)(row + c) = pack_h(acc_o[g][2] * invl1, acc_o[g][3] * invl1);
            }
        }
    }
}

// ===========================================================================
extern "C" void kernel_launch(void* const* d_in, const int* in_sizes, int n_in,
                              void* d_out, int out_size)
{
    const float* x        = (const float*)d_in[0];
    const float* qkv_w    = (const float*)d_in[1];
    const float* qkv_b    = (const float*)d_in[2];
    const float* q_norm_w = (const float*)d_in[3];
    const float* k_norm_w = (const float*)d_in[4];
    const float* proj_w   = (const float*)d_in[5];
    const float* proj_b   = (const float*)d_in[6];
    float* out = (float*)d_out;

    float* qkvp = nullptr;
    __half *asp = nullptr, *wqp = nullptr, *wpp = nullptr;
    __half *qp = nullptr, *kp = nullptr, *vp = nullptr;
    cudaGetSymbolAddress((void**)&qkvp, g_qkv);
    cudaGetSymbolAddress((void**)&asp, g_as);
    cudaGetSymbolAddress((void**)&wqp, g_wq);
    cudaGetSymbolAddress((void**)&wpp, g_wp);
    cudaGetSymbolAddress((void**)&qp, g_q);
    cudaGetSymbolAddress((void**)&kp, g_k);
    cudaGetSymbolAddress((void**)&vp, g_v);

    cudaFuncSetAttribute(gemm_mma,
                         cudaFuncAttributeMaxDynamicSharedMemorySize, GSMEM_TOTAL);
    cudaFuncSetAttribute(fa2,
                         cudaFuncAttributeMaxDynamicSharedMemorySize, ZSMEM);

    const int mt = (Mq + GBM - 1) / GBM;        // 65
    const int nt_qkv = QKV_N / GBN;             // 75
    const int nt_prj = Cq / GBN;                // 25

    // 1) convert x to fp16; round weights to fp16 (transposed)
    {
        size_t e4 = (size_t)Mq * Cq / 4;
        conv_a_kernel<<<(unsigned)((e4 + 255) / 256), 256>>>(x, asp, Mq);
    }
    split_wt_kernel<<<dim3(QKV_N / 32, Cq / 32), dim3(32, 8)>>>(qkv_w, wqp, QKV_N);
    split_wt_kernel<<<dim3(Cq / 32, Cq / 32), dim3(32, 8)>>>(proj_w, wpp, Cq);

    // 2) qkv = x @ qkv_w + b   (1-pass fp16)
    gemm_mma<<<mt * nt_qkv, 256, GSMEM_TOTAL>>>(
        asp, wqp, qkv_b, qkvp, Mq, QKV_N, mt, nt_qkv);

    // 3) fused rmsnorm + fp16 convert -> g_q / g_k / g_v
    fuse_nc<<<dim3(Mq, 3), 256>>>(qkvp, q_norm_w, k_norm_w, qp, kp, vp);

    // 4) FA2 attention (single-pass fp16) -> g_as
    fa2<<<dim3(9, Hq, Bq), 256, ZSMEM>>>(qp, kp, vp, asp);

    // 5) out = att @ proj_w + b   (1-pass fp16)
    gemm_mma<<<mt * nt_prj, 256, GSMEM_TOTAL>>>(
        asp, wpp, proj_b, out, Mq, Cq, mt, nt_prj);
}

// round 15
// speedup vs baseline: 3.6119x; 1.0464x over previous
#include <cuda_runtime.h>
#include <cuda_bf16.h>
#include <cuda_fp16.h>
#include <cstdint>
#include <math.h>

// Problem constants
#define Bq 8
#define Nq 1025
#define Cq 3200
#define Hq 25
#define Dq 128
#define Mq (Bq * Nq)        // 8200
#define QKV_N (3 * Cq)      // 9600
#define EPSq 1e-6f

// Scratch (__device__ globals per alloc-free rule)
__device__ __half g_qkv16[(size_t)Mq * 2 * Cq];     // q,k fp16 (GEMM output)
__device__ __half g_as[(size_t)Mq * Cq];            // fp16 A (x, then attn out)
__device__ __half g_wq[(size_t)QKV_N * Cq];         // qkv_w^T fp16
__device__ __half g_wp[(size_t)Cq * Cq];            // proj_w^T fp16
__device__ __half g_q[(size_t)Bq * Hq * Nq * 128];  // q: fp16, normed+scaled
__device__ __half g_k[(size_t)Bq * Hq * Nq * 128];  // k: fp16, normed
__device__ __half g_v[(size_t)Bq * Hq * Nq * 128];  // v: fp16 (GEMM-direct)

// ===========================================================================
// helpers
// ===========================================================================
__device__ __forceinline__ uint32_t smem_u32(const void* p) {
    uint32_t a;
    asm("{ .reg .u64 t; cvta.to.shared.u64 t, %1; cvt.u32.u64 %0, t; }"
        : "=r"(a) : "l"(p));
    return a;
}
__device__ __forceinline__ uint32_t swz128(uint32_t off) {
    return off ^ ((off >> 3) & 0x70);
}
__device__ __forceinline__ void cp16(uint32_t s, const void* g) {
    asm volatile("cp.async.cg.shared.global [%0], [%1], 16;"
                 :: "r"(s), "l"(g) : "memory");
}
__device__ __forceinline__ void cp16z(uint32_t s, const void* g, int sz) {
    asm volatile("cp.async.cg.shared.global [%0], [%1], 16, %2;"
                 :: "r"(s), "l"(g), "r"(sz) : "memory");
}
#define CP_COMMIT() asm volatile("cp.async.commit_group;" ::: "memory")

#define LDSM_X4(r, addr)                                                       \
    asm volatile("ldmatrix.sync.aligned.m8n8.x4.shared.b16 {%0,%1,%2,%3}, [%4];" \
        : "=r"((r)[0]), "=r"((r)[1]), "=r"((r)[2]), "=r"((r)[3]) : "r"(addr))

#define LDSM_X4_T(r, addr)                                                     \
    asm volatile("ldmatrix.sync.aligned.m8n8.x4.trans.shared.b16 {%0,%1,%2,%3}, [%4];" \
        : "=r"((r)[0]), "=r"((r)[1]), "=r"((r)[2]), "=r"((r)[3]) : "r"(addr))

#define MMA16816_F16(d, a, b)                                                  \
    asm volatile("mma.sync.aligned.m16n8k16.row.col.f32.f16.f16.f32 "          \
        "{%0,%1,%2,%3}, {%4,%5,%6,%7}, {%8,%9}, {%0,%1,%2,%3};"                \
        : "+f"((d)[0]), "+f"((d)[1]), "+f"((d)[2]), "+f"((d)[3])               \
        : "r"((a)[0]), "r"((a)[1]), "r"((a)[2]), "r"((a)[3]),                  \
          "r"((b)[0]), "r"((b)[1]))

__device__ __forceinline__ uint32_t pack_h(float x, float y) {
    __half2 h2; h2.x = __float2half_rn(x); h2.y = __float2half_rn(y);
    return *(uint32_t*)&h2;
}

// ===========================================================================
// Convert kernels
// ===========================================================================
__global__ __launch_bounds__(256) void conv_a_kernel(
    const float* __restrict__ in, __half* __restrict__ out, int M)
{
    size_t idx = ((size_t)blockIdx.x * 256 + threadIdx.x) * 4;
    if (idx >= (size_t)M * Cq) return;
    float4 v = *(const float4*)(in + idx);
    *(uint32_t*)(out + idx)     = pack_h(v.x, v.y);
    *(uint32_t*)(out + idx + 2) = pack_h(v.z, v.w);
}

__global__ __launch_bounds__(256) void split_wt_kernel(
    const float* __restrict__ W, __half* __restrict__ out, int Nw)
{
    __shared__ float tile[32][33];
    int n0 = blockIdx.x * 32, k0 = blockIdx.y * 32;
    int tx = threadIdx.x, ty = threadIdx.y;
    #pragma unroll
    for (int i = ty; i < 32; i += 8)
        tile[i][tx] = W[(size_t)(k0 + i) * Nw + n0 + tx];
    __syncthreads();
    #pragma unroll
    for (int i = ty; i < 32; i += 8) {
        int n = n0 + i, k = k0 + tx;
        out[(size_t)n * Cq + k] = __float2half_rn(tile[tx][i]);
    }
}

// ===========================================================================
// Plain fp16 mma.sync GEMM (proven mainloop).
// mode 0: fp32 C (+bias), row stride Nt        [proj]
// mode 1: fp16 out: cols [0,2Cq) -> qkv16 (q,k); cols [2Cq,3Cq) -> g_v
//         head-contiguous layout                 [qkv]
// ===========================================================================
#define GBM 128
#define GBN 128
#define GBK 64
#define GNIT (Cq / GBK)            // 50
#define ABYTES (GBM * GBK * 2)
#define BBYTES (GBN * GBK * 2)
#define BUFB (ABYTES + BBYTES)
#define GSTAGES 3
#define GSMEM_TOTAL (GSTAGES * BUFB)
#define G_GM 8

__global__ __launch_bounds__(256, 2) void gemm_mma(
    const __half* __restrict__ A,
    const __half* __restrict__ Bt,
    const float* __restrict__ bias,
    void* __restrict__ Cout,
    __half* __restrict__ vout,
    int M, int Nt, int mt, int nt, int mode)
{
    extern __shared__ char smem[];
    const uint32_t sbase = smem_u32(smem);
    const int tid = threadIdx.x;
    const int wid = tid >> 5, lane = tid & 31;
    const int wm = wid >> 2, wn = wid & 3;

    int bid = blockIdx.x;
    int per_group = G_GM * nt;
    int gid = bid / per_group;
    int first_m = gid * G_GM;
    int gsz = min(G_GM, mt - first_m);
    int rem = bid % per_group;
    const int m0 = (first_m + rem % gsz) * GBM;
    const int n0 = (rem / gsz) * GBN;

    float acc[4][4][4];
    #pragma unroll
    for (int i = 0; i < 4; i++)
        #pragma unroll
        for (int j = 0; j < 4; j++)
            #pragma unroll
            for (int r = 0; r < 4; r++) acc[i][j][r] = 0.f;

    auto load_tile = [&](int it, int buf) {
        const int k0 = it * GBK;
        const uint32_t sA = sbase + buf * BUFB;
        const uint32_t sB = sA + ABYTES;
        #pragma unroll
        for (int p = 0; p < 4; p++) {
            int id = p * 256 + tid;
            int row = id >> 3, ch = id & 7;
            uint32_t so = swz128((uint32_t)(row * 128 + ch * 16));
            int m = min(m0 + row, M - 1);
            cp16(sA + so, A  + (size_t)m * Cq + k0 + ch * 8);
            cp16(sB + so, Bt + (size_t)(n0 + row) * Cq + k0 + ch * 8);
        }
        CP_COMMIT();
    };

    auto compute = [&](int buf) {
        const uint32_t sA = sbase + buf * BUFB + (uint32_t)(wm * 64 * 128);
        const uint32_t sB = sbase + buf * BUFB + ABYTES + (uint32_t)(wn * 32 * 128);
        #pragma unroll
        for (int kk = 0; kk < 4; kk++) {
            uint32_t afr[4][4];
            #pragma unroll
            for (int mi = 0; mi < 4; mi++) {
                int row = mi * 16 + (lane & 15);
                int cb = kk * 32 + ((lane >> 4) << 4);
                LDSM_X4(afr[mi], sA + swz128((uint32_t)(row * 128 + cb)));
            }
            uint32_t bfr[4][2];
            #pragma unroll
            for (int bj = 0; bj < 2; bj++) {
                int row = bj * 16 + ((lane >> 4) << 3) + (lane & 7);
                int cb = kk * 32 + (((lane >> 3) & 1) << 4);
                uint32_t r[4];
                LDSM_X4(r, sB + swz128((uint32_t)(row * 128 + cb)));
                bfr[2 * bj][0] = r[0];     bfr[2 * bj][1] = r[1];
                bfr[2 * bj + 1][0] = r[2]; bfr[2 * bj + 1][1] = r[3];
            }
            #pragma unroll
            for (int mi = 0; mi < 4; mi++)
                #pragma unroll
                for (int nj = 0; nj < 4; nj++)
                    MMA16816_F16(acc[mi][nj], afr[mi], bfr[nj]);
        }
    };

    load_tile(0, 0);
    load_tile(1, 1);
    for (int it = 0; it < GNIT; it++) {
        if (it + 1 < GNIT)
            asm volatile("cp.async.wait_group 1;" ::: "memory");
        else
            asm volatile("cp.async.wait_group 0;" ::: "memory");
        __syncthreads();
        if (it + 2 < GNIT) load_tile(it + 2, (it + 2) % GSTAGES);
        compute(it % GSTAGES);
    }

    const int mbase = m0 + wm * 64;
    const int nbase = n0 + wn * 32;
    #pragma unroll
    for (int mi = 0; mi < 4; mi++) {
        #pragma unroll
        for (int nj = 0; nj < 4; nj++) {
            int r0 = mbase + mi * 16 + (lane >> 2);
            int c = nbase + nj * 8 + 2 * (lane & 3);
            float bx = bias[c], by = bias[c + 1];
            float v00 = acc[mi][nj][0] + bx, v01 = acc[mi][nj][1] + by;
            float v10 = acc[mi][nj][2] + bx, v11 = acc[mi][nj][3] + by;
            if (mode == 0) {
                float* C = (float*)Cout;
                if (r0 < M)
                    *(float2*)(C + (size_t)r0 * Nt + c) = make_float2(v00, v01);
                if (r0 + 8 < M)
                    *(float2*)(C + (size_t)(r0 + 8) * Nt + c) = make_float2(v10, v11);
            } else {
                if (c < 2 * Cq) {
                    __half* C = (__half*)Cout;
                    if (r0 < M)
                        *(uint32_t*)(C + (size_t)r0 * 2 * Cq + c) = pack_h(v00, v01);
                    if (r0 + 8 < M)
                        *(uint32_t*)(C + (size_t)(r0 + 8) * 2 * Cq + c) = pack_h(v10, v11);
                } else {
                    int cc = c - 2 * Cq;
                    int h = cc >> 7, d = cc & 127;
                    if (r0 < M) {
                        int b = r0 / Nq, nn = r0 % Nq;
                        *(uint32_t*)(vout + ((size_t)(b * Hq + h) * Nq + nn) * 128 + d)
                            = pack_h(v00, v01);
                    }
                    if (r0 + 8 < M) {
                        int b = (r0 + 8) / Nq, nn = (r0 + 8) % Nq;
                        *(uint32_t*)(vout + ((size_t)(b * Hq + h) * Nq + nn) * 128 + d)
                            = pack_h(v10, v11);
                    }
                }
            }
        }
    }
}

// ===========================================================================
// Fused rmsnorm + head-contiguous relayout, fp16 in/out.
// which=0: q -> norm, *scale -> g_q ; which=1: k -> norm -> g_k
// ===========================================================================
__global__ __launch_bounds__(256) void fuse_nc(
    const __half* __restrict__ qkv16,
    const float* __restrict__ qw, const float* __restrict__ kw,
    __half* __restrict__ gq, __half* __restrict__ gk)
{
    const int row = blockIdx.x;
    const int which = blockIdx.y;       // 0 q, 1 k
    const int b = row / Nq, n = row % Nq;
    const __half* p = qkv16 + (size_t)row * 2 * Cq + which * Cq;
    const int tid = threadIdx.x;

    float ss = 0.f;
    for (int c = tid * 8; c < Cq; c += 2048) {
        uint4 u = *(const uint4*)(p + c);
        const __half2* h2 = (const __half2*)&u;
        #pragma unroll
        for (int j = 0; j < 4; j++) {
            float2 f = __half22float2(h2[j]);
            ss += f.x * f.x + f.y * f.y;
        }
    }
    #pragma unroll
    for (int o = 16; o; o >>= 1) ss += __shfl_xor_sync(0xffffffffu, ss, o);
    __shared__ float red[8];
    if ((tid & 31) == 0) red[tid >> 5] = ss;
    __syncthreads();
    if (tid < 8) {
        float v = red[tid];
        #pragma unroll
        for (int o = 4; o; o >>= 1) v += __shfl_xor_sync(0xffu, v, o);
        if (tid == 0) red[0] = v;
    }
    __syncthreads();
    const float sc = which ? 1.f : 0.08838834764831845f;
    const float inv = rsqrtf(red[0] * (1.f / Cq) + EPSq) * sc;
    const float* w = which ? kw : qw;
    __half* g = which ? gk : gq;

    for (int c = tid * 8; c < Cq; c += 2048) {
        uint4 u = *(const uint4*)(p + c);
        const __half2* h2 = (const __half2*)&u;
        float4 w0 = *(const float4*)(w + c);
        float4 w1 = *(const float4*)(w + c + 4);
        int h = c >> 7, d = c & 127;
        __half* orow = g + ((size_t)(b * Hq + h) * Nq + n) * 128;
        float2 f0 = __half22float2(h2[0]);
        float2 f1 = __half22float2(h2[1]);
        float2 f2 = __half22float2(h2[2]);
        float2 f3 = __half22float2(h2[3]);
        uint4 o;
        o.x = pack_h(f0.x * inv * w0.x, f0.y * inv * w0.y);
        o.y = pack_h(f1.x * inv * w0.z, f1.y * inv * w0.w);
        o.z = pack_h(f2.x * inv * w1.x, f2.y * inv * w1.y);
        o.w = pack_h(f3.x * inv * w1.z, f3.y * inv * w1.w);
        *(uint4*)(orow + d) = o;
    }
}

// ===========================================================================
// FA2-style flash attention, single-pass fp16 (proven round-14 kernel).
// ===========================================================================
#define ZK_B 272
#define ZKBUF (64 * ZK_B)
#define ZA_Q 0
#define ZA_K (128 * ZK_B)
#define ZA_V (ZA_K + 2 * ZKBUF)
#define ZSMEM (ZA_V + 2 * ZKBUF)

__global__ __launch_bounds__(256, 2) void fa2(
    const __half* __restrict__ gq, const __half* __restrict__ gk,
    const __half* __restrict__ gv, __half* __restrict__ outAs)
{
    extern __shared__ char sm[];
    const uint32_t sq = smem_u32(sm + ZA_Q);
    const uint32_t sk = smem_u32(sm + ZA_K);
    const uint32_t sv = smem_u32(sm + ZA_V);

    const int qt = blockIdx.x, h = blockIdx.y, b = blockIdx.z;
    const int tid = threadIdx.x, w = tid >> 5, lane = tid & 31;
    const int q0 = qt * 128;

    const __half* qb = gq + (size_t)(b * Hq + h) * Nq * 128;
    const __half* kb = gk + (size_t)(b * Hq + h) * Nq * 128;
    const __half* vb = gv + (size_t)(b * Hq + h) * Nq * 128;

    for (int i = tid; i < 128 * 16; i += 256) {
        int r = i >> 4, ch = i & 15;
        int n = q0 + r;
        int nc = min(n, Nq - 1);
        cp16z(sq + (uint32_t)(r * ZK_B + ch * 16),
              qb + (size_t)nc * 128 + ch * 8, (n < Nq) ? 16 : 0);
    }
    CP_COMMIT();

    auto fillKV = [&](int kt, int buf) {
        const int k0 = kt * 64;
        const uint32_t dk = sk + buf * ZKBUF;
        const uint32_t dv = sv + buf * ZKBUF;
        for (int i = tid; i < 64 * 16; i += 256) {
            int r = i >> 4, ch = i & 15;
            int n = k0 + r;
            int nc = min(n, Nq - 1);
            int sz = (n < Nq) ? 16 : 0;
            cp16z(dk + (uint32_t)(r * ZK_B + ch * 16), kb + (size_t)nc * 128 + ch * 8, sz);
            cp16z(dv + (uint32_t)(r * ZK_B + ch * 16), vb + (size_t)nc * 128 + ch * 8, sz);
        }
        CP_COMMIT();
    };
    fillKV(0, 0);

    float m0 = -1e30f, m1 = -1e30f, l0 = 0.f, l1 = 0.f;
    float acc_o[16][4];
    #pragma unroll
    for (int g = 0; g < 16; g++)
        #pragma unroll
        for (int r = 0; r < 4; r++) acc_o[g][r] = 0.f;

    const int arow = w * 16 + (lane & 15);
    const uint32_t a_cb = (uint32_t)((lane >> 4) << 4);
    const int krow_b = ((lane >> 4) << 3) + (lane & 7);
    const uint32_t b_cb = (uint32_t)(((lane >> 3) & 1) << 4);

    for (int kt = 0; kt < 17; kt++) {
        const int buf = kt & 1;
        asm volatile("cp.async.wait_group 0;" ::: "memory");
        __syncthreads();
        if (kt < 16) fillKV(kt + 1, buf ^ 1);

        const uint32_t skb = sk + buf * ZKBUF;
        const uint32_t svb = sv + buf * ZKBUF;

        float accs[8][4];
        #pragma unroll
        for (int nj = 0; nj < 8; nj++)
            #pragma unroll
            for (int r = 0; r < 4; r++) accs[nj][r] = 0.f;

        #pragma unroll
        for (int ks = 0; ks < 8; ks++) {
            uint32_t afr[4];
            LDSM_X4(afr, sq + (uint32_t)(arow * ZK_B + ks * 32) + a_cb);
            #pragma unroll
            for (int bj = 0; bj < 4; bj++) {
                uint32_t r[4];
                LDSM_X4(r, skb + (uint32_t)((bj * 16 + krow_b) * ZK_B + ks * 32) + b_cb);
                uint32_t b0[2] = {r[0], r[1]};
                uint32_t b1[2] = {r[2], r[3]};
                MMA16816_F16(accs[2 * bj],     afr, b0);
                MMA16816_F16(accs[2 * bj + 1], afr, b1);
            }
        }

        if (kt == 16) {
            #pragma unroll
            for (int nj = 0; nj < 8; nj++)
                #pragma unroll
                for (int j = 0; j < 4; j++) {
                    int col = 1024 + nj * 8 + 2 * (lane & 3) + (j & 1);
                    if (col >= Nq) accs[nj][j] = -1e30f;
                }
        }

        float mx0 = -1e30f, mx1 = -1e30f;
        #pragma unroll
        for (int nj = 0; nj < 8; nj++) {
            mx0 = fmaxf(mx0, fmaxf(accs[nj][0], accs[nj][1]));
            mx1 = fmaxf(mx1, fmaxf(accs[nj][2], accs[nj][3]));
        }
        mx0 = fmaxf(mx0, __shfl_xor_sync(0xffffffffu, mx0, 1));
        mx0 = fmaxf(mx0, __shfl_xor_sync(0xffffffffu, mx0, 2));
        mx1 = fmaxf(mx1, __shfl_xor_sync(0xffffffffu, mx1, 1));
        mx1 = fmaxf(mx1, __shfl_xor_sync(0xffffffffu, mx1, 2));

        const float mn0 = fmaxf(m0, mx0), mn1 = fmaxf(m1, mx1);
        const float cr0 = __expf(m0 - mn0), cr1 = __expf(m1 - mn1);

        float s0 = 0.f, s1 = 0.f;
        uint32_t ph[8][2];
        #pragma unroll
        for (int nj = 0; nj < 8; nj++) {
            float p0 = __expf(accs[nj][0] - mn0);
            float p1 = __expf(accs[nj][1] - mn0);
            float p2 = __expf(accs[nj][2] - mn1);
            float p3 = __expf(accs[nj][3] - mn1);
            s0 += p0 + p1; s1 += p2 + p3;
            ph[nj][0] = pack_h(p0, p1);
            ph[nj][1] = pack_h(p2, p3);
        }
        s0 += __shfl_xor_sync(0xffffffffu, s0, 1);
        s0 += __shfl_xor_sync(0xffffffffu, s0, 2);
        s1 += __shfl_xor_sync(0xffffffffu, s1, 1);
        s1 += __shfl_xor_sync(0xffffffffu, s1, 2);
        l0 = l0 * cr0 + s0; l1 = l1 * cr1 + s1;
        m0 = mn0; m1 = mn1;

        #pragma unroll
        for (int g = 0; g < 16; g++) {
            acc_o[g][0] *= cr0; acc_o[g][1] *= cr0;
            acc_o[g][2] *= cr1; acc_o[g][3] *= cr1;
        }

        const int vrow_b = (lane & 7) + (((lane >> 3) & 1) << 3);
        const uint32_t v_cb = (uint32_t)((lane >> 4) << 4);
        #pragma unroll
        for (int kc = 0; kc < 4; kc++) {
            uint32_t aPh[4] = {ph[2 * kc][0], ph[2 * kc][1], ph[2 * kc + 1][0], ph[2 * kc + 1][1]};
            #pragma unroll
            for (int g2 = 0; g2 < 8; g2++) {
                uint32_t r[4];
                LDSM_X4_T(r, svb + (uint32_t)((kc * 16 + vrow_b) * ZK_B + g2 * 32) + v_cb);
                uint32_t b0[2] = {r[0], r[1]};
                uint32_t b1[2] = {r[2], r[3]};
                MMA16816_F16(acc_o[2 * g2],     aPh, b0);
                MMA16816_F16(acc_o[2 * g2 + 1], aPh, b1);
            }
        }
    }

    // ---- epilogue: normalize, write fp16 (stride Cq) ----
    {
        const float invl0 = 1.f / l0, invl1 = 1.f / l1;
        const int n0v = q0 + w * 16 + (lane >> 2);
        const int n1v = n0v + 8;
        #pragma unroll
        for (int g = 0; g < 16; g++) {
            int c = h * Dq + g * 8 + 2 * (lane & 3);
            if (n0v < Nq) {
                __half* row = outAs + (size_t)(b * Nq + n0v) * Cq;
                *(uint32_t*)(row + c) = pack_h(acc_o[g][0] * invl0, acc_o[g][1] * invl0);
            }
            if (n1v < Nq) {
                __half* row = outAs + (size_t)(b * Nq + n1v) * Cq;
                *(uint32_t*)(row + c) = pack_h(acc_o[g][2] * invl1, acc_o[g][3] * invl1);
            }
        }
    }
}

// ===========================================================================
extern "C" void kernel_launch(void* const* d_in, const int* in_sizes, int n_in,
                              void* d_out, int out_size)
{
    const float* x        = (const float*)d_in[0];
    const float* qkv_w    = (const float*)d_in[1];
    const float* qkv_b    = (const float*)d_in[2];
    const float* q_norm_w = (const float*)d_in[3];
    const float* k_norm_w = (const float*)d_in[4];
    const float* proj_w   = (const float*)d_in[5];
    const float* proj_b   = (const float*)d_in[6];
    float* out = (float*)d_out;

    __half *qkvp = nullptr, *asp = nullptr, *wqp = nullptr, *wpp = nullptr;
    __half *qp = nullptr, *kp = nullptr, *vp = nullptr;
    cudaGetSymbolAddress((void**)&qkvp, g_qkv16);
    cudaGetSymbolAddress((void**)&asp, g_as);
    cudaGetSymbolAddress((void**)&wqp, g_wq);
    cudaGetSymbolAddress((void**)&wpp, g_wp);
    cudaGetSymbolAddress((void**)&qp, g_q);
    cudaGetSymbolAddress((void**)&kp, g_k);
    cudaGetSymbolAddress((void**)&vp, g_v);

    cudaFuncSetAttribute(gemm_mma,
                         cudaFuncAttributeMaxDynamicSharedMemorySize, GSMEM_TOTAL);
    cudaFuncSetAttribute(fa2,
                         cudaFuncAttributeMaxDynamicSharedMemorySize, ZSMEM);

    const int mt = (Mq + GBM - 1) / GBM;        // 65
    const int nt_qkv = QKV_N / GBN;             // 75
    const int nt_prj = Cq / GBN;                // 25

    // 1) convert x to fp16; round weights to fp16 (transposed)
    {
        size_t e4 = (size_t)Mq * Cq / 4;
        conv_a_kernel<<<(unsigned)((e4 + 255) / 256), 256>>>(x, asp, Mq);
    }
    split_wt_kernel<<<dim3(QKV_N / 32, Cq / 32), dim3(32, 8)>>>(qkv_w, wqp, QKV_N);
    split_wt_kernel<<<dim3(Cq / 32, Cq / 32), dim3(32, 8)>>>(proj_w, wpp, Cq);

    // 2) qkv GEMM: q,k -> g_qkv16 fp16; v -> g_v (head layout) directly
    gemm_mma<<<mt * nt_qkv, 256, GSMEM_TOTAL>>>(
        asp, wqp, qkv_b, qkvp, vp, Mq, QKV_N, mt, nt_qkv, 1);

    // 3) fused rmsnorm + relayout -> g_q / g_k
    fuse_nc<<<dim3(Mq, 2), 256>>>(qkvp, q_norm_w, k_norm_w, qp, kp);

    // 4) FA2 attention -> g_as (fp16)
    fa2<<<dim3(9, Hq, Bq), 256, ZSMEM>>>(qp, kp, vp, asp);

    // 5) out = att @ proj_w + b (fp32 out)
    gemm_mma<<<mt * nt_prj, 256, GSMEM_TOTAL>>>(
        asp, wpp, proj_b, out, nullptr, Mq, Cq, mt, nt_prj, 0);
}